// round 2
// baseline (speedup 1.0000x reference)
#include <cuda_runtime.h>
#include <math.h>

typedef long long LL;

#define BATCH   16
#define SEQ     197
#define NPATCH  196
#define DIM     768
#define NH      12
#define HDK     9216   /* NH*DIM */
#define MLP     3072
#define ROWS    (BATCH*SEQ)     /* 3152 */
#define PROWS   (BATCH*NPATCH)  /* 3136 */
#define NLAYER  4
#define NC      4

// ---------------- scratch (device globals; allocation-free) ----------------
__device__ float g_Xp [PROWS*DIM];        // im2col
__device__ float g_PO [PROWS*DIM];        // patch GEMM out
__device__ float g_WpT[DIM*DIM];          // transposed patch weight
__device__ float g_H  [ROWS*DIM];         // residual stream
__device__ float g_Xn [ROWS*DIM];         // LN output
__device__ float g_Wf [DIM*HDK];          // folded QKV weight (reused q/k/v)
__device__ float g_Bf [HDK];              // folded QKV bias
__device__ float g_Q  [ROWS*HDK];         // Q, later reused as "cat" (av output)
__device__ float g_K  [ROWS*HDK];
__device__ float g_V  [ROWS*HDK];
__device__ float g_S  [BATCH*NH*SEQ*SEQ]; // scores / probs
__device__ float g_Hid[ROWS*MLP];         // MLP hidden

// ---------------- small kernels ----------------
__global__ void transpose_k(const float* __restrict__ in, float* __restrict__ out) {
    int idx = blockIdx.x*blockDim.x + threadIdx.x;
    if (idx >= DIM*DIM) return;
    int d = idx % DIM, f = idx / DIM;
    out[idx] = in[d*DIM + f];           // out[f][d] = Wp[d][f]
}

__global__ void im2col_k(const float* __restrict__ x, float* __restrict__ out) {
    int idx = blockIdx.x*blockDim.x + threadIdx.x;
    if (idx >= PROWS*DIM) return;
    int f   = idx % DIM;
    int row = idx / DIM;
    int b = row / NPATCH, n = row % NPATCH;
    int ph = n / 14, pw = n % 14;
    int c = f / 256, r = f % 256;
    int p = r / 16,  q = r % 16;
    out[idx] = x[(((LL)b*3 + c)*224 + ph*16 + p)*224 + pw*16 + q];
}

__global__ void assemble_k(const float* __restrict__ patch, const float* __restrict__ cls,
                           const float* __restrict__ pos, float* __restrict__ h) {
    int idx = blockIdx.x*blockDim.x + threadIdx.x;
    if (idx >= ROWS*DIM) return;
    int d = idx % DIM;
    int row = idx / DIM;
    int b = row / SEQ, s = row % SEQ;
    float v = (s == 0) ? cls[d] : patch[((LL)b*NPATCH + (s-1))*DIM + d];
    h[idx] = v + pos[s*DIM + d];
}

// fold: Wf[d][h*DIM+k] = g1[h][d] * Wq[h][d][k]
__global__ void fold_w_k(const float* __restrict__ W, const float* __restrict__ g,
                         float* __restrict__ out) {
    int idx = blockIdx.x*blockDim.x + threadIdx.x;
    if (idx >= NH*DIM*DIM) return;
    int k = idx % DIM;
    int d = (idx / DIM) % DIM;
    int h = idx / (DIM*DIM);
    out[(LL)d*HDK + h*DIM + k] = g[h*DIM + d] * W[idx];
}

// Bf[h*DIM+k] = bq[h][k] + sum_d b1[h][d] * Wq[h][d][k]
__global__ void fold_b_k(const float* __restrict__ W, const float* __restrict__ b1,
                         const float* __restrict__ bq, float* __restrict__ out) {
    int hk = blockIdx.x*blockDim.x + threadIdx.x;
    if (hk >= HDK) return;
    int h = hk / DIM, k = hk % DIM;
    float s = bq[hk];
    const float* Wh = W + (LL)h*DIM*DIM;
    for (int d = 0; d < DIM; d++) s = fmaf(b1[h*DIM + d], Wh[(LL)d*DIM + k], s);
    out[hk] = s;
}

template<bool AFF>
__global__ void ln_k(const float* __restrict__ in, const float* __restrict__ g,
                     const float* __restrict__ b, float* __restrict__ out) {
    int row = blockIdx.x;
    const float* xr = in + (LL)row*DIM;
    int t = threadIdx.x;                 // 256 threads, 3 elems each
    float v0 = xr[t], v1 = xr[t+256], v2 = xr[t+512];
    __shared__ float rs[256], rss[256];
    rs[t]  = v0 + v1 + v2;
    rss[t] = v0*v0 + v1*v1 + v2*v2;
    __syncthreads();
    for (int off = 128; off > 0; off >>= 1) {
        if (t < off) { rs[t] += rs[t+off]; rss[t] += rss[t+off]; }
        __syncthreads();
    }
    float mu   = rs[0]  * (1.f/768.f);
    float var  = rss[0] * (1.f/768.f) - mu*mu;
    float rstd = rsqrtf(var + 1e-5f);
    float* orow = out + (LL)row*DIM;
    float y0 = (v0-mu)*rstd, y1 = (v1-mu)*rstd, y2 = (v2-mu)*rstd;
    if (AFF) {
        y0 = y0*g[t]     + b[t];
        y1 = y1*g[t+256] + b[t+256];
        y2 = y2*g[t+512] + b[t+512];
    }
    orow[t] = y0; orow[t+256] = y1; orow[t+512] = y2;
}

// softmax over the QUERY axis (columns of the [q,k] matrix)
__global__ void softmax_q_k(float* __restrict__ S) {
    LL base = (LL)blockIdx.x * (SEQ*SEQ);
    int k = threadIdx.x;
    if (k >= SEQ) return;
    float mx = -1e30f;
    for (int q = 0; q < SEQ; q++) mx = fmaxf(mx, S[base + (LL)q*SEQ + k]);
    float sum = 0.f;
    for (int q = 0; q < SEQ; q++) sum += expf(S[base + (LL)q*SEQ + k] - mx);
    float inv = 1.f / sum;
    for (int q = 0; q < SEQ; q++) {
        LL i = base + (LL)q*SEQ + k;
        S[i] = expf(S[i] - mx) * inv;
    }
}

__global__ void final_head_k(const float* __restrict__ h, const float* __restrict__ g,
                             const float* __restrict__ b, const float* __restrict__ Wc,
                             const float* __restrict__ bc, float* __restrict__ out) {
    int bi = blockIdx.x;
    const float* xr = h + (LL)bi*SEQ*DIM;   // CLS row (s=0)
    int t = threadIdx.x;
    float v0 = xr[t], v1 = xr[t+256], v2 = xr[t+512];
    __shared__ float rs[256], rss[256];
    rs[t]  = v0 + v1 + v2;
    rss[t] = v0*v0 + v1*v1 + v2*v2;
    __syncthreads();
    for (int off = 128; off > 0; off >>= 1) {
        if (t < off) { rs[t] += rs[t+off]; rss[t] += rss[t+off]; }
        __syncthreads();
    }
    float mu   = rs[0]  * (1.f/768.f);
    float rstd = rsqrtf(rss[0]*(1.f/768.f) - mu*mu + 1e-5f);
    __shared__ float pa[NC][256];
    float a[NC] = {0.f, 0.f, 0.f, 0.f};
    float vv[3] = {v0, v1, v2};
    #pragma unroll
    for (int i = 0; i < 3; i++) {
        int d = t + i*256;
        float y = (vv[i]-mu)*rstd*g[d] + b[d];
        #pragma unroll
        for (int c = 0; c < NC; c++) a[c] = fmaf(y, Wc[d*NC + c], a[c]);
    }
    #pragma unroll
    for (int c = 0; c < NC; c++) pa[c][t] = a[c];
    __syncthreads();
    for (int off = 128; off > 0; off >>= 1) {
        if (t < off) {
            #pragma unroll
            for (int c = 0; c < NC; c++) pa[c][t] += pa[c][t+off];
        }
        __syncthreads();
    }
    if (t < NC) out[bi*NC + t] = pa[t][0] + bc[t];
}

// ---------------- generic tiled SGEMM ----------------
// C[m,n] = alpha * sum_k A[m,k] * (TB ? B[n,k] : B[k,n])  (+bias[n]) (+res[m,n]) (gelu)
// batched via blockIdx.z with 2-level offsets: off = (z/zdiv)*s0 + (z%zdiv)*s1
#define EPI_BIAS 1
#define EPI_RES  2
#define EPI_GELU 4

template<int BM,int BN,int BK,int TM,int TN,bool TB,int EPI>
__global__ void __launch_bounds__((BM/TM)*(BN/TN))
gemm_k(const float* __restrict__ A, int lda, LL sA0, LL sA1,
       const float* __restrict__ B, int ldb, LL sB0, LL sB1,
       float* __restrict__ C, int ldc, LL sC0, LL sC1,
       const float* __restrict__ bias,
       const float* __restrict__ res, int ldres,
       int zdiv, int M, int N, int K, float alpha)
{
    constexpr int THREADS = (BM/TM)*(BN/TN);
    const int bz = blockIdx.z;
    const int zo = bz / zdiv, zi = bz - zo*zdiv;
    A += zo*sA0 + zi*sA1;
    B += zo*sB0 + zi*sB1;
    C += zo*sC0 + zi*sC1;

    __shared__ float As[BK][BM+4];
    __shared__ float Bs[BK][BN+4];

    const int bm = blockIdx.y*BM, bn = blockIdx.x*BN;
    const int tid = threadIdx.x;
    const int ncols = BN/TN;
    const int tr = tid / ncols;
    const int tc = tid % ncols;

    float acc[TM][TN];
    #pragma unroll
    for (int i = 0; i < TM; i++)
        #pragma unroll
        for (int j = 0; j < TN; j++) acc[i][j] = 0.f;

    for (int k0 = 0; k0 < K; k0 += BK) {
        #pragma unroll
        for (int it = 0; it < (BM*BK)/THREADS; it++) {
            int i = tid + it*THREADS;
            int m = i / BK, kk = i % BK;
            int gm = bm + m, gk = k0 + kk;
            As[kk][m] = (gm < M && gk < K) ? A[(LL)gm*lda + gk] : 0.f;
        }
        if (TB) {
            #pragma unroll
            for (int it = 0; it < (BN*BK)/THREADS; it++) {
                int i = tid + it*THREADS;
                int n = i / BK, kk = i % BK;
                int gn = bn + n, gk = k0 + kk;
                Bs[kk][n] = (gn < N && gk < K) ? B[(LL)gn*ldb + gk] : 0.f;
            }
        } else {
            #pragma unroll
            for (int it = 0; it < (BK*BN)/THREADS; it++) {
                int i = tid + it*THREADS;
                int kk = i / BN, n = i % BN;
                int gk = k0 + kk, gn = bn + n;
                Bs[kk][n] = (gk < K && gn < N) ? B[(LL)gk*ldb + gn] : 0.f;
            }
        }
        __syncthreads();
        #pragma unroll
        for (int kk = 0; kk < BK; kk++) {
            float ra[TM], rb[TN];
            #pragma unroll
            for (int i = 0; i < TM; i++) ra[i] = As[kk][tr*TM + i];
            #pragma unroll
            for (int j = 0; j < TN; j++) rb[j] = Bs[kk][tc*TN + j];
            #pragma unroll
            for (int i = 0; i < TM; i++)
                #pragma unroll
                for (int j = 0; j < TN; j++)
                    acc[i][j] = fmaf(ra[i], rb[j], acc[i][j]);
        }
        __syncthreads();
    }

    #pragma unroll
    for (int i = 0; i < TM; i++) {
        int m = bm + tr*TM + i;
        if (m >= M) continue;
        #pragma unroll
        for (int j = 0; j < TN; j++) {
            int n = bn + tc*TN + j;
            if (n >= N) continue;
            float v = acc[i][j] * alpha;
            if (EPI & EPI_BIAS) v += bias[n];
            if (EPI & EPI_RES)  v += res[(LL)m*ldres + n];
            if (EPI & EPI_GELU) v = 0.5f*v*(1.f + erff(v*0.70710678118654752440f));
            C[(LL)m*ldc + n] = v;
        }
    }
}

// ---------------- orchestration ----------------
extern "C" void kernel_launch(void* const* d_in, const int* in_sizes, int n_in,
                              void* d_out, int out_size)
{
    const float* x      = (const float*)d_in[0];
    const float* Wpatch = (const float*)d_in[1];
    const float* bpatch = (const float*)d_in[2];
    const float* cls    = (const float*)d_in[3];
    const float* pos    = (const float*)d_in[4];
    const float* ln1g   = (const float*)d_in[5];
    const float* ln1b   = (const float*)d_in[6];
    const float* Wq     = (const float*)d_in[7];
    const float* bq     = (const float*)d_in[8];
    const float* Wk     = (const float*)d_in[9];
    const float* bk     = (const float*)d_in[10];
    const float* Wv     = (const float*)d_in[11];
    const float* bv     = (const float*)d_in[12];
    const float* Wo     = (const float*)d_in[13];
    const float* bo     = (const float*)d_in[14];
    const float* ln2g   = (const float*)d_in[15];
    const float* ln2b   = (const float*)d_in[16];
    const float* W1     = (const float*)d_in[17];
    const float* b1m    = (const float*)d_in[18];
    const float* W2     = (const float*)d_in[19];
    const float* b2m    = (const float*)d_in[20];
    const float* lnfg   = (const float*)d_in[21];
    const float* lnfb   = (const float*)d_in[22];
    const float* Wc     = (const float*)d_in[23];
    const float* bc     = (const float*)d_in[24];
    float* out = (float*)d_out;

    float *Xp, *PO, *WpT, *H, *Xn, *Wf, *Bf, *Q, *Kb, *V, *S, *Hid;
    { void* p;
      cudaGetSymbolAddress(&p, g_Xp);  Xp  = (float*)p;
      cudaGetSymbolAddress(&p, g_PO);  PO  = (float*)p;
      cudaGetSymbolAddress(&p, g_WpT); WpT = (float*)p;
      cudaGetSymbolAddress(&p, g_H);   H   = (float*)p;
      cudaGetSymbolAddress(&p, g_Xn);  Xn  = (float*)p;
      cudaGetSymbolAddress(&p, g_Wf);  Wf  = (float*)p;
      cudaGetSymbolAddress(&p, g_Bf);  Bf  = (float*)p;
      cudaGetSymbolAddress(&p, g_Q);   Q   = (float*)p;
      cudaGetSymbolAddress(&p, g_K);   Kb  = (float*)p;
      cudaGetSymbolAddress(&p, g_V);   V   = (float*)p;
      cudaGetSymbolAddress(&p, g_S);   S   = (float*)p;
      cudaGetSymbolAddress(&p, g_Hid); Hid = (float*)p;
    }

    const float inv_scale = 1.0f / sqrtf(768.0f);

    // ---- patch embed ----
    transpose_k<<<(DIM*DIM + 255)/256, 256>>>(Wpatch, WpT);
    im2col_k<<<(PROWS*DIM + 255)/256, 256>>>(x, Xp);
    {
        dim3 grid((DIM+127)/128, (PROWS+127)/128, 1);
        gemm_k<128,128,8,8,8,false,EPI_BIAS><<<grid,256>>>(
            Xp, DIM, 0, 0,  WpT, DIM, 0, 0,  PO, DIM, 0, 0,
            bpatch, nullptr, 0, 1, PROWS, DIM, DIM, 1.f);
    }
    assemble_k<<<(ROWS*DIM + 255)/256, 256>>>(PO, cls, pos, H);

    // ---- transformer layers ----
    for (int l = 0; l < NLAYER; l++) {
        const float* ln1g_l = ln1g + (LL)l*NH*DIM;
        const float* ln1b_l = ln1b + (LL)l*NH*DIM;
        const float* Wqkv[3] = { Wq + (LL)l*NH*DIM*DIM, Wk + (LL)l*NH*DIM*DIM, Wv + (LL)l*NH*DIM*DIM };
        const float* bqkv[3] = { bq + (LL)l*NH*DIM,     bk + (LL)l*NH*DIM,     bv + (LL)l*NH*DIM };
        float* QKV[3] = { Q, Kb, V };
        const float* Wo_l = Wo  + (LL)l*HDK*DIM;
        const float* bo_l = bo  + (LL)l*DIM;
        const float* g2_l = ln2g + (LL)l*DIM;
        const float* b2_l = ln2b + (LL)l*DIM;
        const float* W1_l = W1  + (LL)l*DIM*MLP;
        const float* b1_l = b1m + (LL)l*MLP;
        const float* W2_l = W2  + (LL)l*MLP*DIM;
        const float* bb2_l= b2m + (LL)l*DIM;

        // LN1 (no affine — folded into QKV weights)
        ln_k<false><<<ROWS, 256>>>(H, nullptr, nullptr, Xn);

        for (int m = 0; m < 3; m++) {
            fold_w_k<<<(NH*DIM*DIM + 255)/256, 256>>>(Wqkv[m], ln1g_l, Wf);
            fold_b_k<<<(HDK + 255)/256, 256>>>(Wqkv[m], ln1b_l, bqkv[m], Bf);
            dim3 grid(HDK/128, (ROWS+127)/128, 1);
            gemm_k<128,128,8,8,8,false,EPI_BIAS><<<grid,256>>>(
                Xn, DIM, 0, 0,  Wf, HDK, 0, 0,  QKV[m], HDK, 0, 0,
                Bf, nullptr, 0, 1, ROWS, HDK, DIM, 1.f);
        }

        // scores[b,h,q,k] = Q·K / sqrt(768)  (batched NT)
        {
            dim3 grid((SEQ+63)/64, (SEQ+63)/64, BATCH*NH);
            gemm_k<64,64,16,4,4,true,0><<<grid,256>>>(
                Q,  HDK, (LL)SEQ*HDK, (LL)DIM,
                Kb, HDK, (LL)SEQ*HDK, (LL)DIM,
                S,  SEQ, (LL)NH*SEQ*SEQ, (LL)SEQ*SEQ,
                nullptr, nullptr, 0, NH, SEQ, SEQ, DIM, inv_scale);
        }
        // softmax over query axis (columns)
        softmax_q_k<<<BATCH*NH, 224>>>(S);
        // av = probs @ V, written directly in "cat" layout into Q buffer
        {
            dim3 grid(DIM/64, (SEQ+63)/64, BATCH*NH);
            gemm_k<64,64,16,4,4,false,0><<<grid,256>>>(
                S, SEQ, (LL)NH*SEQ*SEQ, (LL)SEQ*SEQ,
                V, HDK, (LL)SEQ*HDK, (LL)DIM,
                Q, HDK, (LL)SEQ*HDK, (LL)DIM,
                nullptr, nullptr, 0, NH, SEQ, DIM, SEQ, 1.f);
        }
        // out proj + bias + residual -> H
        {
            dim3 grid(DIM/128, (ROWS+127)/128, 1);
            gemm_k<128,128,8,8,8,false,EPI_BIAS|EPI_RES><<<grid,256>>>(
                Q, HDK, 0, 0,  Wo_l, DIM, 0, 0,  H, DIM, 0, 0,
                bo_l, H, DIM, 1, ROWS, DIM, HDK, 1.f);
        }
        // LN2 with affine
        ln_k<true><<<ROWS, 256>>>(H, g2_l, b2_l, Xn);
        // MLP fc1 + bias + GELU(exact)
        {
            dim3 grid(MLP/128, (ROWS+127)/128, 1);
            gemm_k<128,128,8,8,8,false,EPI_BIAS|EPI_GELU><<<grid,256>>>(
                Xn, DIM, 0, 0,  W1_l, MLP, 0, 0,  Hid, MLP, 0, 0,
                b1_l, nullptr, 0, 1, ROWS, MLP, DIM, 1.f);
        }
        // MLP fc2 + bias + residual -> H
        {
            dim3 grid(DIM/128, (ROWS+127)/128, 1);
            gemm_k<128,128,8,8,8,false,EPI_BIAS|EPI_RES><<<grid,256>>>(
                Hid, MLP, 0, 0,  W2_l, DIM, 0, 0,  H, DIM, 0, 0,
                bb2_l, H, DIM, 1, ROWS, DIM, MLP, 1.f);
        }
    }

    // ---- final LN on CLS + classifier ----
    final_head_k<<<BATCH, 256>>>(H, lnfg, lnfb, Wc, bc, out);
}

// round 4
// speedup vs baseline: 2.0806x; 2.0806x over previous
#include <cuda_runtime.h>
#include <cuda_bf16.h>
#include <math.h>
#include <stdint.h>

typedef long long LL;

#define BATCH   16
#define SEQ     197
#define NPATCH  196
#define DIM     768
#define NH      12
#define HDK     9216   /* NH*DIM */
#define MLP     3072
#define ROWS    (BATCH*SEQ)     /* 3152 */
#define PROWS   (BATCH*NPATCH)  /* 3136 */
#define NLAYER  4
#define NC      4

// ---------------- scratch (device globals; allocation-free) ----------------
__device__ float g_Xp [PROWS*DIM];
__device__ float g_PO [PROWS*DIM];
__device__ float g_H  [ROWS*DIM];
__device__ float g_Xn [ROWS*DIM];
__device__ float g_Bf [HDK];
__device__ float g_Q  [(LL)ROWS*HDK];
__device__ float g_K  [(LL)ROWS*HDK];
__device__ float g_V  [(LL)ROWS*HDK];
__device__ float g_S  [(LL)BATCH*NH*SEQ*SEQ];
__device__ float g_Hid[(LL)ROWS*MLP];

// bf16 hi/lo operand buffers
__device__ __nv_bfloat16 g_Ah[(LL)ROWS*HDK];
__device__ __nv_bfloat16 g_Al[(LL)ROWS*HDK];
__device__ __nv_bfloat16 g_Bh[(LL)DIM*HDK];
__device__ __nv_bfloat16 g_Bl[(LL)DIM*HDK];

// ---------------- helpers ----------------
__device__ __forceinline__ uint32_t smem_u32(const void* p) {
    uint32_t a;
    asm("{ .reg .u64 t; cvta.to.shared.u64 t, %1; cvt.u32.u64 %0, t; }" : "=r"(a) : "l"(p));
    return a;
}
__device__ __forceinline__ uint32_t swz(uint32_t off) { return off ^ ((off >> 3) & 0x70); }

__device__ __forceinline__ void cp16z(uint32_t dst, const void* src, uint32_t sz) {
    asm volatile("cp.async.cg.shared.global [%0], [%1], 16, %2;\n"
                 :: "r"(dst), "l"(src), "r"(sz) : "memory");
}
__device__ __forceinline__ void cp_commit() {
    asm volatile("cp.async.commit_group;\n" ::: "memory");
}

__device__ __forceinline__ void ldsm4(uint32_t* r, uint32_t addr) {
    asm volatile("ldmatrix.sync.aligned.m8n8.x4.shared.b16 {%0,%1,%2,%3}, [%4];\n"
                 : "=r"(r[0]), "=r"(r[1]), "=r"(r[2]), "=r"(r[3]) : "r"(addr));
}

__device__ __forceinline__ void mma16816(float* c, const uint32_t* a, const uint32_t* b) {
    asm volatile(
        "mma.sync.aligned.m16n8k16.row.col.f32.bf16.bf16.f32 "
        "{%0,%1,%2,%3}, {%4,%5,%6,%7}, {%8,%9}, {%0,%1,%2,%3};\n"
        : "+f"(c[0]), "+f"(c[1]), "+f"(c[2]), "+f"(c[3])
        : "r"(a[0]), "r"(a[1]), "r"(a[2]), "r"(a[3]), "r"(b[0]), "r"(b[1]));
}

// ---------------- mma.sync GEMM: C[M,N] = (Ah+Al)·(Bh+Bl)^T + epi ----------
// A: [M,K] bf16 K-major. B: [N,K] bf16 K-major. BM=128, BN=128, BK=64.
#define EPI_BIAS 1
#define EPI_RES  2
#define EPI_GELU 4

#define STAGES 3
#define STG_BYTES 65536
#define SA_H 0
#define SA_L 16384
#define SB_H 32768
#define SB_L 49152
#define MM_SMEM (STAGES*STG_BYTES)   /* 196608 */

__device__ __forceinline__ void load_tile(uint32_t stg,
    const __nv_bfloat16* __restrict__ Ah, const __nv_bfloat16* __restrict__ Al,
    const __nv_bfloat16* __restrict__ Bh, const __nv_bfloat16* __restrict__ Bl,
    int bm, int bn, int M, int K, int k0, int tid)
{
    int row = tid >> 1;
    int jb  = (tid & 1) * 64;           // 4 chunks of 16B
    uint32_t base = (uint32_t)row * 128u + (uint32_t)jb;
    {
        int gm = bm + row;
        uint32_t sz = (gm < M) ? 16u : 0u;
        int gmc = (gm < M) ? gm : 0;
        const char* pAh = (const char*)(Ah + (LL)gmc * K + k0) + jb;
        const char* pAl = (const char*)(Al + (LL)gmc * K + k0) + jb;
        #pragma unroll
        for (int j = 0; j < 4; j++) {
            uint32_t so = swz(base + j*16);
            cp16z(stg + SA_H + so, pAh + j*16, sz);
            cp16z(stg + SA_L + so, pAl + j*16, sz);
        }
    }
    {
        int gn = bn + row;
        const char* pBh = (const char*)(Bh + (LL)gn * K + k0) + jb;
        const char* pBl = (const char*)(Bl + (LL)gn * K + k0) + jb;
        #pragma unroll
        for (int j = 0; j < 4; j++) {
            uint32_t so = swz(base + j*16);
            cp16z(stg + SB_H + so, pBh + j*16, 16u);
            cp16z(stg + SB_L + so, pBl + j*16, 16u);
        }
    }
}

template<int EPI>
__global__ void __launch_bounds__(256, 1)
mm_gemm(const __nv_bfloat16* __restrict__ Ah, const __nv_bfloat16* __restrict__ Al,
        const __nv_bfloat16* __restrict__ Bh, const __nv_bfloat16* __restrict__ Bl,
        float* __restrict__ C, const float* __restrict__ bias,
        const float* __restrict__ res, int M, int N, int K)
{
    extern __shared__ char smem[];
    uint32_t sb = smem_u32(smem);
    const int tid  = threadIdx.x;
    const int wid  = tid >> 5;
    const int lane = tid & 31;
    const int bm = blockIdx.y * 128;
    const int bn = blockIdx.x * 128;
    const int m_warp = (wid & 1) * 64;   // 2 warps along M
    const int n_warp = (wid >> 1) * 32;  // 4 warps along N

    float acc[4][4][4];
    #pragma unroll
    for (int mt = 0; mt < 4; mt++)
        #pragma unroll
        for (int nt = 0; nt < 4; nt++)
            #pragma unroll
            for (int e = 0; e < 4; e++) acc[mt][nt][e] = 0.f;

    const int NCH = K >> 6;

    #pragma unroll
    for (int s = 0; s < STAGES-1; s++) {
        if (s < NCH) {
            load_tile(sb + s*STG_BYTES, Ah, Al, Bh, Bl, bm, bn, M, K, s*64, tid);
            cp_commit();
        }
    }

    // ldmatrix lane-address components
    const int lar = lane & 15;                          // A row within 16
    const int lac = (lane >> 4) * 16;                   // A k-half byte
    const int lbr = ((lane & 16) >> 1) + (lane & 7);    // B row within 16
    const int lbc = ((lane >> 3) & 1) * 16;             // B k-half byte

    for (int c = 0; c < NCH; c++) {
        if (c + STAGES-1 < NCH) {
            load_tile(sb + ((c + STAGES-1) % STAGES)*STG_BYTES,
                      Ah, Al, Bh, Bl, bm, bn, M, K, (c + STAGES-1)*64, tid);
            cp_commit();
            asm volatile("cp.async.wait_group 2;\n" ::: "memory");
        } else if (c + 1 < NCH) {
            asm volatile("cp.async.wait_group 1;\n" ::: "memory");
        } else {
            asm volatile("cp.async.wait_group 0;\n" ::: "memory");
        }
        __syncthreads();

        uint32_t stg = sb + (c % STAGES)*STG_BYTES;
        #pragma unroll
        for (int ks = 0; ks < 4; ks++) {
            uint32_t a_h[4][4], a_l[4][4], b_h[4][2], b_l[4][2];
            #pragma unroll
            for (int mt = 0; mt < 4; mt++) {
                uint32_t off = swz((uint32_t)(m_warp + mt*16 + lar)*128u + ks*32 + lac);
                ldsm4(a_h[mt], stg + SA_H + off);
                ldsm4(a_l[mt], stg + SA_L + off);
            }
            #pragma unroll
            for (int p = 0; p < 2; p++) {
                uint32_t off = swz((uint32_t)(n_warp + p*16 + lbr)*128u + ks*32 + lbc);
                uint32_t rh[4], rl[4];
                ldsm4(rh, stg + SB_H + off);
                ldsm4(rl, stg + SB_L + off);
                b_h[2*p][0] = rh[0]; b_h[2*p][1] = rh[1];
                b_h[2*p+1][0] = rh[2]; b_h[2*p+1][1] = rh[3];
                b_l[2*p][0] = rl[0]; b_l[2*p][1] = rl[1];
                b_l[2*p+1][0] = rl[2]; b_l[2*p+1][1] = rl[3];
            }
            #pragma unroll
            for (int mt = 0; mt < 4; mt++)
                #pragma unroll
                for (int nt = 0; nt < 4; nt++) {
                    mma16816(acc[mt][nt], a_h[mt], b_h[nt]);
                    mma16816(acc[mt][nt], a_h[mt], b_l[nt]);
                    mma16816(acc[mt][nt], a_l[mt], b_h[nt]);
                }
        }
        __syncthreads();
    }

    // ---- epilogue: direct global stores (float2 per fragment row) ----
    #pragma unroll
    for (int mt = 0; mt < 4; mt++) {
        int m0 = bm + m_warp + mt*16 + (lane >> 2);
        #pragma unroll
        for (int half = 0; half < 2; half++) {
            int m = m0 + half*8;
            if (m >= M) continue;
            #pragma unroll
            for (int nt = 0; nt < 4; nt++) {
                int n = bn + n_warp + nt*8 + (lane & 3)*2;
                float v0 = acc[mt][nt][half*2 + 0];
                float v1 = acc[mt][nt][half*2 + 1];
                if (EPI & EPI_BIAS) { v0 += __ldg(&bias[n]); v1 += __ldg(&bias[n+1]); }
                if (EPI & EPI_RES) {
                    const float2 rv = *(const float2*)(res + (LL)m*N + n);
                    v0 += rv.x; v1 += rv.y;
                }
                if (EPI & EPI_GELU) {
                    v0 = 0.5f*v0*(1.f + erff(v0*0.70710678118654752440f));
                    v1 = 0.5f*v1*(1.f + erff(v1*0.70710678118654752440f));
                }
                *(float2*)(C + (LL)m*N + n) = make_float2(v0, v1);
            }
        }
    }
}

// ---------------- conversion kernels ----------------
__global__ void split_k(const float4* __restrict__ in, __nv_bfloat16* __restrict__ hi,
                        __nv_bfloat16* __restrict__ lo, int n4) {
    int i = blockIdx.x*blockDim.x + threadIdx.x;
    if (i >= n4) return;
    float4 v = in[i];
    float vv[4] = { v.x, v.y, v.z, v.w };
    #pragma unroll
    for (int e = 0; e < 4; e++) {
        __nv_bfloat16 h = __float2bfloat16(vv[e]);
        hi[i*4 + e] = h;
        lo[i*4 + e] = __float2bfloat16(vv[e] - __bfloat162float(h));
    }
}

// QKV fold+transpose+split: W[h][d][k] * g[h][d] -> B[(h*768+k)][d]
__global__ void fold_split_w(const float* __restrict__ W, const float* __restrict__ g,
                             __nv_bfloat16* __restrict__ Bh, __nv_bfloat16* __restrict__ Bl) {
    __shared__ float t[32][33];
    int h = blockIdx.z, d0 = blockIdx.y*32, k0 = blockIdx.x*32;
    const float* Wh = W + (LL)h*DIM*DIM;
    for (int i = threadIdx.y; i < 32; i += 8)
        t[i][threadIdx.x] = Wh[(LL)(d0+i)*DIM + k0 + threadIdx.x] * g[h*DIM + d0 + i];
    __syncthreads();
    for (int i = threadIdx.y; i < 32; i += 8) {
        float v = t[threadIdx.x][i];
        LL o = (LL)(h*DIM + k0 + i)*DIM + d0 + threadIdx.x;
        __nv_bfloat16 hb = __float2bfloat16(v);
        Bh[o] = hb;
        Bl[o] = __float2bfloat16(v - __bfloat162float(hb));
    }
}

// transpose+split: W[K][N] -> B[N][K]
__global__ void tsplit_k(const float* __restrict__ W, __nv_bfloat16* __restrict__ Bh,
                         __nv_bfloat16* __restrict__ Bl, int K, int N) {
    __shared__ float t[32][33];
    int k0 = blockIdx.x*32, n0 = blockIdx.y*32;
    for (int i = threadIdx.y; i < 32; i += 8)
        t[i][threadIdx.x] = W[(LL)(k0+i)*N + n0 + threadIdx.x];
    __syncthreads();
    for (int i = threadIdx.y; i < 32; i += 8) {
        float v = t[threadIdx.x][i];
        LL o = (LL)(n0+i)*K + k0 + threadIdx.x;
        __nv_bfloat16 hb = __float2bfloat16(v);
        Bh[o] = hb;
        Bl[o] = __float2bfloat16(v - __bfloat162float(hb));
    }
}

// ---------------- small kernels ----------------
__global__ void im2col_k(const float* __restrict__ x, float* __restrict__ out) {
    int idx = blockIdx.x*blockDim.x + threadIdx.x;
    if (idx >= PROWS*DIM) return;
    int f   = idx % DIM;
    int row = idx / DIM;
    int b = row / NPATCH, n = row % NPATCH;
    int ph = n / 14, pw = n % 14;
    int c = f / 256, r = f % 256;
    int p = r / 16,  q = r % 16;
    out[idx] = x[(((LL)b*3 + c)*224 + ph*16 + p)*224 + pw*16 + q];
}

__global__ void assemble_k(const float* __restrict__ patch, const float* __restrict__ cls,
                           const float* __restrict__ pos, float* __restrict__ h) {
    int idx = blockIdx.x*blockDim.x + threadIdx.x;
    if (idx >= ROWS*DIM) return;
    int d = idx % DIM;
    int row = idx / DIM;
    int b = row / SEQ, s = row % SEQ;
    float v = (s == 0) ? cls[d] : patch[((LL)b*NPATCH + (s-1))*DIM + d];
    h[idx] = v + pos[s*DIM + d];
}

__global__ void fold_b_k(const float* __restrict__ W, const float* __restrict__ b1,
                         const float* __restrict__ bq, float* __restrict__ out) {
    int hk = blockIdx.x*blockDim.x + threadIdx.x;
    if (hk >= HDK) return;
    int h = hk / DIM, k = hk % DIM;
    float s = bq[hk];
    const float* Wh = W + (LL)h*DIM*DIM;
    for (int d = 0; d < DIM; d++) s = fmaf(b1[h*DIM + d], Wh[(LL)d*DIM + k], s);
    out[hk] = s;
}

template<bool AFF>
__global__ void ln_k(const float* __restrict__ in, const float* __restrict__ g,
                     const float* __restrict__ b, float* __restrict__ out) {
    int row = blockIdx.x;
    const float* xr = in + (LL)row*DIM;
    int t = threadIdx.x;
    float v0 = xr[t], v1 = xr[t+256], v2 = xr[t+512];
    __shared__ float rs[256], rss[256];
    rs[t]  = v0 + v1 + v2;
    rss[t] = v0*v0 + v1*v1 + v2*v2;
    __syncthreads();
    for (int off = 128; off > 0; off >>= 1) {
        if (t < off) { rs[t] += rs[t+off]; rss[t] += rss[t+off]; }
        __syncthreads();
    }
    float mu   = rs[0]  * (1.f/768.f);
    float var  = rss[0] * (1.f/768.f) - mu*mu;
    float rstd = rsqrtf(var + 1e-5f);
    float* orow = out + (LL)row*DIM;
    float y0 = (v0-mu)*rstd, y1 = (v1-mu)*rstd, y2 = (v2-mu)*rstd;
    if (AFF) {
        y0 = y0*g[t]     + b[t];
        y1 = y1*g[t+256] + b[t+256];
        y2 = y2*g[t+512] + b[t+512];
    }
    orow[t] = y0; orow[t+256] = y1; orow[t+512] = y2;
}

__global__ void softmax_q_k(float* __restrict__ S) {
    LL base = (LL)blockIdx.x * (SEQ*SEQ);
    int k = threadIdx.x;
    if (k >= SEQ) return;
    float mx = -1e30f;
    for (int q = 0; q < SEQ; q++) mx = fmaxf(mx, S[base + (LL)q*SEQ + k]);
    float sum = 0.f;
    for (int q = 0; q < SEQ; q++) sum += expf(S[base + (LL)q*SEQ + k] - mx);
    float inv = 1.f / sum;
    for (int q = 0; q < SEQ; q++) {
        LL i = base + (LL)q*SEQ + k;
        S[i] = expf(S[i] - mx) * inv;
    }
}

__global__ void final_head_k(const float* __restrict__ h, const float* __restrict__ g,
                             const float* __restrict__ b, const float* __restrict__ Wc,
                             const float* __restrict__ bc, float* __restrict__ out) {
    int bi = blockIdx.x;
    const float* xr = h + (LL)bi*SEQ*DIM;
    int t = threadIdx.x;
    float v0 = xr[t], v1 = xr[t+256], v2 = xr[t+512];
    __shared__ float rs[256], rss[256];
    rs[t]  = v0 + v1 + v2;
    rss[t] = v0*v0 + v1*v1 + v2*v2;
    __syncthreads();
    for (int off = 128; off > 0; off >>= 1) {
        if (t < off) { rs[t] += rs[t+off]; rss[t] += rss[t+off]; }
        __syncthreads();
    }
    float mu   = rs[0]  * (1.f/768.f);
    float rstd = rsqrtf(rss[0]*(1.f/768.f) - mu*mu + 1e-5f);
    __shared__ float pa[NC][256];
    float a[NC] = {0.f, 0.f, 0.f, 0.f};
    float vv[3] = {v0, v1, v2};
    #pragma unroll
    for (int i = 0; i < 3; i++) {
        int d = t + i*256;
        float y = (vv[i]-mu)*rstd*g[d] + b[d];
        #pragma unroll
        for (int c = 0; c < NC; c++) a[c] = fmaf(y, Wc[d*NC + c], a[c]);
    }
    #pragma unroll
    for (int c = 0; c < NC; c++) pa[c][t] = a[c];
    __syncthreads();
    for (int off = 128; off > 0; off >>= 1) {
        if (t < off) {
            #pragma unroll
            for (int c = 0; c < NC; c++) pa[c][t] += pa[c][t+off];
        }
        __syncthreads();
    }
    if (t < NC) out[bi*NC + t] = pa[t][0] + bc[t];
}

// ---------------- fp32 SGEMM (attention only) ----------------
template<int BM,int BN,int BK,int TM,int TN,bool TB>
__global__ void __launch_bounds__((BM/TM)*(BN/TN))
gemm_k(const float* __restrict__ A, int lda, LL sA0, LL sA1,
       const float* __restrict__ B, int ldb, LL sB0, LL sB1,
       float* __restrict__ C, int ldc, LL sC0, LL sC1,
       int zdiv, int M, int N, int K, float alpha)
{
    constexpr int THREADS = (BM/TM)*(BN/TN);
    const int bz = blockIdx.z;
    const int zo = bz / zdiv, zi = bz - zo*zdiv;
    A += zo*sA0 + zi*sA1;
    B += zo*sB0 + zi*sB1;
    C += zo*sC0 + zi*sC1;

    __shared__ float As[BK][BM+4];
    __shared__ float Bs[BK][BN+4];

    const int bm = blockIdx.y*BM, bn = blockIdx.x*BN;
    const int tid = threadIdx.x;
    const int ncols = BN/TN;
    const int tr = tid / ncols;
    const int tc = tid % ncols;

    float acc[TM][TN];
    #pragma unroll
    for (int i = 0; i < TM; i++)
        #pragma unroll
        for (int j = 0; j < TN; j++) acc[i][j] = 0.f;

    for (int k0 = 0; k0 < K; k0 += BK) {
        #pragma unroll
        for (int it = 0; it < (BM*BK)/THREADS; it++) {
            int i = tid + it*THREADS;
            int mI = i / BK, kk = i % BK;
            int gm = bm + mI, gk = k0 + kk;
            As[kk][mI] = (gm < M && gk < K) ? A[(LL)gm*lda + gk] : 0.f;
        }
        if (TB) {
            #pragma unroll
            for (int it = 0; it < (BN*BK)/THREADS; it++) {
                int i = tid + it*THREADS;
                int nI = i / BK, kk = i % BK;
                int gn = bn + nI, gk = k0 + kk;
                Bs[kk][nI] = (gn < N && gk < K) ? B[(LL)gn*ldb + gk] : 0.f;
            }
        } else {
            #pragma unroll
            for (int it = 0; it < (BK*BN)/THREADS; it++) {
                int i = tid + it*THREADS;
                int kk = i / BN, nI = i % BN;
                int gk = k0 + kk, gn = bn + nI;
                Bs[kk][nI] = (gk < K && gn < N) ? B[(LL)gk*ldb + gn] : 0.f;
            }
        }
        __syncthreads();
        #pragma unroll
        for (int kk = 0; kk < BK; kk++) {
            float ra[TM], rb[TN];
            #pragma unroll
            for (int i = 0; i < TM; i++) ra[i] = As[kk][tr*TM + i];
            #pragma unroll
            for (int j = 0; j < TN; j++) rb[j] = Bs[kk][tc*TN + j];
            #pragma unroll
            for (int i = 0; i < TM; i++)
                #pragma unroll
                for (int j = 0; j < TN; j++)
                    acc[i][j] = fmaf(ra[i], rb[j], acc[i][j]);
        }
        __syncthreads();
    }

    #pragma unroll
    for (int i = 0; i < TM; i++) {
        int mI = bm + tr*TM + i;
        if (mI >= M) continue;
        #pragma unroll
        for (int j = 0; j < TN; j++) {
            int nI = bn + tc*TN + j;
            if (nI >= N) continue;
            C[(LL)mI*ldc + nI] = acc[i][j] * alpha;
        }
    }
}

// ---------------- orchestration ----------------
static void run_mm(int epi, const __nv_bfloat16* Ah, const __nv_bfloat16* Al,
                   const __nv_bfloat16* Bh, const __nv_bfloat16* Bl,
                   float* C, const float* bias, const float* res, int M, int N, int K)
{
    dim3 grid(N/128, (M + 127)/128);
    if (epi == EPI_BIAS)
        mm_gemm<EPI_BIAS><<<grid, 256, MM_SMEM>>>(Ah, Al, Bh, Bl, C, bias, res, M, N, K);
    else if (epi == (EPI_BIAS|EPI_RES))
        mm_gemm<EPI_BIAS|EPI_RES><<<grid, 256, MM_SMEM>>>(Ah, Al, Bh, Bl, C, bias, res, M, N, K);
    else
        mm_gemm<EPI_BIAS|EPI_GELU><<<grid, 256, MM_SMEM>>>(Ah, Al, Bh, Bl, C, bias, res, M, N, K);
}

extern "C" void kernel_launch(void* const* d_in, const int* in_sizes, int n_in,
                              void* d_out, int out_size)
{
    const float* x      = (const float*)d_in[0];
    const float* Wpatch = (const float*)d_in[1];
    const float* bpatch = (const float*)d_in[2];
    const float* cls    = (const float*)d_in[3];
    const float* pos    = (const float*)d_in[4];
    const float* ln1g   = (const float*)d_in[5];
    const float* ln1b   = (const float*)d_in[6];
    const float* Wq     = (const float*)d_in[7];
    const float* bq     = (const float*)d_in[8];
    const float* Wk     = (const float*)d_in[9];
    const float* bk     = (const float*)d_in[10];
    const float* Wv     = (const float*)d_in[11];
    const float* bv     = (const float*)d_in[12];
    const float* Wo     = (const float*)d_in[13];
    const float* bo     = (const float*)d_in[14];
    const float* ln2g   = (const float*)d_in[15];
    const float* ln2b   = (const float*)d_in[16];
    const float* W1     = (const float*)d_in[17];
    const float* b1m    = (const float*)d_in[18];
    const float* W2     = (const float*)d_in[19];
    const float* b2m    = (const float*)d_in[20];
    const float* lnfg   = (const float*)d_in[21];
    const float* lnfb   = (const float*)d_in[22];
    const float* Wc     = (const float*)d_in[23];
    const float* bc     = (const float*)d_in[24];
    float* out = (float*)d_out;

    float *Xp, *PO, *H, *Xn, *Bf, *Q, *Kb, *V, *S, *Hid;
    __nv_bfloat16 *Ah, *Al, *Bh, *Bl;
    { void* p;
      cudaGetSymbolAddress(&p, g_Xp);  Xp  = (float*)p;
      cudaGetSymbolAddress(&p, g_PO);  PO  = (float*)p;
      cudaGetSymbolAddress(&p, g_H);   H   = (float*)p;
      cudaGetSymbolAddress(&p, g_Xn);  Xn  = (float*)p;
      cudaGetSymbolAddress(&p, g_Bf);  Bf  = (float*)p;
      cudaGetSymbolAddress(&p, g_Q);   Q   = (float*)p;
      cudaGetSymbolAddress(&p, g_K);   Kb  = (float*)p;
      cudaGetSymbolAddress(&p, g_V);   V   = (float*)p;
      cudaGetSymbolAddress(&p, g_S);   S   = (float*)p;
      cudaGetSymbolAddress(&p, g_Hid); Hid = (float*)p;
      cudaGetSymbolAddress(&p, g_Ah);  Ah  = (__nv_bfloat16*)p;
      cudaGetSymbolAddress(&p, g_Al);  Al  = (__nv_bfloat16*)p;
      cudaGetSymbolAddress(&p, g_Bh);  Bh  = (__nv_bfloat16*)p;
      cudaGetSymbolAddress(&p, g_Bl);  Bl  = (__nv_bfloat16*)p;
    }

    static int attr_done = 0;
    if (!attr_done) {
        cudaFuncSetAttribute(mm_gemm<EPI_BIAS>, cudaFuncAttributeMaxDynamicSharedMemorySize, MM_SMEM);
        cudaFuncSetAttribute(mm_gemm<EPI_BIAS|EPI_RES>, cudaFuncAttributeMaxDynamicSharedMemorySize, MM_SMEM);
        cudaFuncSetAttribute(mm_gemm<EPI_BIAS|EPI_GELU>, cudaFuncAttributeMaxDynamicSharedMemorySize, MM_SMEM);
        attr_done = 1;
    }

    const float inv_scale = 1.0f / sqrtf(768.0f);

    // ---- patch embed (tensor core) ----
    im2col_k<<<(PROWS*DIM + 255)/256, 256>>>(x, Xp);
    split_k<<<((PROWS*DIM/4) + 255)/256, 256>>>((const float4*)Xp, Ah, Al, PROWS*DIM/4);
    split_k<<<((DIM*DIM/4) + 255)/256, 256>>>((const float4*)Wpatch, Bh, Bl, DIM*DIM/4);
    run_mm(EPI_BIAS, Ah, Al, Bh, Bl, PO, bpatch, nullptr, PROWS, DIM, DIM);
    assemble_k<<<(ROWS*DIM + 255)/256, 256>>>(PO, cls, pos, H);

    // ---- transformer layers ----
    for (int l = 0; l < NLAYER; l++) {
        const float* ln1g_l = ln1g + (LL)l*NH*DIM;
        const float* ln1b_l = ln1b + (LL)l*NH*DIM;
        const float* Wqkv[3] = { Wq + (LL)l*NH*DIM*DIM, Wk + (LL)l*NH*DIM*DIM, Wv + (LL)l*NH*DIM*DIM };
        const float* bqkv[3] = { bq + (LL)l*NH*DIM,     bk + (LL)l*NH*DIM,     bv + (LL)l*NH*DIM };
        float* QKV[3] = { Q, Kb, V };
        const float* Wo_l = Wo  + (LL)l*HDK*DIM;
        const float* bo_l = bo  + (LL)l*DIM;
        const float* g2_l = ln2g + (LL)l*DIM;
        const float* b2_l = ln2b + (LL)l*DIM;
        const float* W1_l = W1  + (LL)l*DIM*MLP;
        const float* b1_l = b1m + (LL)l*MLP;
        const float* W2_l = W2  + (LL)l*MLP*DIM;
        const float* bb2_l= b2m + (LL)l*DIM;

        // LN1 (affine folded into QKV weights) + split activations once
        ln_k<false><<<ROWS, 256>>>(H, nullptr, nullptr, Xn);
        split_k<<<((ROWS*DIM/4) + 255)/256, 256>>>((const float4*)Xn, Ah, Al, ROWS*DIM/4);

        for (int m = 0; m < 3; m++) {
            dim3 fg(DIM/32, DIM/32, NH);
            fold_split_w<<<fg, dim3(32,8)>>>(Wqkv[m], ln1g_l, Bh, Bl);
            fold_b_k<<<(HDK + 255)/256, 256>>>(Wqkv[m], ln1b_l, bqkv[m], Bf);
            run_mm(EPI_BIAS, Ah, Al, Bh, Bl, QKV[m], Bf, nullptr, ROWS, HDK, DIM);
        }

        // scores = Q·K^T / sqrt(768)  (fp32, batched NT)
        {
            dim3 grid((SEQ+63)/64, (SEQ+63)/64, BATCH*NH);
            gemm_k<64,64,16,4,4,true><<<grid,256>>>(
                Q,  HDK, (LL)SEQ*HDK, (LL)DIM,
                Kb, HDK, (LL)SEQ*HDK, (LL)DIM,
                S,  SEQ, (LL)NH*SEQ*SEQ, (LL)SEQ*SEQ,
                NH, SEQ, SEQ, DIM, inv_scale);
        }
        softmax_q_k<<<BATCH*NH, 224>>>(S);
        // av = probs @ V -> Q buffer ("cat" layout)
        {
            dim3 grid(DIM/64, (SEQ+63)/64, BATCH*NH);
            gemm_k<64,64,16,4,4,false><<<grid,256>>>(
                S, SEQ, (LL)NH*SEQ*SEQ, (LL)SEQ*SEQ,
                V, HDK, (LL)SEQ*HDK, (LL)DIM,
                Q, HDK, (LL)SEQ*HDK, (LL)DIM,
                NH, SEQ, DIM, SEQ, 1.f);
        }

        // out proj: split cat + Wo^T, bias + residual
        split_k<<<(((LL)ROWS*HDK/4) + 255)/256, 256>>>((const float4*)Q, Ah, Al, ROWS*HDK/4);
        tsplit_k<<<dim3(HDK/32, DIM/32), dim3(32,8)>>>(Wo_l, Bh, Bl, HDK, DIM);
        run_mm(EPI_BIAS|EPI_RES, Ah, Al, Bh, Bl, H, bo_l, H, ROWS, DIM, HDK);

        // MLP
        ln_k<true><<<ROWS, 256>>>(H, g2_l, b2_l, Xn);
        split_k<<<((ROWS*DIM/4) + 255)/256, 256>>>((const float4*)Xn, Ah, Al, ROWS*DIM/4);
        tsplit_k<<<dim3(DIM/32, MLP/32), dim3(32,8)>>>(W1_l, Bh, Bl, DIM, MLP);
        run_mm(EPI_BIAS|EPI_GELU, Ah, Al, Bh, Bl, Hid, b1_l, nullptr, ROWS, MLP, DIM);

        split_k<<<(((LL)ROWS*MLP/4) + 255)/256, 256>>>((const float4*)Hid, Ah, Al, ROWS*MLP/4);
        tsplit_k<<<dim3(MLP/32, DIM/32), dim3(32,8)>>>(W2_l, Bh, Bl, MLP, DIM);
        run_mm(EPI_BIAS|EPI_RES, Ah, Al, Bh, Bl, H, bb2_l, H, ROWS, DIM, MLP);
    }

    // ---- final LN on CLS + classifier ----
    final_head_k<<<BATCH, 256>>>(H, lnfg, lnfb, Wc, bc, out);
}

// round 5
// speedup vs baseline: 3.2288x; 1.5519x over previous
#include <cuda_runtime.h>
#include <cuda_bf16.h>
#include <math.h>
#include <stdint.h>

typedef long long LL;
typedef __nv_bfloat16 bf16;

#define BATCH   16
#define SEQ     197
#define SEQP    256
#define NPATCH  196
#define DIM     768
#define NH      12
#define HDK     9216
#define MLP     3072
#define ROWS    (BATCH*SEQ)     /* 3152 */
#define PROWS   (BATCH*NPATCH)  /* 3136 */
#define NLAYER  4
#define NC      4
#define NBH     (BATCH*NH)      /* 192 */

// ---------------- scratch (device globals) ----------------
__device__ float g_PO [PROWS*DIM];
__device__ float g_H  [ROWS*DIM];
__device__ float g_Bf [HDK];
__device__ float g_S  [(LL)NBH*SEQ*SEQP];

__device__ bf16 g_XnH[ROWS*DIM],  g_XnL[ROWS*DIM];
__device__ bf16 g_XpH[PROWS*DIM], g_XpL[PROWS*DIM];
__device__ bf16 g_Qh [(LL)ROWS*HDK], g_Ql [(LL)ROWS*HDK];   // Q, later cat
__device__ bf16 g_Kh [(LL)ROWS*HDK], g_Kl [(LL)ROWS*HDK];   // K, later Hid
__device__ bf16 g_Vh [(LL)ROWS*HDK], g_Vl [(LL)ROWS*HDK];
__device__ bf16 g_Ph [(LL)NBH*SEQ*SEQP], g_Pl [(LL)NBH*SEQ*SEQP];
__device__ bf16 g_Bh [(LL)DIM*HDK], g_Bl [(LL)DIM*HDK];      // weight split

// ---------------- helpers ----------------
__device__ __forceinline__ uint32_t smem_u32(const void* p) {
    uint32_t a;
    asm("{ .reg .u64 t; cvta.to.shared.u64 t, %1; cvt.u32.u64 %0, t; }" : "=r"(a) : "l"(p));
    return a;
}
__device__ __forceinline__ uint32_t swz(uint32_t off) { return off ^ ((off >> 3) & 0x70); }

__device__ __forceinline__ void cp16z(uint32_t dst, const void* src, uint32_t sz) {
    asm volatile("cp.async.cg.shared.global [%0], [%1], 16, %2;\n"
                 :: "r"(dst), "l"(src), "r"(sz) : "memory");
}
__device__ __forceinline__ void cp_commit() {
    asm volatile("cp.async.commit_group;\n" ::: "memory");
}
__device__ __forceinline__ void ldsm4(uint32_t* r, uint32_t addr) {
    asm volatile("ldmatrix.sync.aligned.m8n8.x4.shared.b16 {%0,%1,%2,%3}, [%4];\n"
                 : "=r"(r[0]), "=r"(r[1]), "=r"(r[2]), "=r"(r[3]) : "r"(addr));
}
__device__ __forceinline__ void ldsm4t(uint32_t* r, uint32_t addr) {
    asm volatile("ldmatrix.sync.aligned.m8n8.x4.trans.shared.b16 {%0,%1,%2,%3}, [%4];\n"
                 : "=r"(r[0]), "=r"(r[1]), "=r"(r[2]), "=r"(r[3]) : "r"(addr));
}
__device__ __forceinline__ void mma16816(float* c, const uint32_t* a, const uint32_t* b) {
    asm volatile(
        "mma.sync.aligned.m16n8k16.row.col.f32.bf16.bf16.f32 "
        "{%0,%1,%2,%3}, {%4,%5,%6,%7}, {%8,%9}, {%0,%1,%2,%3};\n"
        : "+f"(c[0]), "+f"(c[1]), "+f"(c[2]), "+f"(c[3])
        : "r"(a[0]), "r"(a[1]), "r"(a[2]), "r"(a[3]), "r"(b[0]), "r"(b[1]));
}

// ---------------- unified mma GEMM ----------------
// C[M,N] = alpha*(Ah+Al)·(Bh+Bl)^T + epi      (3-pass hi/lo)
// A: [M,K] bf16 K-major (lda).
// BT=false: B [N,K] K-major (ldb), Brows = valid N rows.
// BT=true : B [K,N] N-major (ldb), Brows = valid K rows.
#define EPI_BIAS  1
#define EPI_RES   2
#define EPI_GELU  4
#define EPI_SPLIT 8

#define STAGES 3
#define STG_BYTES 65536
#define SA_H 0
#define SA_L 16384
#define SB_H 32768
#define SB_L 49152
#define MM_SMEM (STAGES*STG_BYTES)   /* 196608 */

template<bool BT>
__device__ __forceinline__ void load_tile2(uint32_t stg,
    const bf16* __restrict__ Ah, const bf16* __restrict__ Al,
    const bf16* __restrict__ Bh, const bf16* __restrict__ Bl,
    int bm, int bn, int M, int Brows, int lda, int ldb, int k0, int tid)
{
    {   // A: 128 rows x 128B per matrix; 512 thr -> 1 row, 2 chunks each
        int row = tid >> 2;
        int j0  = tid & 3;
        int gm = bm + row;
        uint32_t sz = (gm < M) ? 16u : 0u;
        int gmc = (gm < M) ? gm : (M-1);
        const char* pAh = (const char*)(Ah + (LL)gmc*lda + k0);
        const char* pAl = (const char*)(Al + (LL)gmc*lda + k0);
        #pragma unroll
        for (int jj = 0; jj < 2; jj++) {
            int j = j0 + jj*4;
            uint32_t so = swz((uint32_t)row*128u + (uint32_t)j*16u);
            cp16z(stg + SA_H + so, pAh + j*16, sz);
            cp16z(stg + SA_L + so, pAl + j*16, sz);
        }
    }
    if (!BT) {
        int row = tid >> 2;
        int j0  = tid & 3;
        int gn = bn + row;
        uint32_t sz = (gn < Brows) ? 16u : 0u;
        int gnc = (gn < Brows) ? gn : (Brows-1);
        const char* pBh = (const char*)(Bh + (LL)gnc*ldb + k0);
        const char* pBl = (const char*)(Bl + (LL)gnc*ldb + k0);
        #pragma unroll
        for (int jj = 0; jj < 2; jj++) {
            int j = j0 + jj*4;
            uint32_t so = swz((uint32_t)row*128u + (uint32_t)j*16u);
            cp16z(stg + SB_H + so, pBh + j*16, sz);
            cp16z(stg + SB_L + so, pBl + j*16, sz);
        }
    } else {
        // B: 64 k-rows x 256B per matrix
        int krow = tid >> 3;
        int j0   = tid & 7;
        int gk = k0 + krow;
        uint32_t sz = (gk < Brows) ? 16u : 0u;
        int gkc = (gk < Brows) ? gk : (Brows-1);
        const char* pBh = (const char*)(Bh + (LL)gkc*ldb + bn);
        const char* pBl = (const char*)(Bl + (LL)gkc*ldb + bn);
        #pragma unroll
        for (int jj = 0; jj < 2; jj++) {
            int j = j0 + jj*8;
            uint32_t so = (uint32_t)krow*256u + (((uint32_t)j*16u) ^ (((uint32_t)krow & 7u) << 4));
            cp16z(stg + SB_H + so, pBh + j*16, sz);
            cp16z(stg + SB_L + so, pBl + j*16, sz);
        }
    }
}

template<int EPI, bool BT>
__global__ void __launch_bounds__(512, 1)
mm2(const bf16* __restrict__ Ah, const bf16* __restrict__ Al,
    const bf16* __restrict__ Bh, const bf16* __restrict__ Bl,
    float* __restrict__ C, bf16* __restrict__ Ch, bf16* __restrict__ Cl,
    const float* __restrict__ bias, const float* __restrict__ res,
    int M, int N, int Brows, int K,
    int lda, int ldb, int ldc,
    int zdiv, LL sA0, LL sA1, LL sB0, LL sB1, LL sC0, LL sC1,
    float alpha)
{
    extern __shared__ char smem[];
    uint32_t sb = smem_u32(smem);
    const int tid  = threadIdx.x;
    const int wid  = tid >> 5;
    const int lane = tid & 31;
    const int bm = blockIdx.y * 128;
    const int bn = blockIdx.x * 128;
    const int zo = blockIdx.z / zdiv, zi = blockIdx.z - zo*zdiv;
    Ah += zo*sA0 + zi*sA1;  Al += zo*sA0 + zi*sA1;
    Bh += zo*sB0 + zi*sB1;  Bl += zo*sB0 + zi*sB1;
    const LL cbase = zo*sC0 + zi*sC1;

    const int m_warp = (wid & 3) * 32;   // 4 warps along M
    const int n_warp = (wid >> 2) * 32;  // 4 warps along N

    float acc[2][4][4];
    #pragma unroll
    for (int mt = 0; mt < 2; mt++)
        #pragma unroll
        for (int nt = 0; nt < 4; nt++)
            #pragma unroll
            for (int e = 0; e < 4; e++) acc[mt][nt][e] = 0.f;

    const int NCH = K >> 6;

    #pragma unroll
    for (int s = 0; s < STAGES-1; s++) {
        if (s < NCH) {
            load_tile2<BT>(sb + s*STG_BYTES, Ah, Al, Bh, Bl, bm, bn, M, Brows, lda, ldb, s*64, tid);
            cp_commit();
        }
    }

    const int lar = lane & 15;
    const int lac = (lane >> 4) * 16;
    const int lbr = ((lane & 16) >> 1) + (lane & 7);
    const int lbc = ((lane >> 3) & 1) * 16;

    for (int c = 0; c < NCH; c++) {
        if (c + STAGES-1 < NCH) {
            load_tile2<BT>(sb + ((c + STAGES-1) % STAGES)*STG_BYTES,
                           Ah, Al, Bh, Bl, bm, bn, M, Brows, lda, ldb, (c + STAGES-1)*64, tid);
            cp_commit();
            asm volatile("cp.async.wait_group 2;\n" ::: "memory");
        } else if (c + 1 < NCH) {
            asm volatile("cp.async.wait_group 1;\n" ::: "memory");
        } else {
            asm volatile("cp.async.wait_group 0;\n" ::: "memory");
        }
        __syncthreads();

        uint32_t stg = sb + (c % STAGES)*STG_BYTES;
        #pragma unroll
        for (int ks = 0; ks < 4; ks++) {
            uint32_t a_h[2][4], a_l[2][4], b_h[4][2], b_l[4][2];
            #pragma unroll
            for (int mt = 0; mt < 2; mt++) {
                uint32_t off = swz((uint32_t)(m_warp + mt*16 + lar)*128u + ks*32 + lac);
                ldsm4(a_h[mt], stg + SA_H + off);
                ldsm4(a_l[mt], stg + SA_L + off);
            }
            if (!BT) {
                #pragma unroll
                for (int p = 0; p < 2; p++) {
                    uint32_t off = swz((uint32_t)(n_warp + p*16 + lbr)*128u + ks*32 + lbc);
                    uint32_t rh[4], rl[4];
                    ldsm4(rh, stg + SB_H + off);
                    ldsm4(rl, stg + SB_L + off);
                    b_h[2*p][0]=rh[0]; b_h[2*p][1]=rh[1]; b_h[2*p+1][0]=rh[2]; b_h[2*p+1][1]=rh[3];
                    b_l[2*p][0]=rl[0]; b_l[2*p][1]=rl[1]; b_l[2*p+1][0]=rl[2]; b_l[2*p+1][1]=rl[3];
                }
            } else {
                #pragma unroll
                for (int p = 0; p < 2; p++) {
                    uint32_t row = (uint32_t)(ks*16 + (lane & 15));
                    uint32_t nb  = (uint32_t)((n_warp + p*16)*2) + (((uint32_t)lane >> 4) << 4);
                    uint32_t off = row*256u + (nb ^ ((row & 7u) << 4));
                    uint32_t rh[4], rl[4];
                    ldsm4t(rh, stg + SB_H + off);
                    ldsm4t(rl, stg + SB_L + off);
                    b_h[2*p][0]=rh[0]; b_h[2*p][1]=rh[1]; b_h[2*p+1][0]=rh[2]; b_h[2*p+1][1]=rh[3];
                    b_l[2*p][0]=rl[0]; b_l[2*p][1]=rl[1]; b_l[2*p+1][0]=rl[2]; b_l[2*p+1][1]=rl[3];
                }
            }
            #pragma unroll
            for (int mt = 0; mt < 2; mt++)
                #pragma unroll
                for (int nt = 0; nt < 4; nt++) {
                    mma16816(acc[mt][nt], a_h[mt], b_h[nt]);
                    mma16816(acc[mt][nt], a_h[mt], b_l[nt]);
                    mma16816(acc[mt][nt], a_l[mt], b_h[nt]);
                }
        }
        __syncthreads();
    }

    // ---- epilogue ----
    #pragma unroll
    for (int mt = 0; mt < 2; mt++) {
        #pragma unroll
        for (int half = 0; half < 2; half++) {
            int m = bm + m_warp + mt*16 + (lane >> 2) + half*8;
            if (m >= M) continue;
            #pragma unroll
            for (int nt = 0; nt < 4; nt++) {
                int n = bn + n_warp + nt*8 + (lane & 3)*2;
                if (n >= N) continue;
                float v0 = acc[mt][nt][half*2 + 0] * alpha;
                float v1 = acc[mt][nt][half*2 + 1] * alpha;
                if (EPI & EPI_BIAS) { v0 += __ldg(&bias[n]); v1 += __ldg(&bias[n+1]); }
                if (EPI & EPI_RES) {
                    const float2 rv = *(const float2*)(res + (LL)m*ldc + n);
                    v0 += rv.x; v1 += rv.y;
                }
                if (EPI & EPI_GELU) {
                    v0 = 0.5f*v0*(1.f + erff(v0*0.70710678118654752440f));
                    v1 = 0.5f*v1*(1.f + erff(v1*0.70710678118654752440f));
                }
                if (EPI & EPI_SPLIT) {
                    bf16 h0 = __float2bfloat16(v0), h1 = __float2bfloat16(v1);
                    bf16 l0 = __float2bfloat16(v0 - __bfloat162float(h0));
                    bf16 l1 = __float2bfloat16(v1 - __bfloat162float(h1));
                    __nv_bfloat162 ph; ph.x = h0; ph.y = h1;
                    __nv_bfloat162 pl; pl.x = l0; pl.y = l1;
                    *(__nv_bfloat162*)(Ch + cbase + (LL)m*ldc + n) = ph;
                    *(__nv_bfloat162*)(Cl + cbase + (LL)m*ldc + n) = pl;
                } else {
                    if (n + 1 < N) *(float2*)(C + cbase + (LL)m*ldc + n) = make_float2(v0, v1);
                    else C[cbase + (LL)m*ldc + n] = v0;
                }
            }
        }
    }
}

// ---------------- conversion / small kernels ----------------
__global__ void split_k(const float4* __restrict__ in, bf16* __restrict__ hi,
                        bf16* __restrict__ lo, int n4) {
    int i = blockIdx.x*blockDim.x + threadIdx.x;
    if (i >= n4) return;
    float4 v = in[i];
    float vv[4] = { v.x, v.y, v.z, v.w };
    #pragma unroll
    for (int e = 0; e < 4; e++) {
        bf16 h = __float2bfloat16(vv[e]);
        hi[i*4 + e] = h;
        lo[i*4 + e] = __float2bfloat16(vv[e] - __bfloat162float(h));
    }
}

__global__ void fold_split_w(const float* __restrict__ W, const float* __restrict__ g,
                             bf16* __restrict__ Bh, bf16* __restrict__ Bl) {
    __shared__ float t[32][33];
    int h = blockIdx.z, d0 = blockIdx.y*32, k0 = blockIdx.x*32;
    const float* Wh = W + (LL)h*DIM*DIM;
    for (int i = threadIdx.y; i < 32; i += 8)
        t[i][threadIdx.x] = Wh[(LL)(d0+i)*DIM + k0 + threadIdx.x] * g[h*DIM + d0 + i];
    __syncthreads();
    for (int i = threadIdx.y; i < 32; i += 8) {
        float v = t[threadIdx.x][i];
        LL o = (LL)(h*DIM + k0 + i)*DIM + d0 + threadIdx.x;
        bf16 hb = __float2bfloat16(v);
        Bh[o] = hb;
        Bl[o] = __float2bfloat16(v - __bfloat162float(hb));
    }
}

__global__ void tsplit_k(const float* __restrict__ W, bf16* __restrict__ Bh,
                         bf16* __restrict__ Bl, int K, int N) {
    __shared__ float t[32][33];
    int k0 = blockIdx.x*32, n0 = blockIdx.y*32;
    for (int i = threadIdx.y; i < 32; i += 8)
        t[i][threadIdx.x] = W[(LL)(k0+i)*N + n0 + threadIdx.x];
    __syncthreads();
    for (int i = threadIdx.y; i < 32; i += 8) {
        float v = t[threadIdx.x][i];
        LL o = (LL)(n0+i)*K + k0 + threadIdx.x;
        bf16 hb = __float2bfloat16(v);
        Bh[o] = hb;
        Bl[o] = __float2bfloat16(v - __bfloat162float(hb));
    }
}

__global__ void im2col_split(const float* __restrict__ x, bf16* __restrict__ oh,
                             bf16* __restrict__ ol) {
    int idx = blockIdx.x*blockDim.x + threadIdx.x;
    if (idx >= PROWS*DIM) return;
    int f   = idx % DIM;
    int row = idx / DIM;
    int b = row / NPATCH, n = row % NPATCH;
    int ph = n / 14, pw = n % 14;
    int c = f / 256, r = f % 256;
    int p = r / 16,  q = r % 16;
    float v = x[(((LL)b*3 + c)*224 + ph*16 + p)*224 + pw*16 + q];
    bf16 h = __float2bfloat16(v);
    oh[idx] = h;
    ol[idx] = __float2bfloat16(v - __bfloat162float(h));
}

__global__ void assemble_k(const float* __restrict__ patch, const float* __restrict__ cls,
                           const float* __restrict__ pos, float* __restrict__ h) {
    int idx = blockIdx.x*blockDim.x + threadIdx.x;
    if (idx >= ROWS*DIM) return;
    int d = idx % DIM;
    int row = idx / DIM;
    int b = row / SEQ, s = row % SEQ;
    float v = (s == 0) ? cls[d] : patch[((LL)b*NPATCH + (s-1))*DIM + d];
    h[idx] = v + pos[s*DIM + d];
}

__global__ void fold_b_k(const float* __restrict__ W, const float* __restrict__ b1,
                         const float* __restrict__ bq, float* __restrict__ out) {
    int hk = blockIdx.x*blockDim.x + threadIdx.x;
    if (hk >= HDK) return;
    int h = hk / DIM, k = hk % DIM;
    float s = bq[hk];
    const float* Wh = W + (LL)h*DIM*DIM;
    for (int d = 0; d < DIM; d++) s = fmaf(b1[h*DIM + d], Wh[(LL)d*DIM + k], s);
    out[hk] = s;
}

// LN with split bf16 output
template<bool AFF>
__global__ void ln_split_k(const float* __restrict__ in, const float* __restrict__ g,
                           const float* __restrict__ b, bf16* __restrict__ oh,
                           bf16* __restrict__ ol) {
    int row = blockIdx.x;
    const float* xr = in + (LL)row*DIM;
    int t = threadIdx.x;
    float v0 = xr[t], v1 = xr[t+256], v2 = xr[t+512];
    __shared__ float rs[256], rss[256];
    rs[t]  = v0 + v1 + v2;
    rss[t] = v0*v0 + v1*v1 + v2*v2;
    __syncthreads();
    for (int off = 128; off > 0; off >>= 1) {
        if (t < off) { rs[t] += rs[t+off]; rss[t] += rss[t+off]; }
        __syncthreads();
    }
    float mu   = rs[0]  * (1.f/768.f);
    float rstd = rsqrtf(rss[0]*(1.f/768.f) - mu*mu + 1e-5f);
    float y[3] = { (v0-mu)*rstd, (v1-mu)*rstd, (v2-mu)*rstd };
    #pragma unroll
    for (int i = 0; i < 3; i++) {
        int d = t + i*256;
        float yy = y[i];
        if (AFF) yy = yy*g[d] + b[d];
        bf16 h = __float2bfloat16(yy);
        oh[(LL)row*DIM + d] = h;
        ol[(LL)row*DIM + d] = __float2bfloat16(yy - __bfloat162float(h));
    }
}

// softmax over the QUERY axis + hi/lo split of P (padded cols zeroed)
__global__ void softmax_split_k(const float* __restrict__ S, bf16* __restrict__ Ph,
                                bf16* __restrict__ Pl) {
    LL base = (LL)blockIdx.x * (SEQ*SEQP);
    int k = threadIdx.x;   // 256 threads
    if (k >= SEQ) {
        for (int q = 0; q < SEQ; q++) {
            Ph[base + (LL)q*SEQP + k] = __float2bfloat16(0.f);
            Pl[base + (LL)q*SEQP + k] = __float2bfloat16(0.f);
        }
        return;
    }
    float mx = -1e30f;
    for (int q = 0; q < SEQ; q++) mx = fmaxf(mx, S[base + (LL)q*SEQP + k]);
    float sum = 0.f;
    for (int q = 0; q < SEQ; q++) sum += expf(S[base + (LL)q*SEQP + k] - mx);
    float inv = 1.f / sum;
    for (int q = 0; q < SEQ; q++) {
        float p = expf(S[base + (LL)q*SEQP + k] - mx) * inv;
        bf16 h = __float2bfloat16(p);
        Ph[base + (LL)q*SEQP + k] = h;
        Pl[base + (LL)q*SEQP + k] = __float2bfloat16(p - __bfloat162float(h));
    }
}

__global__ void final_head_k(const float* __restrict__ h, const float* __restrict__ g,
                             const float* __restrict__ b, const float* __restrict__ Wc,
                             const float* __restrict__ bc, float* __restrict__ out) {
    int bi = blockIdx.x;
    const float* xr = h + (LL)bi*SEQ*DIM;
    int t = threadIdx.x;
    float v0 = xr[t], v1 = xr[t+256], v2 = xr[t+512];
    __shared__ float rs[256], rss[256];
    rs[t]  = v0 + v1 + v2;
    rss[t] = v0*v0 + v1*v1 + v2*v2;
    __syncthreads();
    for (int off = 128; off > 0; off >>= 1) {
        if (t < off) { rs[t] += rs[t+off]; rss[t] += rss[t+off]; }
        __syncthreads();
    }
    float mu   = rs[0]  * (1.f/768.f);
    float rstd = rsqrtf(rss[0]*(1.f/768.f) - mu*mu + 1e-5f);
    __shared__ float pa[NC][256];
    float a[NC] = {0.f, 0.f, 0.f, 0.f};
    float vv[3] = {v0, v1, v2};
    #pragma unroll
    for (int i = 0; i < 3; i++) {
        int d = t + i*256;
        float y = (vv[i]-mu)*rstd*g[d] + b[d];
        #pragma unroll
        for (int c = 0; c < NC; c++) a[c] = fmaf(y, Wc[d*NC + c], a[c]);
    }
    #pragma unroll
    for (int c = 0; c < NC; c++) pa[c][t] = a[c];
    __syncthreads();
    for (int off = 128; off > 0; off >>= 1) {
        if (t < off) {
            #pragma unroll
            for (int c = 0; c < NC; c++) pa[c][t] += pa[c][t+off];
        }
        __syncthreads();
    }
    if (t < NC) out[bi*NC + t] = pa[t][0] + bc[t];
}

// ---------------- orchestration ----------------
extern "C" void kernel_launch(void* const* d_in, const int* in_sizes, int n_in,
                              void* d_out, int out_size)
{
    const float* x      = (const float*)d_in[0];
    const float* Wpatch = (const float*)d_in[1];
    const float* bpatch = (const float*)d_in[2];
    const float* cls    = (const float*)d_in[3];
    const float* pos    = (const float*)d_in[4];
    const float* ln1g   = (const float*)d_in[5];
    const float* ln1b   = (const float*)d_in[6];
    const float* Wq     = (const float*)d_in[7];
    const float* bq     = (const float*)d_in[8];
    const float* Wk     = (const float*)d_in[9];
    const float* bk     = (const float*)d_in[10];
    const float* Wv     = (const float*)d_in[11];
    const float* bv     = (const float*)d_in[12];
    const float* Wo     = (const float*)d_in[13];
    const float* bo     = (const float*)d_in[14];
    const float* ln2g   = (const float*)d_in[15];
    const float* ln2b   = (const float*)d_in[16];
    const float* W1     = (const float*)d_in[17];
    const float* b1m    = (const float*)d_in[18];
    const float* W2     = (const float*)d_in[19];
    const float* b2m    = (const float*)d_in[20];
    const float* lnfg   = (const float*)d_in[21];
    const float* lnfb   = (const float*)d_in[22];
    const float* Wc     = (const float*)d_in[23];
    const float* bc     = (const float*)d_in[24];
    float* out = (float*)d_out;

    float *PO, *H, *Bf, *S;
    bf16 *XnH, *XnL, *XpH, *XpL, *Qh, *Ql, *Kh, *Kl, *Vh, *Vl, *Ph, *Pl, *Bh, *Bl;
    { void* p;
      cudaGetSymbolAddress(&p, g_PO);  PO  = (float*)p;
      cudaGetSymbolAddress(&p, g_H);   H   = (float*)p;
      cudaGetSymbolAddress(&p, g_Bf);  Bf  = (float*)p;
      cudaGetSymbolAddress(&p, g_S);   S   = (float*)p;
      cudaGetSymbolAddress(&p, g_XnH); XnH = (bf16*)p;
      cudaGetSymbolAddress(&p, g_XnL); XnL = (bf16*)p;
      cudaGetSymbolAddress(&p, g_XpH); XpH = (bf16*)p;
      cudaGetSymbolAddress(&p, g_XpL); XpL = (bf16*)p;
      cudaGetSymbolAddress(&p, g_Qh);  Qh  = (bf16*)p;
      cudaGetSymbolAddress(&p, g_Ql);  Ql  = (bf16*)p;
      cudaGetSymbolAddress(&p, g_Kh);  Kh  = (bf16*)p;
      cudaGetSymbolAddress(&p, g_Kl);  Kl  = (bf16*)p;
      cudaGetSymbolAddress(&p, g_Vh);  Vh  = (bf16*)p;
      cudaGetSymbolAddress(&p, g_Vl);  Vl  = (bf16*)p;
      cudaGetSymbolAddress(&p, g_Ph);  Ph  = (bf16*)p;
      cudaGetSymbolAddress(&p, g_Pl);  Pl  = (bf16*)p;
      cudaGetSymbolAddress(&p, g_Bh);  Bh  = (bf16*)p;
      cudaGetSymbolAddress(&p, g_Bl);  Bl  = (bf16*)p;
    }

    static int attr_done = 0;
    if (!attr_done) {
        cudaFuncSetAttribute(mm2<EPI_BIAS, false>,                     cudaFuncAttributeMaxDynamicSharedMemorySize, MM_SMEM);
        cudaFuncSetAttribute(mm2<EPI_BIAS|EPI_SPLIT, false>,           cudaFuncAttributeMaxDynamicSharedMemorySize, MM_SMEM);
        cudaFuncSetAttribute(mm2<EPI_BIAS|EPI_RES, false>,             cudaFuncAttributeMaxDynamicSharedMemorySize, MM_SMEM);
        cudaFuncSetAttribute(mm2<EPI_BIAS|EPI_GELU|EPI_SPLIT, false>,  cudaFuncAttributeMaxDynamicSharedMemorySize, MM_SMEM);
        cudaFuncSetAttribute(mm2<0, false>,                            cudaFuncAttributeMaxDynamicSharedMemorySize, MM_SMEM);
        cudaFuncSetAttribute(mm2<EPI_SPLIT, true>,                     cudaFuncAttributeMaxDynamicSharedMemorySize, MM_SMEM);
        attr_done = 1;
    }

    const float inv_scale = 1.0f / sqrtf(768.0f);

    // ---- patch embed ----
    im2col_split<<<(PROWS*DIM + 255)/256, 256>>>(x, XpH, XpL);
    split_k<<<((DIM*DIM/4) + 255)/256, 256>>>((const float4*)Wpatch, Bh, Bl, DIM*DIM/4);
    mm2<EPI_BIAS, false><<<dim3(DIM/128, (PROWS+127)/128, 1), 512, MM_SMEM>>>(
        XpH, XpL, Bh, Bl, PO, nullptr, nullptr, bpatch, nullptr,
        PROWS, DIM, DIM, DIM, DIM, DIM, DIM,
        1, 0, 0, 0, 0, 0, 0, 1.f);
    assemble_k<<<(ROWS*DIM + 255)/256, 256>>>(PO, cls, pos, H);

    // ---- transformer layers ----
    for (int l = 0; l < NLAYER; l++) {
        const float* ln1g_l = ln1g + (LL)l*NH*DIM;
        const float* ln1b_l = ln1b + (LL)l*NH*DIM;
        const float* Wqkv[3] = { Wq + (LL)l*NH*DIM*DIM, Wk + (LL)l*NH*DIM*DIM, Wv + (LL)l*NH*DIM*DIM };
        const float* bqkv[3] = { bq + (LL)l*NH*DIM,     bk + (LL)l*NH*DIM,     bv + (LL)l*NH*DIM };
        bf16* QKVh[3] = { Qh, Kh, Vh };
        bf16* QKVl[3] = { Ql, Kl, Vl };
        const float* Wo_l = Wo  + (LL)l*HDK*DIM;
        const float* bo_l = bo  + (LL)l*DIM;
        const float* g2_l = ln2g + (LL)l*DIM;
        const float* b2_l = ln2b + (LL)l*DIM;
        const float* W1_l = W1  + (LL)l*DIM*MLP;
        const float* b1_l = b1m + (LL)l*MLP;
        const float* W2_l = W2  + (LL)l*MLP*DIM;
        const float* bb2_l= b2m + (LL)l*DIM;

        // LN1 (affine folded into QKV weights), split output
        ln_split_k<false><<<ROWS, 256>>>(H, nullptr, nullptr, XnH, XnL);

        for (int m = 0; m < 3; m++) {
            fold_split_w<<<dim3(DIM/32, DIM/32, NH), dim3(32,8)>>>(Wqkv[m], ln1g_l, Bh, Bl);
            fold_b_k<<<(HDK + 255)/256, 256>>>(Wqkv[m], ln1b_l, bqkv[m], Bf);
            mm2<EPI_BIAS|EPI_SPLIT, false><<<dim3(HDK/128, (ROWS+127)/128, 1), 512, MM_SMEM>>>(
                XnH, XnL, Bh, Bl, nullptr, QKVh[m], QKVl[m], Bf, nullptr,
                ROWS, HDK, HDK, DIM, DIM, DIM, HDK,
                1, 0, 0, 0, 0, 0, 0, 1.f);
        }

        // scores[q][k_] = Q·K^T / sqrt(768)   (bf16 3-pass, batched)
        mm2<0, false><<<dim3(2, 2, NBH), 512, MM_SMEM>>>(
            Qh, Ql, Kh, Kl, S, nullptr, nullptr, nullptr, nullptr,
            SEQ, SEQ, SEQ, DIM,
            HDK, HDK, SEQP,
            NH, (LL)SEQ*HDK, (LL)DIM, (LL)SEQ*HDK, (LL)DIM,
            (LL)NH*SEQ*SEQP, (LL)SEQ*SEQP, inv_scale);

        // softmax over query axis + P split (pads zeroed)
        softmax_split_k<<<NBH, 256>>>(S, Ph, Pl);

        // av = P·V (trans-B), written split in cat layout -> Qh/Ql
        mm2<EPI_SPLIT, true><<<dim3(DIM/128, 2, NBH), 512, MM_SMEM>>>(
            Ph, Pl, Vh, Vl, nullptr, Qh, Ql, nullptr, nullptr,
            SEQ, DIM, SEQ, SEQP,
            SEQP, HDK, HDK,
            NH, (LL)NH*SEQ*SEQP, (LL)SEQ*SEQP, (LL)SEQ*HDK, (LL)DIM,
            (LL)SEQ*HDK, (LL)DIM, 1.f);

        // out proj + bias + residual -> H
        tsplit_k<<<dim3(HDK/32, DIM/32), dim3(32,8)>>>(Wo_l, Bh, Bl, HDK, DIM);
        mm2<EPI_BIAS|EPI_RES, false><<<dim3(DIM/128, (ROWS+127)/128, 1), 512, MM_SMEM>>>(
            Qh, Ql, Bh, Bl, H, nullptr, nullptr, bo_l, H,
            ROWS, DIM, DIM, HDK, HDK, HDK, DIM,
            1, 0, 0, 0, 0, 0, 0, 1.f);

        // MLP
        ln_split_k<true><<<ROWS, 256>>>(H, g2_l, b2_l, XnH, XnL);
        tsplit_k<<<dim3(DIM/32, MLP/32), dim3(32,8)>>>(W1_l, Bh, Bl, DIM, MLP);
        mm2<EPI_BIAS|EPI_GELU|EPI_SPLIT, false><<<dim3(MLP/128, (ROWS+127)/128, 1), 512, MM_SMEM>>>(
            XnH, XnL, Bh, Bl, nullptr, Kh, Kl, b1_l, nullptr,
            ROWS, MLP, MLP, DIM, DIM, DIM, MLP,
            1, 0, 0, 0, 0, 0, 0, 1.f);

        tsplit_k<<<dim3(MLP/32, DIM/32), dim3(32,8)>>>(W2_l, Bh, Bl, MLP, DIM);
        mm2<EPI_BIAS|EPI_RES, false><<<dim3(DIM/128, (ROWS+127)/128, 1), 512, MM_SMEM>>>(
            Kh, Kl, Bh, Bl, H, nullptr, nullptr, bb2_l, H,
            ROWS, DIM, DIM, MLP, MLP, MLP, DIM,
            1, 0, 0, 0, 0, 0, 0, 1.f);
    }

    // ---- final LN on CLS + classifier ----
    final_head_k<<<BATCH, 256>>>(H, lnfg, lnfb, Wc, bc, out);
}

// round 6
// speedup vs baseline: 4.3411x; 1.3445x over previous
#include <cuda_runtime.h>
#include <cuda_fp16.h>
#include <math.h>
#include <stdint.h>

typedef long long LL;
typedef __half fp16;

#define BATCH   16
#define SEQ     197
#define SEQP    256
#define NPATCH  196
#define DIM     768
#define NH      12
#define HDK     9216
#define MLP     3072
#define ROWS    (BATCH*SEQ)     /* 3152 */
#define PROWS   (BATCH*NPATCH)  /* 3136 */
#define NLAYER  4
#define NC      4
#define NBH     (BATCH*NH)      /* 192 */

// ---------------- scratch (device globals) ----------------
__device__ float g_PO [PROWS*DIM];
__device__ float g_H  [ROWS*DIM];
__device__ float g_Bf [HDK];
__device__ float g_S  [(LL)NBH*SEQ*SEQP];

__device__ fp16 g_Xn [ROWS*DIM];                          // LN out (hi only)
__device__ fp16 g_Xp [PROWS*DIM];                         // im2col (hi only)
__device__ fp16 g_Qh [(LL)ROWS*HDK], g_Ql [(LL)ROWS*HDK]; // Q split; later cat (hi)
__device__ fp16 g_Kh [(LL)ROWS*HDK], g_Kl [(LL)ROWS*HDK]; // K split; later Hid (hi)
__device__ fp16 g_Vh [(LL)ROWS*HDK], g_Vl [(LL)ROWS*HDK]; // V split
__device__ fp16 g_Ph [(LL)NBH*SEQ*SEQP];                  // probs (hi only)
__device__ fp16 g_Bh [(LL)DIM*HDK], g_Bl [(LL)DIM*HDK];   // weight split

// ---------------- helpers ----------------
__device__ __forceinline__ uint32_t smem_u32(const void* p) {
    uint32_t a;
    asm("{ .reg .u64 t; cvta.to.shared.u64 t, %1; cvt.u32.u64 %0, t; }" : "=r"(a) : "l"(p));
    return a;
}
__device__ __forceinline__ uint32_t swz(uint32_t off) { return off ^ ((off >> 3) & 0x70); }

__device__ __forceinline__ void cp16z(uint32_t dst, const void* src, uint32_t sz) {
    asm volatile("cp.async.cg.shared.global [%0], [%1], 16, %2;\n"
                 :: "r"(dst), "l"(src), "r"(sz) : "memory");
}
__device__ __forceinline__ void cp_commit() {
    asm volatile("cp.async.commit_group;\n" ::: "memory");
}
__device__ __forceinline__ void ldsm4(uint32_t* r, uint32_t addr) {
    asm volatile("ldmatrix.sync.aligned.m8n8.x4.shared.b16 {%0,%1,%2,%3}, [%4];\n"
                 : "=r"(r[0]), "=r"(r[1]), "=r"(r[2]), "=r"(r[3]) : "r"(addr));
}
__device__ __forceinline__ void ldsm4t(uint32_t* r, uint32_t addr) {
    asm volatile("ldmatrix.sync.aligned.m8n8.x4.trans.shared.b16 {%0,%1,%2,%3}, [%4];\n"
                 : "=r"(r[0]), "=r"(r[1]), "=r"(r[2]), "=r"(r[3]) : "r"(addr));
}
__device__ __forceinline__ void mma16816(float* c, const uint32_t* a, const uint32_t* b) {
    asm volatile(
        "mma.sync.aligned.m16n8k16.row.col.f32.f16.f16.f32 "
        "{%0,%1,%2,%3}, {%4,%5,%6,%7}, {%8,%9}, {%0,%1,%2,%3};\n"
        : "+f"(c[0]), "+f"(c[1]), "+f"(c[2]), "+f"(c[3])
        : "r"(a[0]), "r"(a[1]), "r"(a[2]), "r"(a[3]), "r"(b[0]), "r"(b[1]));
}
__device__ __forceinline__ void split2(float v, fp16& h, fp16& l) {
    h = __float2half_rn(v);
    l = __float2half_rn(v - __half2float(h));
}

// ---------------- unified mma GEMM ----------------
// PASSES=2: C = alpha*A·(Bh+Bl)^T + epi   (A plain fp16)
// PASSES=3: C = alpha*(Ah+Al)·(Bh+Bl)^T   (drop Al·Bl)
// A: [M,K] K-major (lda). BT=false: B [N,K] K-major. BT=true: B [K,N] N-major.
#define EPI_BIAS   1
#define EPI_RES    2
#define EPI_GELU   4
#define EPI_SPLIT  8
#define EPI_SPLITH 16

#define MM_SMEM 196608

template<bool BT, int PASSES>
__device__ __forceinline__ void load_tile2(uint32_t stg,
    const fp16* __restrict__ Ah, const fp16* __restrict__ Al,
    const fp16* __restrict__ Bh, const fp16* __restrict__ Bl,
    int bm, int bn, int M, int Brows, int lda, int ldb, int k0, int tid)
{
    constexpr uint32_t SAH = 0;
    constexpr uint32_t SAL = 16384;
    constexpr uint32_t SBH = (PASSES == 3) ? 32768 : 16384;
    constexpr uint32_t SBL = SBH + 16384;
    {   // A: 128 rows x 128B per matrix
        int row = tid >> 2;
        int j0  = tid & 3;
        int gm = bm + row;
        uint32_t sz = (gm < M) ? 16u : 0u;
        int gmc = (gm < M) ? gm : (M-1);
        const char* pAh = (const char*)(Ah + (LL)gmc*lda + k0);
        const char* pAl = (PASSES == 3) ? (const char*)(Al + (LL)gmc*lda + k0) : nullptr;
        #pragma unroll
        for (int jj = 0; jj < 2; jj++) {
            int j = j0 + jj*4;
            uint32_t so = swz((uint32_t)row*128u + (uint32_t)j*16u);
            cp16z(stg + SAH + so, pAh + j*16, sz);
            if (PASSES == 3) cp16z(stg + SAL + so, pAl + j*16, sz);
        }
    }
    if (!BT) {
        int row = tid >> 2;
        int j0  = tid & 3;
        int gn = bn + row;
        uint32_t sz = (gn < Brows) ? 16u : 0u;
        int gnc = (gn < Brows) ? gn : (Brows-1);
        const char* pBh = (const char*)(Bh + (LL)gnc*ldb + k0);
        const char* pBl = (const char*)(Bl + (LL)gnc*ldb + k0);
        #pragma unroll
        for (int jj = 0; jj < 2; jj++) {
            int j = j0 + jj*4;
            uint32_t so = swz((uint32_t)row*128u + (uint32_t)j*16u);
            cp16z(stg + SBH + so, pBh + j*16, sz);
            cp16z(stg + SBL + so, pBl + j*16, sz);
        }
    } else {
        // B: 64 k-rows x 256B per matrix
        int krow = tid >> 3;
        int j0   = tid & 7;
        int gk = k0 + krow;
        uint32_t sz = (gk < Brows) ? 16u : 0u;
        int gkc = (gk < Brows) ? gk : (Brows-1);
        const char* pBh = (const char*)(Bh + (LL)gkc*ldb + bn);
        const char* pBl = (const char*)(Bl + (LL)gkc*ldb + bn);
        #pragma unroll
        for (int jj = 0; jj < 2; jj++) {
            int j = j0 + jj*8;
            uint32_t so = (uint32_t)krow*256u + (((uint32_t)j*16u) ^ (((uint32_t)krow & 7u) << 4));
            cp16z(stg + SBH + so, pBh + j*16, sz);
            cp16z(stg + SBL + so, pBl + j*16, sz);
        }
    }
}

template<int EPI, bool BT, int PASSES>
__global__ void __launch_bounds__(512, 1)
mm2(const fp16* __restrict__ Ah, const fp16* __restrict__ Al,
    const fp16* __restrict__ Bh, const fp16* __restrict__ Bl,
    float* __restrict__ C, fp16* __restrict__ Ch, fp16* __restrict__ Cl,
    const float* __restrict__ bias, const float* __restrict__ res,
    int M, int N, int Brows, int K,
    int lda, int ldb, int ldc,
    int zdiv, LL sA0, LL sA1, LL sB0, LL sB1, LL sC0, LL sC1,
    float alpha)
{
    constexpr uint32_t SAH = 0;
    constexpr uint32_t SAL = 16384;
    constexpr uint32_t SBH = (PASSES == 3) ? 32768 : 16384;
    constexpr uint32_t SBL = SBH + 16384;
    constexpr int STG  = (PASSES == 3) ? 65536 : 49152;
    constexpr int NSTG = (PASSES == 3) ? 3 : 4;

    extern __shared__ char smem[];
    uint32_t sb = smem_u32(smem);
    const int tid  = threadIdx.x;
    const int wid  = tid >> 5;
    const int lane = tid & 31;
    const int bm = blockIdx.y * 128;
    const int bn = blockIdx.x * 128;
    const int zo = blockIdx.z / zdiv, zi = blockIdx.z - zo*zdiv;
    Ah += zo*sA0 + zi*sA1;
    if (PASSES == 3) Al += zo*sA0 + zi*sA1;
    Bh += zo*sB0 + zi*sB1;  Bl += zo*sB0 + zi*sB1;
    const LL cbase = zo*sC0 + zi*sC1;

    const int m_warp = (wid & 3) * 32;   // 4 warps along M
    const int n_warp = (wid >> 2) * 32;  // 4 warps along N

    float acc[2][4][4];
    #pragma unroll
    for (int mt = 0; mt < 2; mt++)
        #pragma unroll
        for (int nt = 0; nt < 4; nt++)
            #pragma unroll
            for (int e = 0; e < 4; e++) acc[mt][nt][e] = 0.f;

    const int NCH = K >> 6;

    #pragma unroll
    for (int s = 0; s < NSTG-1; s++) {
        if (s < NCH)
            load_tile2<BT, PASSES>(sb + s*STG, Ah, Al, Bh, Bl, bm, bn, M, Brows, lda, ldb, s*64, tid);
        cp_commit();
    }

    const int lar = lane & 15;
    const int lac = (lane >> 4) * 16;
    const int lbr = ((lane & 16) >> 1) + (lane & 7);
    const int lbc = ((lane >> 3) & 1) * 16;

    for (int c = 0; c < NCH; c++) {
        if (c + NSTG-1 < NCH)
            load_tile2<BT, PASSES>(sb + ((c + NSTG-1) % NSTG)*STG,
                                   Ah, Al, Bh, Bl, bm, bn, M, Brows, lda, ldb, (c + NSTG-1)*64, tid);
        cp_commit();
        asm volatile("cp.async.wait_group %0;\n" :: "n"(NSTG-1) : "memory");
        __syncthreads();

        uint32_t stg = sb + (c % NSTG)*STG;
        #pragma unroll
        for (int ks = 0; ks < 4; ks++) {
            uint32_t a_h[2][4], a_l[2][4], b_h[4][2], b_l[4][2];
            #pragma unroll
            for (int mt = 0; mt < 2; mt++) {
                uint32_t off = swz((uint32_t)(m_warp + mt*16 + lar)*128u + ks*32 + lac);
                ldsm4(a_h[mt], stg + SAH + off);
                if (PASSES == 3) ldsm4(a_l[mt], stg + SAL + off);
            }
            if (!BT) {
                #pragma unroll
                for (int p = 0; p < 2; p++) {
                    uint32_t off = swz((uint32_t)(n_warp + p*16 + lbr)*128u + ks*32 + lbc);
                    uint32_t rh[4], rl[4];
                    ldsm4(rh, stg + SBH + off);
                    ldsm4(rl, stg + SBL + off);
                    b_h[2*p][0]=rh[0]; b_h[2*p][1]=rh[1]; b_h[2*p+1][0]=rh[2]; b_h[2*p+1][1]=rh[3];
                    b_l[2*p][0]=rl[0]; b_l[2*p][1]=rl[1]; b_l[2*p+1][0]=rl[2]; b_l[2*p+1][1]=rl[3];
                }
            } else {
                #pragma unroll
                for (int p = 0; p < 2; p++) {
                    uint32_t row = (uint32_t)(ks*16 + (lane & 15));
                    uint32_t nb  = (uint32_t)((n_warp + p*16)*2) + (((uint32_t)lane >> 4) << 4);
                    uint32_t off = row*256u + (nb ^ ((row & 7u) << 4));
                    uint32_t rh[4], rl[4];
                    ldsm4t(rh, stg + SBH + off);
                    ldsm4t(rl, stg + SBL + off);
                    b_h[2*p][0]=rh[0]; b_h[2*p][1]=rh[1]; b_h[2*p+1][0]=rh[2]; b_h[2*p+1][1]=rh[3];
                    b_l[2*p][0]=rl[0]; b_l[2*p][1]=rl[1]; b_l[2*p+1][0]=rl[2]; b_l[2*p+1][1]=rl[3];
                }
            }
            #pragma unroll
            for (int mt = 0; mt < 2; mt++)
                #pragma unroll
                for (int nt = 0; nt < 4; nt++) {
                    mma16816(acc[mt][nt], a_h[mt], b_h[nt]);
                    mma16816(acc[mt][nt], a_h[mt], b_l[nt]);
                    if (PASSES == 3) mma16816(acc[mt][nt], a_l[mt], b_h[nt]);
                }
        }
        __syncthreads();
    }

    // ---- epilogue ----
    #pragma unroll
    for (int mt = 0; mt < 2; mt++) {
        #pragma unroll
        for (int half = 0; half < 2; half++) {
            int m = bm + m_warp + mt*16 + (lane >> 2) + half*8;
            if (m >= M) continue;
            #pragma unroll
            for (int nt = 0; nt < 4; nt++) {
                int n = bn + n_warp + nt*8 + (lane & 3)*2;
                if (n >= N) continue;
                float v0 = acc[mt][nt][half*2 + 0] * alpha;
                float v1 = acc[mt][nt][half*2 + 1] * alpha;
                if (EPI & EPI_BIAS) { v0 += __ldg(&bias[n]); v1 += __ldg(&bias[n+1]); }
                if (EPI & EPI_RES) {
                    const float2 rv = *(const float2*)(res + (LL)m*ldc + n);
                    v0 += rv.x; v1 += rv.y;
                }
                if (EPI & EPI_GELU) {
                    v0 = 0.5f*v0*(1.f + erff(v0*0.70710678118654752440f));
                    v1 = 0.5f*v1*(1.f + erff(v1*0.70710678118654752440f));
                }
                if (EPI & EPI_SPLIT) {
                    fp16 h0, l0, h1, l1;
                    split2(v0, h0, l0); split2(v1, h1, l1);
                    __half2 ph; ph.x = h0; ph.y = h1;
                    __half2 pl; pl.x = l0; pl.y = l1;
                    *(__half2*)(Ch + cbase + (LL)m*ldc + n) = ph;
                    *(__half2*)(Cl + cbase + (LL)m*ldc + n) = pl;
                } else if (EPI & EPI_SPLITH) {
                    __half2 ph; ph.x = __float2half_rn(v0); ph.y = __float2half_rn(v1);
                    *(__half2*)(Ch + cbase + (LL)m*ldc + n) = ph;
                } else {
                    if (n + 1 < N) *(float2*)(C + cbase + (LL)m*ldc + n) = make_float2(v0, v1);
                    else C[cbase + (LL)m*ldc + n] = v0;
                }
            }
        }
    }
}

// ---------------- conversion / small kernels ----------------
__global__ void split_k(const float4* __restrict__ in, fp16* __restrict__ hi,
                        fp16* __restrict__ lo, int n4) {
    int i = blockIdx.x*blockDim.x + threadIdx.x;
    if (i >= n4) return;
    float4 v = in[i];
    float vv[4] = { v.x, v.y, v.z, v.w };
    #pragma unroll
    for (int e = 0; e < 4; e++) {
        fp16 h, l; split2(vv[e], h, l);
        hi[i*4 + e] = h;
        lo[i*4 + e] = l;
    }
}

__global__ void fold_split_w(const float* __restrict__ W, const float* __restrict__ g,
                             fp16* __restrict__ Bh, fp16* __restrict__ Bl) {
    __shared__ float t[32][33];
    int h = blockIdx.z, d0 = blockIdx.y*32, k0 = blockIdx.x*32;
    const float* Wh = W + (LL)h*DIM*DIM;
    for (int i = threadIdx.y; i < 32; i += 8)
        t[i][threadIdx.x] = Wh[(LL)(d0+i)*DIM + k0 + threadIdx.x] * g[h*DIM + d0 + i];
    __syncthreads();
    for (int i = threadIdx.y; i < 32; i += 8) {
        float v = t[threadIdx.x][i];
        LL o = (LL)(h*DIM + k0 + i)*DIM + d0 + threadIdx.x;
        fp16 hb, lb; split2(v, hb, lb);
        Bh[o] = hb;
        Bl[o] = lb;
    }
}

__global__ void tsplit_k(const float* __restrict__ W, fp16* __restrict__ Bh,
                         fp16* __restrict__ Bl, int K, int N) {
    __shared__ float t[32][33];
    int k0 = blockIdx.x*32, n0 = blockIdx.y*32;
    for (int i = threadIdx.y; i < 32; i += 8)
        t[i][threadIdx.x] = W[(LL)(k0+i)*N + n0 + threadIdx.x];
    __syncthreads();
    for (int i = threadIdx.y; i < 32; i += 8) {
        float v = t[threadIdx.x][i];
        LL o = (LL)(n0+i)*K + k0 + threadIdx.x;
        fp16 hb, lb; split2(v, hb, lb);
        Bh[o] = hb;
        Bl[o] = lb;
    }
}

__global__ void im2col_half(const float* __restrict__ x, fp16* __restrict__ oh) {
    int idx = blockIdx.x*blockDim.x + threadIdx.x;
    if (idx >= PROWS*DIM) return;
    int f   = idx % DIM;
    int row = idx / DIM;
    int b = row / NPATCH, n = row % NPATCH;
    int ph = n / 14, pw = n % 14;
    int c = f / 256, r = f % 256;
    int p = r / 16,  q = r % 16;
    oh[idx] = __float2half_rn(x[(((LL)b*3 + c)*224 + ph*16 + p)*224 + pw*16 + q]);
}

__global__ void assemble_k(const float* __restrict__ patch, const float* __restrict__ cls,
                           const float* __restrict__ pos, float* __restrict__ h) {
    int idx = blockIdx.x*blockDim.x + threadIdx.x;
    if (idx >= ROWS*DIM) return;
    int d = idx % DIM;
    int row = idx / DIM;
    int b = row / SEQ, s = row % SEQ;
    float v = (s == 0) ? cls[d] : patch[((LL)b*NPATCH + (s-1))*DIM + d];
    h[idx] = v + pos[s*DIM + d];
}

// Bf[h*DIM+k] = bq[h][k] + sum_d b1[h][d] * W[h][d][k]   (parallel 8-way d-split)
__global__ void fold_b_k(const float* __restrict__ W, const float* __restrict__ b1,
                         const float* __restrict__ bq, float* __restrict__ out) {
    int kb = blockIdx.x * 32;          // 288 blocks
    int h  = kb / DIM;
    int k0 = kb % DIM;
    int t  = threadIdx.x;              // 256
    int kk = t & 31;
    int dz = t >> 5;                   // 8 groups
    const float* Wh = W + (LL)h*DIM*DIM;
    const float* b1h = b1 + (LL)h*DIM;
    float s = 0.f;
    #pragma unroll 4
    for (int d = dz*96; d < dz*96 + 96; d++)
        s = fmaf(b1h[d], Wh[(LL)d*DIM + k0 + kk], s);
    __shared__ float red[256];
    red[t] = s;
    __syncthreads();
    if (t < 128) red[t] += red[t+128];
    __syncthreads();
    if (t < 64) red[t] += red[t+64];
    __syncthreads();
    if (t < 32) out[kb + t] = red[t] + red[t+32] + bq[kb + t];
}

// LN writing plain fp16 (hi only)
template<bool AFF>
__global__ void ln_half_k(const float* __restrict__ in, const float* __restrict__ g,
                          const float* __restrict__ b, fp16* __restrict__ oh) {
    int row = blockIdx.x;
    const float* xr = in + (LL)row*DIM;
    int t = threadIdx.x;
    float v0 = xr[t], v1 = xr[t+256], v2 = xr[t+512];
    __shared__ float rs[256], rss[256];
    rs[t]  = v0 + v1 + v2;
    rss[t] = v0*v0 + v1*v1 + v2*v2;
    __syncthreads();
    for (int off = 128; off > 0; off >>= 1) {
        if (t < off) { rs[t] += rs[t+off]; rss[t] += rss[t+off]; }
        __syncthreads();
    }
    float mu   = rs[0]  * (1.f/768.f);
    float rstd = rsqrtf(rss[0]*(1.f/768.f) - mu*mu + 1e-5f);
    float y[3] = { (v0-mu)*rstd, (v1-mu)*rstd, (v2-mu)*rstd };
    #pragma unroll
    for (int i = 0; i < 3; i++) {
        int d = t + i*256;
        float yy = y[i];
        if (AFF) yy = yy*g[d] + b[d];
        oh[(LL)row*DIM + d] = __float2half_rn(yy);
    }
}

// softmax over QUERY axis; writes plain fp16 P (pads zeroed). grid (NBH, 2) x 128
__global__ void softmax_half_k(const float* __restrict__ S, fp16* __restrict__ Ph) {
    LL base = (LL)blockIdx.x * (SEQ*SEQP);
    int k = blockIdx.y*128 + threadIdx.x;
    if (k >= SEQ) {
        for (int q = 0; q < SEQ; q++) Ph[base + (LL)q*SEQP + k] = __float2half_rn(0.f);
        return;
    }
    float mx = -1e30f;
    for (int q = 0; q < SEQ; q++) mx = fmaxf(mx, S[base + (LL)q*SEQP + k]);
    float sum = 0.f;
    for (int q = 0; q < SEQ; q++) sum += expf(S[base + (LL)q*SEQP + k] - mx);
    float inv = 1.f / sum;
    for (int q = 0; q < SEQ; q++) {
        float p = expf(S[base + (LL)q*SEQP + k] - mx) * inv;
        Ph[base + (LL)q*SEQP + k] = __float2half_rn(p);
    }
}

__global__ void final_head_k(const float* __restrict__ h, const float* __restrict__ g,
                             const float* __restrict__ b, const float* __restrict__ Wc,
                             const float* __restrict__ bc, float* __restrict__ out) {
    int bi = blockIdx.x;
    const float* xr = h + (LL)bi*SEQ*DIM;
    int t = threadIdx.x;
    float v0 = xr[t], v1 = xr[t+256], v2 = xr[t+512];
    __shared__ float rs[256], rss[256];
    rs[t]  = v0 + v1 + v2;
    rss[t] = v0*v0 + v1*v1 + v2*v2;
    __syncthreads();
    for (int off = 128; off > 0; off >>= 1) {
        if (t < off) { rs[t] += rs[t+off]; rss[t] += rss[t+off]; }
        __syncthreads();
    }
    float mu   = rs[0]  * (1.f/768.f);
    float rstd = rsqrtf(rss[0]*(1.f/768.f) - mu*mu + 1e-5f);
    __shared__ float pa[NC][256];
    float a[NC] = {0.f, 0.f, 0.f, 0.f};
    float vv[3] = {v0, v1, v2};
    #pragma unroll
    for (int i = 0; i < 3; i++) {
        int d = t + i*256;
        float y = (vv[i]-mu)*rstd*g[d] + b[d];
        #pragma unroll
        for (int c = 0; c < NC; c++) a[c] = fmaf(y, Wc[d*NC + c], a[c]);
    }
    #pragma unroll
    for (int c = 0; c < NC; c++) pa[c][t] = a[c];
    __syncthreads();
    for (int off = 128; off > 0; off >>= 1) {
        if (t < off) {
            #pragma unroll
            for (int c = 0; c < NC; c++) pa[c][t] += pa[c][t+off];
        }
        __syncthreads();
    }
    if (t < NC) out[bi*NC + t] = pa[t][0] + bc[t];
}

// ---------------- orchestration ----------------
extern "C" void kernel_launch(void* const* d_in, const int* in_sizes, int n_in,
                              void* d_out, int out_size)
{
    const float* x      = (const float*)d_in[0];
    const float* Wpatch = (const float*)d_in[1];
    const float* bpatch = (const float*)d_in[2];
    const float* cls    = (const float*)d_in[3];
    const float* pos    = (const float*)d_in[4];
    const float* ln1g   = (const float*)d_in[5];
    const float* ln1b   = (const float*)d_in[6];
    const float* Wq     = (const float*)d_in[7];
    const float* bq     = (const float*)d_in[8];
    const float* Wk     = (const float*)d_in[9];
    const float* bk     = (const float*)d_in[10];
    const float* Wv     = (const float*)d_in[11];
    const float* bv     = (const float*)d_in[12];
    const float* Wo     = (const float*)d_in[13];
    const float* bo     = (const float*)d_in[14];
    const float* ln2g   = (const float*)d_in[15];
    const float* ln2b   = (const float*)d_in[16];
    const float* W1     = (const float*)d_in[17];
    const float* b1m    = (const float*)d_in[18];
    const float* W2     = (const float*)d_in[19];
    const float* b2m    = (const float*)d_in[20];
    const float* lnfg   = (const float*)d_in[21];
    const float* lnfb   = (const float*)d_in[22];
    const float* Wc     = (const float*)d_in[23];
    const float* bc     = (const float*)d_in[24];
    float* out = (float*)d_out;

    float *PO, *H, *Bf, *S;
    fp16 *Xn, *Xp, *Qh, *Ql, *Kh, *Kl, *Vh, *Vl, *Ph, *Bh, *Bl;
    { void* p;
      cudaGetSymbolAddress(&p, g_PO);  PO  = (float*)p;
      cudaGetSymbolAddress(&p, g_H);   H   = (float*)p;
      cudaGetSymbolAddress(&p, g_Bf);  Bf  = (float*)p;
      cudaGetSymbolAddress(&p, g_S);   S   = (float*)p;
      cudaGetSymbolAddress(&p, g_Xn);  Xn  = (fp16*)p;
      cudaGetSymbolAddress(&p, g_Xp);  Xp  = (fp16*)p;
      cudaGetSymbolAddress(&p, g_Qh);  Qh  = (fp16*)p;
      cudaGetSymbolAddress(&p, g_Ql);  Ql  = (fp16*)p;
      cudaGetSymbolAddress(&p, g_Kh);  Kh  = (fp16*)p;
      cudaGetSymbolAddress(&p, g_Kl);  Kl  = (fp16*)p;
      cudaGetSymbolAddress(&p, g_Vh);  Vh  = (fp16*)p;
      cudaGetSymbolAddress(&p, g_Vl);  Vl  = (fp16*)p;
      cudaGetSymbolAddress(&p, g_Ph);  Ph  = (fp16*)p;
      cudaGetSymbolAddress(&p, g_Bh);  Bh  = (fp16*)p;
      cudaGetSymbolAddress(&p, g_Bl);  Bl  = (fp16*)p;
    }

    static int attr_done = 0;
    if (!attr_done) {
        cudaFuncSetAttribute(mm2<EPI_BIAS, false, 2>,                     cudaFuncAttributeMaxDynamicSharedMemorySize, MM_SMEM);
        cudaFuncSetAttribute(mm2<EPI_BIAS|EPI_SPLIT, false, 2>,           cudaFuncAttributeMaxDynamicSharedMemorySize, MM_SMEM);
        cudaFuncSetAttribute(mm2<EPI_BIAS|EPI_RES, false, 2>,             cudaFuncAttributeMaxDynamicSharedMemorySize, MM_SMEM);
        cudaFuncSetAttribute(mm2<EPI_BIAS|EPI_GELU|EPI_SPLITH, false, 2>, cudaFuncAttributeMaxDynamicSharedMemorySize, MM_SMEM);
        cudaFuncSetAttribute(mm2<0, false, 3>,                            cudaFuncAttributeMaxDynamicSharedMemorySize, MM_SMEM);
        cudaFuncSetAttribute(mm2<EPI_SPLITH, true, 2>,                    cudaFuncAttributeMaxDynamicSharedMemorySize, MM_SMEM);
        attr_done = 1;
    }

    const float inv_scale = 1.0f / sqrtf(768.0f);

    // ---- patch embed ----
    im2col_half<<<(PROWS*DIM + 255)/256, 256>>>(x, Xp);
    split_k<<<((DIM*DIM/4) + 255)/256, 256>>>((const float4*)Wpatch, Bh, Bl, DIM*DIM/4);
    mm2<EPI_BIAS, false, 2><<<dim3(DIM/128, (PROWS+127)/128, 1), 512, MM_SMEM>>>(
        Xp, nullptr, Bh, Bl, PO, nullptr, nullptr, bpatch, nullptr,
        PROWS, DIM, DIM, DIM, DIM, DIM, DIM,
        1, 0, 0, 0, 0, 0, 0, 1.f);
    assemble_k<<<(ROWS*DIM + 255)/256, 256>>>(PO, cls, pos, H);

    // ---- transformer layers ----
    for (int l = 0; l < NLAYER; l++) {
        const float* ln1g_l = ln1g + (LL)l*NH*DIM;
        const float* ln1b_l = ln1b + (LL)l*NH*DIM;
        const float* Wqkv[3] = { Wq + (LL)l*NH*DIM*DIM, Wk + (LL)l*NH*DIM*DIM, Wv + (LL)l*NH*DIM*DIM };
        const float* bqkv[3] = { bq + (LL)l*NH*DIM,     bk + (LL)l*NH*DIM,     bv + (LL)l*NH*DIM };
        fp16* QKVh[3] = { Qh, Kh, Vh };
        fp16* QKVl[3] = { Ql, Kl, Vl };
        const float* Wo_l = Wo  + (LL)l*HDK*DIM;
        const float* bo_l = bo  + (LL)l*DIM;
        const float* g2_l = ln2g + (LL)l*DIM;
        const float* b2_l = ln2b + (LL)l*DIM;
        const float* W1_l = W1  + (LL)l*DIM*MLP;
        const float* b1_l = b1m + (LL)l*MLP;
        const float* W2_l = W2  + (LL)l*MLP*DIM;
        const float* bb2_l= b2m + (LL)l*DIM;

        // LN1 (affine folded into QKV weights), plain fp16 out
        ln_half_k<false><<<ROWS, 256>>>(H, nullptr, nullptr, Xn);

        for (int m = 0; m < 3; m++) {
            fold_split_w<<<dim3(DIM/32, DIM/32, NH), dim3(32,8)>>>(Wqkv[m], ln1g_l, Bh, Bl);
            fold_b_k<<<HDK/32, 256>>>(Wqkv[m], ln1b_l, bqkv[m], Bf);
            mm2<EPI_BIAS|EPI_SPLIT, false, 2><<<dim3(HDK/128, (ROWS+127)/128, 1), 512, MM_SMEM>>>(
                Xn, nullptr, Bh, Bl, nullptr, QKVh[m], QKVl[m], Bf, nullptr,
                ROWS, HDK, HDK, DIM, DIM, DIM, HDK,
                1, 0, 0, 0, 0, 0, 0, 1.f);
        }

        // scores = Q·K^T / sqrt(768)   (3-pass split-split, batched)
        mm2<0, false, 3><<<dim3(2, 2, NBH), 512, MM_SMEM>>>(
            Qh, Ql, Kh, Kl, S, nullptr, nullptr, nullptr, nullptr,
            SEQ, SEQ, SEQ, DIM,
            HDK, HDK, SEQP,
            NH, (LL)SEQ*HDK, (LL)DIM, (LL)SEQ*HDK, (LL)DIM,
            (LL)NH*SEQ*SEQP, (LL)SEQ*SEQP, inv_scale);

        // softmax over query axis -> plain fp16 P (pads zeroed)
        softmax_half_k<<<dim3(NBH, 2), 128>>>(S, Ph);

        // av = P·V (trans-B, 2-pass), hi-only cat -> Qh
        mm2<EPI_SPLITH, true, 2><<<dim3(DIM/128, 2, NBH), 512, MM_SMEM>>>(
            Ph, nullptr, Vh, Vl, nullptr, Qh, nullptr, nullptr, nullptr,
            SEQ, DIM, SEQ, SEQP,
            SEQP, HDK, HDK,
            NH, (LL)NH*SEQ*SEQP, (LL)SEQ*SEQP, (LL)SEQ*HDK, (LL)DIM,
            (LL)SEQ*HDK, (LL)DIM, 1.f);

        // out proj + bias + residual -> H
        tsplit_k<<<dim3(HDK/32, DIM/32), dim3(32,8)>>>(Wo_l, Bh, Bl, HDK, DIM);
        mm2<EPI_BIAS|EPI_RES, false, 2><<<dim3(DIM/128, (ROWS+127)/128, 1), 512, MM_SMEM>>>(
            Qh, nullptr, Bh, Bl, H, nullptr, nullptr, bo_l, H,
            ROWS, DIM, DIM, HDK, HDK, HDK, DIM,
            1, 0, 0, 0, 0, 0, 0, 1.f);

        // MLP
        ln_half_k<true><<<ROWS, 256>>>(H, g2_l, b2_l, Xn);
        tsplit_k<<<dim3(DIM/32, MLP/32), dim3(32,8)>>>(W1_l, Bh, Bl, DIM, MLP);
        mm2<EPI_BIAS|EPI_GELU|EPI_SPLITH, false, 2><<<dim3(MLP/128, (ROWS+127)/128, 1), 512, MM_SMEM>>>(
            Xn, nullptr, Bh, Bl, nullptr, Kh, nullptr, b1_l, nullptr,
            ROWS, MLP, MLP, DIM, DIM, DIM, MLP,
            1, 0, 0, 0, 0, 0, 0, 1.f);

        tsplit_k<<<dim3(MLP/32, DIM/32), dim3(32,8)>>>(W2_l, Bh, Bl, MLP, DIM);
        mm2<EPI_BIAS|EPI_RES, false, 2><<<dim3(DIM/128, (ROWS+127)/128, 1), 512, MM_SMEM>>>(
            Kh, nullptr, Bh, Bl, H, nullptr, nullptr, bb2_l, H,
            ROWS, DIM, DIM, MLP, MLP, MLP, DIM,
            1, 0, 0, 0, 0, 0, 0, 1.f);
    }

    // ---- final LN on CLS + classifier ----
    final_head_k<<<BATCH, 256>>>(H, lnfg, lnfb, Wc, bc, out);
}

// round 7
// speedup vs baseline: 8.3597x; 1.9257x over previous
#include <cuda_runtime.h>
#include <cuda_fp16.h>
#include <math.h>
#include <stdint.h>

typedef long long LL;
typedef __half fp16;

#define BATCH   16
#define SEQ     197
#define SEQP    256
#define NPATCH  196
#define DIM     768
#define NH      12
#define HDK     9216
#define HDK3    27648
#define MLP     3072
#define ROWS    (BATCH*SEQ)     /* 3152 */
#define PROWS   (BATCH*NPATCH)  /* 3136 */
#define NLAYER  4
#define NC      4
#define NBH     (BATCH*NH)      /* 192 */

// ---------------- scratch (device globals) ----------------
__device__ float g_PO [PROWS*DIM];
__device__ float g_H  [ROWS*DIM];
__device__ float g_Bf [HDK3];
__device__ float g_S  [(LL)NBH*SEQ*SEQP];

__device__ fp16 g_Xn  [ROWS*DIM];
__device__ fp16 g_Xp  [PROWS*DIM];
__device__ fp16 g_QKV [(LL)ROWS*HDK3];     // fused Q|K|V, ld = 27648
__device__ fp16 g_Cat [(LL)ROWS*HDK];      // attention output (cat layout)
__device__ fp16 g_Hid [(LL)ROWS*MLP];
__device__ fp16 g_Ph  [(LL)NBH*SEQ*SEQP];
__device__ fp16 g_Wqkv[(LL)3*HDK*DIM];     // fused folded QKV weight [27648][768]
__device__ fp16 g_Wt  [(LL)HDK*DIM];       // transposed/converted weight

// ---------------- helpers ----------------
__device__ __forceinline__ uint32_t smem_u32(const void* p) {
    uint32_t a;
    asm("{ .reg .u64 t; cvta.to.shared.u64 t, %1; cvt.u32.u64 %0, t; }" : "=r"(a) : "l"(p));
    return a;
}
__device__ __forceinline__ uint32_t swz(uint32_t off) { return off ^ ((off >> 3) & 0x70); }

__device__ __forceinline__ void cp16z(uint32_t dst, const void* src, uint32_t sz) {
    asm volatile("cp.async.cg.shared.global [%0], [%1], 16, %2;\n"
                 :: "r"(dst), "l"(src), "r"(sz) : "memory");
}
__device__ __forceinline__ void cp_commit() {
    asm volatile("cp.async.commit_group;\n" ::: "memory");
}
__device__ __forceinline__ void ldsm4(uint32_t* r, uint32_t addr) {
    asm volatile("ldmatrix.sync.aligned.m8n8.x4.shared.b16 {%0,%1,%2,%3}, [%4];\n"
                 : "=r"(r[0]), "=r"(r[1]), "=r"(r[2]), "=r"(r[3]) : "r"(addr));
}
__device__ __forceinline__ void ldsm4t(uint32_t* r, uint32_t addr) {
    asm volatile("ldmatrix.sync.aligned.m8n8.x4.trans.shared.b16 {%0,%1,%2,%3}, [%4];\n"
                 : "=r"(r[0]), "=r"(r[1]), "=r"(r[2]), "=r"(r[3]) : "r"(addr));
}
__device__ __forceinline__ void mma16816(float* c, const uint32_t* a, const uint32_t* b) {
    asm volatile(
        "mma.sync.aligned.m16n8k16.row.col.f32.f16.f16.f32 "
        "{%0,%1,%2,%3}, {%4,%5,%6,%7}, {%8,%9}, {%0,%1,%2,%3};\n"
        : "+f"(c[0]), "+f"(c[1]), "+f"(c[2]), "+f"(c[3])
        : "r"(a[0]), "r"(a[1]), "r"(a[2]), "r"(a[3]), "r"(b[0]), "r"(b[1]));
}

// ---------------- single-pass fp16 mma GEMM ----------------
// C[M,N] = alpha*A·B^T + epi.   A: [M,K] K-major (lda).
// BT=false: B [N,K] K-major (ldb), Brows = valid N rows (zero-filled beyond).
// BT=true : B [K,N] N-major (ldb), Brows = valid K rows (zero-filled beyond).
// Tile: BM=128 x BN=BNT x BK=64.  512 threads, 4 Mwarps x 4 Nwarps.
#define EPI_BIAS   1
#define EPI_RES    2
#define EPI_GELU   4
#define EPI_SPLITH 16

#define MM_SMEM 196608

template<bool BT, int BNT>
__device__ __forceinline__ void load_tile1(uint32_t stg,
    const fp16* __restrict__ A, const fp16* __restrict__ B,
    int bm, int bn, int M, int Brows, int lda, int ldb, int k0, int tid)
{
    constexpr uint32_t SB = 16384;
    // A: 128 rows x 128B
    #pragma unroll
    for (int it = 0; it < 2; it++) {
        int i = tid + it*512;
        int row = i >> 3, j = i & 7;
        int gm = bm + row;
        uint32_t sz = (gm < M) ? 16u : 0u;
        int gmc = (gm < M) ? gm : 0;
        const char* p = (const char*)(A + (LL)gmc*lda + k0) + j*16;
        cp16z(stg + swz((uint32_t)row*128u + (uint32_t)j*16u), p, sz);
    }
    if (!BT) {
        // B: BNT rows x 128B
        #pragma unroll
        for (int it = 0; it < BNT/64; it++) {
            int i = tid + it*512;
            int row = i >> 3, j = i & 7;
            int gn = bn + row;
            uint32_t sz = (gn < Brows) ? 16u : 0u;
            int gnc = (gn < Brows) ? gn : 0;
            const char* p = (const char*)(B + (LL)gnc*ldb + k0) + j*16;
            cp16z(stg + SB + swz((uint32_t)row*128u + (uint32_t)j*16u), p, sz);
        }
    } else {
        // B: 64 k-rows x (BNT*2) bytes
        constexpr int CPR = BNT/8;   // 16B chunks per row
        #pragma unroll
        for (int it = 0; it < BNT/64; it++) {
            int i = tid + it*512;
            int row = i / CPR, j = i % CPR;
            int gk = k0 + row;
            uint32_t sz = (gk < Brows) ? 16u : 0u;
            int gkc = (gk < Brows) ? gk : 0;
            const char* p = (const char*)(B + (LL)gkc*ldb + bn) + j*16;
            uint32_t so = (uint32_t)row*(BNT*2u) + (((uint32_t)j*16u) ^ (((uint32_t)row & 7u) << 4));
            cp16z(stg + SB + so, p, sz);
        }
    }
}

template<int EPI, bool BT, int BNT>
__global__ void __launch_bounds__(512, 1)
mm1(const fp16* __restrict__ A, const fp16* __restrict__ B,
    float* __restrict__ C, fp16* __restrict__ Ch,
    const float* __restrict__ bias, const float* __restrict__ res,
    int M, int N, int Brows, int K,
    int lda, int ldb, int ldc,
    int zdiv, LL sA0, LL sA1, LL sB0, LL sB1, LL sC0, LL sC1,
    float alpha)
{
    constexpr uint32_t SB = 16384;
    constexpr int STG  = 16384 + BNT*128;      // 48KB or 32KB
    constexpr int NSTG = MM_SMEM / STG;        // 4 or 6
    constexpr int NT   = BNT/32;               // n-frags per warp (8 or 4)

    extern __shared__ char smem[];
    uint32_t sb = smem_u32(smem);
    const int tid  = threadIdx.x;
    const int wid  = tid >> 5;
    const int lane = tid & 31;
    const int bm = blockIdx.y * 128;
    const int bn = blockIdx.x * BNT;
    const int zo = blockIdx.z / zdiv, zi = blockIdx.z - zo*zdiv;
    A += zo*sA0 + zi*sA1;
    B += zo*sB0 + zi*sB1;
    const LL cbase = zo*sC0 + zi*sC1;

    const int m_warp = (wid & 3) * 32;
    const int n_warp = (wid >> 2) * (BNT/4);

    float acc[2][NT][4];
    #pragma unroll
    for (int mt = 0; mt < 2; mt++)
        #pragma unroll
        for (int nt = 0; nt < NT; nt++)
            #pragma unroll
            for (int e = 0; e < 4; e++) acc[mt][nt][e] = 0.f;

    const int NCH = K >> 6;

    #pragma unroll
    for (int s = 0; s < NSTG-1; s++) {
        if (s < NCH)
            load_tile1<BT, BNT>(sb + s*STG, A, B, bm, bn, M, Brows, lda, ldb, s*64, tid);
        cp_commit();
    }

    const int lar = lane & 15;
    const int lac = (lane >> 4) * 16;
    const int lbr = ((lane & 16) >> 1) + (lane & 7);
    const int lbc = ((lane >> 3) & 1) * 16;

    for (int c = 0; c < NCH; c++) {
        if (c + NSTG-1 < NCH)
            load_tile1<BT, BNT>(sb + ((c + NSTG-1) % NSTG)*STG,
                                A, B, bm, bn, M, Brows, lda, ldb, (c + NSTG-1)*64, tid);
        cp_commit();
        asm volatile("cp.async.wait_group %0;\n" :: "n"(NSTG-1) : "memory");
        __syncthreads();

        uint32_t stg = sb + (c % NSTG)*STG;
        #pragma unroll
        for (int ks = 0; ks < 4; ks++) {
            uint32_t a[2][4];
            #pragma unroll
            for (int mt = 0; mt < 2; mt++) {
                uint32_t off = swz((uint32_t)(m_warp + mt*16 + lar)*128u + ks*32 + lac);
                ldsm4(a[mt], stg + off);
            }
            #pragma unroll
            for (int p = 0; p < NT/2; p++) {
                uint32_t rb[4];
                if (!BT) {
                    uint32_t off = swz((uint32_t)(n_warp + p*16 + lbr)*128u + ks*32 + lbc);
                    ldsm4(rb, stg + SB + off);
                } else {
                    uint32_t row = (uint32_t)(ks*16 + (lane & 15));
                    uint32_t nb  = (uint32_t)((n_warp + p*16)*2) + (((uint32_t)lane >> 4) << 4);
                    uint32_t off = row*(BNT*2u) + (nb ^ ((row & 7u) << 4));
                    ldsm4t(rb, stg + SB + off);
                }
                #pragma unroll
                for (int mt = 0; mt < 2; mt++) {
                    mma16816(acc[mt][2*p],   a[mt], rb);
                    mma16816(acc[mt][2*p+1], a[mt], rb+2);
                }
            }
        }
        __syncthreads();
    }

    // ---- epilogue ----
    #pragma unroll
    for (int mt = 0; mt < 2; mt++) {
        #pragma unroll
        for (int half = 0; half < 2; half++) {
            int m = bm + m_warp + mt*16 + (lane >> 2) + half*8;
            if (m >= M) continue;
            #pragma unroll
            for (int nt = 0; nt < NT; nt++) {
                int n = bn + n_warp + nt*8 + (lane & 3)*2;
                if (n >= N) continue;
                float v0 = acc[mt][nt][half*2 + 0] * alpha;
                float v1 = acc[mt][nt][half*2 + 1] * alpha;
                if (EPI & EPI_BIAS) { v0 += __ldg(&bias[n]); v1 += __ldg(&bias[n+1]); }
                if (EPI & EPI_RES) {
                    const float2 rv = *(const float2*)(res + (LL)m*ldc + n);
                    v0 += rv.x; v1 += rv.y;
                }
                if (EPI & EPI_GELU) {
                    v0 = 0.5f*v0*(1.f + erff(v0*0.70710678118654752440f));
                    v1 = 0.5f*v1*(1.f + erff(v1*0.70710678118654752440f));
                }
                if (EPI & EPI_SPLITH) {
                    __half2 ph; ph.x = __float2half_rn(v0); ph.y = __float2half_rn(v1);
                    *(__half2*)(Ch + cbase + (LL)m*ldc + n) = ph;
                } else {
                    if (n + 1 < N) *(float2*)(C + cbase + (LL)m*ldc + n) = make_float2(v0, v1);
                    else C[cbase + (LL)m*ldc + n] = v0;
                }
            }
        }
    }
}

// ---------------- conversion / small kernels ----------------
// straight fp32 -> fp16 convert
__global__ void conv_k(const float4* __restrict__ in, fp16* __restrict__ out, int n4) {
    int i = blockIdx.x*blockDim.x + threadIdx.x;
    if (i >= n4) return;
    float4 v = in[i];
    __half2 a, b;
    a.x = __float2half_rn(v.x); a.y = __float2half_rn(v.y);
    b.x = __float2half_rn(v.z); b.y = __float2half_rn(v.w);
    *(__half2*)(out + i*4)     = a;
    *(__half2*)(out + i*4 + 2) = b;
}

// fused QKV fold+transpose+convert: W_m[h][d][k]*g[h][d] -> out[(m*HDK + h*DIM + k)][d]
__global__ void fold_qkv_w(const float* __restrict__ Wq, const float* __restrict__ Wk,
                           const float* __restrict__ Wv, const float* __restrict__ g,
                           fp16* __restrict__ out) {
    __shared__ float t[32][33];
    int z = blockIdx.z;
    int m = z / NH, h = z % NH;
    const float* W = ((m == 0) ? Wq : (m == 1) ? Wk : Wv) + (LL)h*DIM*DIM;
    int d0 = blockIdx.y*32, k0 = blockIdx.x*32;
    for (int i = threadIdx.y; i < 32; i += 8)
        t[i][threadIdx.x] = W[(LL)(d0+i)*DIM + k0 + threadIdx.x] * g[h*DIM + d0 + i];
    __syncthreads();
    for (int i = threadIdx.y; i < 32; i += 8)
        out[(LL)(m*HDK + h*DIM + k0 + i)*DIM + d0 + threadIdx.x] = __float2half_rn(t[threadIdx.x][i]);
}

// fused QKV bias fold: out[m*HDK + h*DIM + k] = b_m[h][k] + sum_d b1[h][d]*W_m[h][d][k]
__global__ void fold_b3(const float* __restrict__ Wq, const float* __restrict__ Wk,
                        const float* __restrict__ Wv, const float* __restrict__ b1,
                        const float* __restrict__ bq, const float* __restrict__ bk,
                        const float* __restrict__ bv, float* __restrict__ out) {
    int kb = blockIdx.x * 32;              // over 3*HDK
    int m  = kb / HDK;
    int rem = kb - m*HDK;
    int h  = rem / DIM;
    int k0 = rem - h*DIM;
    const float* W  = ((m == 0) ? Wq : (m == 1) ? Wk : Wv) + (LL)h*DIM*DIM;
    const float* bb = ((m == 0) ? bq : (m == 1) ? bk : bv) + (LL)h*DIM;
    const float* b1h = b1 + (LL)h*DIM;
    int t  = threadIdx.x;
    int kk = t & 31;
    int dz = t >> 5;
    float s = 0.f;
    #pragma unroll 4
    for (int d = dz*96; d < dz*96 + 96; d++)
        s = fmaf(b1h[d], W[(LL)d*DIM + k0 + kk], s);
    __shared__ float red[256];
    red[t] = s;
    __syncthreads();
    if (t < 128) red[t] += red[t+128];
    __syncthreads();
    if (t < 64) red[t] += red[t+64];
    __syncthreads();
    if (t < 32) out[kb + t] = red[t] + red[t+32] + bb[k0 + t];
}

// transpose+convert: W[K][N] -> out[N][K]
__global__ void tconv_k(const float* __restrict__ W, fp16* __restrict__ out, int K, int N) {
    __shared__ float t[32][33];
    int k0 = blockIdx.x*32, n0 = blockIdx.y*32;
    for (int i = threadIdx.y; i < 32; i += 8)
        t[i][threadIdx.x] = W[(LL)(k0+i)*N + n0 + threadIdx.x];
    __syncthreads();
    for (int i = threadIdx.y; i < 32; i += 8)
        out[(LL)(n0+i)*K + k0 + threadIdx.x] = __float2half_rn(t[threadIdx.x][i]);
}

__global__ void im2col_half(const float* __restrict__ x, fp16* __restrict__ oh) {
    int idx = blockIdx.x*blockDim.x + threadIdx.x;
    if (idx >= PROWS*DIM) return;
    int f   = idx % DIM;
    int row = idx / DIM;
    int b = row / NPATCH, n = row % NPATCH;
    int ph = n / 14, pw = n % 14;
    int c = f / 256, r = f % 256;
    int p = r / 16,  q = r % 16;
    oh[idx] = __float2half_rn(x[(((LL)b*3 + c)*224 + ph*16 + p)*224 + pw*16 + q]);
}

__global__ void assemble_k(const float* __restrict__ patch, const float* __restrict__ cls,
                           const float* __restrict__ pos, float* __restrict__ h) {
    int idx = blockIdx.x*blockDim.x + threadIdx.x;
    if (idx >= ROWS*DIM) return;
    int d = idx % DIM;
    int row = idx / DIM;
    int b = row / SEQ, s = row % SEQ;
    float v = (s == 0) ? cls[d] : patch[((LL)b*NPATCH + (s-1))*DIM + d];
    h[idx] = v + pos[s*DIM + d];
}

template<bool AFF>
__global__ void ln_half_k(const float* __restrict__ in, const float* __restrict__ g,
                          const float* __restrict__ b, fp16* __restrict__ oh) {
    int row = blockIdx.x;
    const float* xr = in + (LL)row*DIM;
    int t = threadIdx.x;
    float v0 = xr[t], v1 = xr[t+256], v2 = xr[t+512];
    __shared__ float rs[256], rss[256];
    rs[t]  = v0 + v1 + v2;
    rss[t] = v0*v0 + v1*v1 + v2*v2;
    __syncthreads();
    for (int off = 128; off > 0; off >>= 1) {
        if (t < off) { rs[t] += rs[t+off]; rss[t] += rss[t+off]; }
        __syncthreads();
    }
    float mu   = rs[0]  * (1.f/768.f);
    float rstd = rsqrtf(rss[0]*(1.f/768.f) - mu*mu + 1e-5f);
    float y[3] = { (v0-mu)*rstd, (v1-mu)*rstd, (v2-mu)*rstd };
    #pragma unroll
    for (int i = 0; i < 3; i++) {
        int d = t + i*256;
        float yy = y[i];
        if (AFF) yy = yy*g[d] + b[d];
        oh[(LL)row*DIM + d] = __float2half_rn(yy);
    }
}

// softmax over QUERY axis; fp16 P out (pads zeroed). grid (NBH, 2) x 128
__global__ void softmax_half_k(const float* __restrict__ S, fp16* __restrict__ Ph) {
    LL base = (LL)blockIdx.x * (SEQ*SEQP);
    int k = blockIdx.y*128 + threadIdx.x;
    if (k >= SEQ) {
        for (int q = 0; q < SEQ; q++) Ph[base + (LL)q*SEQP + k] = __float2half_rn(0.f);
        return;
    }
    float mx = -1e30f;
    for (int q = 0; q < SEQ; q++) mx = fmaxf(mx, S[base + (LL)q*SEQP + k]);
    float sum = 0.f;
    for (int q = 0; q < SEQ; q++) sum += expf(S[base + (LL)q*SEQP + k] - mx);
    float inv = 1.f / sum;
    for (int q = 0; q < SEQ; q++) {
        float p = expf(S[base + (LL)q*SEQP + k] - mx) * inv;
        Ph[base + (LL)q*SEQP + k] = __float2half_rn(p);
    }
}

__global__ void final_head_k(const float* __restrict__ h, const float* __restrict__ g,
                             const float* __restrict__ b, const float* __restrict__ Wc,
                             const float* __restrict__ bc, float* __restrict__ out) {
    int bi = blockIdx.x;
    const float* xr = h + (LL)bi*SEQ*DIM;
    int t = threadIdx.x;
    float v0 = xr[t], v1 = xr[t+256], v2 = xr[t+512];
    __shared__ float rs[256], rss[256];
    rs[t]  = v0 + v1 + v2;
    rss[t] = v0*v0 + v1*v1 + v2*v2;
    __syncthreads();
    for (int off = 128; off > 0; off >>= 1) {
        if (t < off) { rs[t] += rs[t+off]; rss[t] += rss[t+off]; }
        __syncthreads();
    }
    float mu   = rs[0]  * (1.f/768.f);
    float rstd = rsqrtf(rss[0]*(1.f/768.f) - mu*mu + 1e-5f);
    __shared__ float pa[NC][256];
    float a[NC] = {0.f, 0.f, 0.f, 0.f};
    float vv[3] = {v0, v1, v2};
    #pragma unroll
    for (int i = 0; i < 3; i++) {
        int d = t + i*256;
        float y = (vv[i]-mu)*rstd*g[d] + b[d];
        #pragma unroll
        for (int c = 0; c < NC; c++) a[c] = fmaf(y, Wc[d*NC + c], a[c]);
    }
    #pragma unroll
    for (int c = 0; c < NC; c++) pa[c][t] = a[c];
    __syncthreads();
    for (int off = 128; off > 0; off >>= 1) {
        if (t < off) {
            #pragma unroll
            for (int c = 0; c < NC; c++) pa[c][t] += pa[c][t+off];
        }
        __syncthreads();
    }
    if (t < NC) out[bi*NC + t] = pa[t][0] + bc[t];
}

// ---------------- orchestration ----------------
extern "C" void kernel_launch(void* const* d_in, const int* in_sizes, int n_in,
                              void* d_out, int out_size)
{
    const float* x      = (const float*)d_in[0];
    const float* Wpatch = (const float*)d_in[1];
    const float* bpatch = (const float*)d_in[2];
    const float* cls    = (const float*)d_in[3];
    const float* pos    = (const float*)d_in[4];
    const float* ln1g   = (const float*)d_in[5];
    const float* ln1b   = (const float*)d_in[6];
    const float* Wq     = (const float*)d_in[7];
    const float* bq     = (const float*)d_in[8];
    const float* Wk     = (const float*)d_in[9];
    const float* bk     = (const float*)d_in[10];
    const float* Wv     = (const float*)d_in[11];
    const float* bv     = (const float*)d_in[12];
    const float* Wo     = (const float*)d_in[13];
    const float* bo     = (const float*)d_in[14];
    const float* ln2g   = (const float*)d_in[15];
    const float* ln2b   = (const float*)d_in[16];
    const float* W1     = (const float*)d_in[17];
    const float* b1m    = (const float*)d_in[18];
    const float* W2     = (const float*)d_in[19];
    const float* b2m    = (const float*)d_in[20];
    const float* lnfg   = (const float*)d_in[21];
    const float* lnfb   = (const float*)d_in[22];
    const float* Wc     = (const float*)d_in[23];
    const float* bc     = (const float*)d_in[24];
    float* out = (float*)d_out;

    float *PO, *H, *Bf, *S;
    fp16 *Xn, *Xp, *QKV, *Cat, *Hid, *Ph, *Wqkv16, *Wt;
    { void* p;
      cudaGetSymbolAddress(&p, g_PO);   PO     = (float*)p;
      cudaGetSymbolAddress(&p, g_H);    H      = (float*)p;
      cudaGetSymbolAddress(&p, g_Bf);   Bf     = (float*)p;
      cudaGetSymbolAddress(&p, g_S);    S      = (float*)p;
      cudaGetSymbolAddress(&p, g_Xn);   Xn     = (fp16*)p;
      cudaGetSymbolAddress(&p, g_Xp);   Xp     = (fp16*)p;
      cudaGetSymbolAddress(&p, g_QKV);  QKV    = (fp16*)p;
      cudaGetSymbolAddress(&p, g_Cat);  Cat    = (fp16*)p;
      cudaGetSymbolAddress(&p, g_Hid);  Hid    = (fp16*)p;
      cudaGetSymbolAddress(&p, g_Ph);   Ph     = (fp16*)p;
      cudaGetSymbolAddress(&p, g_Wqkv); Wqkv16 = (fp16*)p;
      cudaGetSymbolAddress(&p, g_Wt);   Wt     = (fp16*)p;
    }

    static int attr_done = 0;
    if (!attr_done) {
        cudaFuncSetAttribute(mm1<EPI_BIAS, false, 256>,                     cudaFuncAttributeMaxDynamicSharedMemorySize, MM_SMEM);
        cudaFuncSetAttribute(mm1<EPI_BIAS|EPI_SPLITH, false, 256>,          cudaFuncAttributeMaxDynamicSharedMemorySize, MM_SMEM);
        cudaFuncSetAttribute(mm1<0, false, 256>,                            cudaFuncAttributeMaxDynamicSharedMemorySize, MM_SMEM);
        cudaFuncSetAttribute(mm1<EPI_SPLITH, true, 256>,                    cudaFuncAttributeMaxDynamicSharedMemorySize, MM_SMEM);
        cudaFuncSetAttribute(mm1<EPI_BIAS|EPI_RES, false, 128>,             cudaFuncAttributeMaxDynamicSharedMemorySize, MM_SMEM);
        cudaFuncSetAttribute(mm1<EPI_BIAS|EPI_GELU|EPI_SPLITH, false, 256>, cudaFuncAttributeMaxDynamicSharedMemorySize, MM_SMEM);
        attr_done = 1;
    }

    const float inv_scale = 1.0f / sqrtf(768.0f);

    // ---- patch embed ----
    im2col_half<<<(PROWS*DIM + 255)/256, 256>>>(x, Xp);
    conv_k<<<((DIM*DIM/4) + 255)/256, 256>>>((const float4*)Wpatch, Wt, DIM*DIM/4);
    mm1<EPI_BIAS, false, 256><<<dim3(3, 25, 1), 512, MM_SMEM>>>(
        Xp, Wt, PO, nullptr, bpatch, nullptr,
        PROWS, DIM, DIM, DIM, DIM, DIM, DIM,
        1, 0, 0, 0, 0, 0, 0, 1.f);
    assemble_k<<<(ROWS*DIM + 255)/256, 256>>>(PO, cls, pos, H);

    // ---- transformer layers ----
    for (int l = 0; l < NLAYER; l++) {
        const float* ln1g_l = ln1g + (LL)l*NH*DIM;
        const float* ln1b_l = ln1b + (LL)l*NH*DIM;
        const float* Wq_l = Wq + (LL)l*NH*DIM*DIM;
        const float* Wk_l = Wk + (LL)l*NH*DIM*DIM;
        const float* Wv_l = Wv + (LL)l*NH*DIM*DIM;
        const float* bq_l = bq + (LL)l*NH*DIM;
        const float* bk_l = bk + (LL)l*NH*DIM;
        const float* bv_l = bv + (LL)l*NH*DIM;
        const float* Wo_l = Wo  + (LL)l*HDK*DIM;
        const float* bo_l = bo  + (LL)l*DIM;
        const float* g2_l = ln2g + (LL)l*DIM;
        const float* b2_l = ln2b + (LL)l*DIM;
        const float* W1_l = W1  + (LL)l*DIM*MLP;
        const float* b1_l = b1m + (LL)l*MLP;
        const float* W2_l = W2  + (LL)l*MLP*DIM;
        const float* bb2_l= b2m + (LL)l*DIM;

        // LN1 (affine folded into QKV weights)
        ln_half_k<false><<<ROWS, 256>>>(H, nullptr, nullptr, Xn);

        // fused QKV weight fold + bias fold
        fold_qkv_w<<<dim3(DIM/32, DIM/32, 3*NH), dim3(32,8)>>>(Wq_l, Wk_l, Wv_l, ln1g_l, Wqkv16);
        fold_b3<<<3*HDK/32, 256>>>(Wq_l, Wk_l, Wv_l, ln1b_l, bq_l, bk_l, bv_l, Bf);

        // one QKV GEMM: [3152 x 27648]
        mm1<EPI_BIAS|EPI_SPLITH, false, 256><<<dim3(HDK3/256, 25, 1), 512, MM_SMEM>>>(
            Xn, Wqkv16, nullptr, QKV, Bf, nullptr,
            ROWS, HDK3, HDK3, DIM, DIM, DIM, HDK3,
            1, 0, 0, 0, 0, 0, 0, 1.f);

        // scores = Q·K^T / sqrt(768)
        mm1<0, false, 256><<<dim3(1, 2, NBH), 512, MM_SMEM>>>(
            QKV, QKV + HDK, S, nullptr, nullptr, nullptr,
            SEQ, SEQ, SEQ, DIM,
            HDK3, HDK3, SEQP,
            NH, (LL)SEQ*HDK3, (LL)DIM, (LL)SEQ*HDK3, (LL)DIM,
            (LL)NH*SEQ*SEQP, (LL)SEQ*SEQP, inv_scale);

        // softmax over query axis -> fp16 P
        softmax_half_k<<<dim3(NBH, 2), 128>>>(S, Ph);

        // av = P·V (trans-B) -> cat layout
        mm1<EPI_SPLITH, true, 256><<<dim3(3, 2, NBH), 512, MM_SMEM>>>(
            Ph, QKV + 2*HDK, nullptr, Cat, nullptr, nullptr,
            SEQ, DIM, SEQ, SEQP,
            SEQP, HDK3, HDK,
            NH, (LL)NH*SEQ*SEQP, (LL)SEQ*SEQP, (LL)SEQ*HDK3, (LL)DIM,
            (LL)SEQ*HDK, (LL)DIM, 1.f);

        // out proj + bias + residual -> H
        tconv_k<<<dim3(HDK/32, DIM/32), dim3(32,8)>>>(Wo_l, Wt, HDK, DIM);
        mm1<EPI_BIAS|EPI_RES, false, 128><<<dim3(6, 25, 1), 512, MM_SMEM>>>(
            Cat, Wt, H, nullptr, bo_l, H,
            ROWS, DIM, DIM, HDK, HDK, HDK, DIM,
            1, 0, 0, 0, 0, 0, 0, 1.f);

        // MLP
        ln_half_k<true><<<ROWS, 256>>>(H, g2_l, b2_l, Xn);
        tconv_k<<<dim3(DIM/32, MLP/32), dim3(32,8)>>>(W1_l, Wt, DIM, MLP);
        mm1<EPI_BIAS|EPI_GELU|EPI_SPLITH, false, 256><<<dim3(MLP/256, 25, 1), 512, MM_SMEM>>>(
            Xn, Wt, nullptr, Hid, b1_l, nullptr,
            ROWS, MLP, MLP, DIM, DIM, DIM, MLP,
            1, 0, 0, 0, 0, 0, 0, 1.f);

        tconv_k<<<dim3(MLP/32, DIM/32), dim3(32,8)>>>(W2_l, Wt, MLP, DIM);
        mm1<EPI_BIAS|EPI_RES, false, 128><<<dim3(6, 25, 1), 512, MM_SMEM>>>(
            Hid, Wt, H, nullptr, bb2_l, H,
            ROWS, DIM, DIM, MLP, MLP, MLP, DIM,
            1, 0, 0, 0, 0, 0, 0, 1.f);
    }

    // ---- final LN on CLS + classifier ----
    final_head_k<<<BATCH, 256>>>(H, lnfg, lnfb, Wc, bc, out);
}

// round 8
// speedup vs baseline: 8.4765x; 1.0140x over previous
#include <cuda_runtime.h>
#include <cuda_fp16.h>
#include <math.h>
#include <stdint.h>

typedef long long LL;
typedef __half fp16;

#define BATCH   16
#define SEQ     197
#define SEQP    256
#define NPATCH  196
#define DIM     768
#define NH      12
#define HDK     9216
#define HDK3    27648
#define MLP     3072
#define ROWS    (BATCH*SEQ)     /* 3152 */
#define PROWS   (BATCH*NPATCH)  /* 3136 */
#define NLAYER  4
#define NC      4
#define NBH     (BATCH*NH)      /* 192 */

// ---------------- scratch (device globals) ----------------
__device__ float g_PO [PROWS*DIM];
__device__ float g_H  [ROWS*DIM];
__device__ float g_Bf [HDK3];
__device__ float g_Part[(LL)24*HDK3];
__device__ float g_S  [(LL)NBH*SEQ*SEQP];

__device__ fp16 g_Xn  [ROWS*DIM];
__device__ fp16 g_Xp  [PROWS*DIM];
__device__ fp16 g_QKV [(LL)ROWS*HDK3];
__device__ fp16 g_Cat [(LL)ROWS*HDK];
__device__ fp16 g_Hid [(LL)ROWS*MLP];
__device__ fp16 g_Ph  [(LL)NBH*SEQ*SEQP];
__device__ fp16 g_Wqkv[(LL)3*HDK*DIM];
__device__ fp16 g_Wt  [(LL)HDK*DIM];

// ---------------- helpers ----------------
__device__ __forceinline__ uint32_t smem_u32(const void* p) {
    uint32_t a;
    asm("{ .reg .u64 t; cvta.to.shared.u64 t, %1; cvt.u32.u64 %0, t; }" : "=r"(a) : "l"(p));
    return a;
}
__device__ __forceinline__ uint32_t swz(uint32_t off) { return off ^ ((off >> 3) & 0x70); }

__device__ __forceinline__ void cp16z(uint32_t dst, const void* src, uint32_t sz) {
    asm volatile("cp.async.cg.shared.global [%0], [%1], 16, %2;\n"
                 :: "r"(dst), "l"(src), "r"(sz) : "memory");
}
__device__ __forceinline__ void cp_commit() {
    asm volatile("cp.async.commit_group;\n" ::: "memory");
}
__device__ __forceinline__ void ldsm4(uint32_t* r, uint32_t addr) {
    asm volatile("ldmatrix.sync.aligned.m8n8.x4.shared.b16 {%0,%1,%2,%3}, [%4];\n"
                 : "=r"(r[0]), "=r"(r[1]), "=r"(r[2]), "=r"(r[3]) : "r"(addr));
}
__device__ __forceinline__ void ldsm4t(uint32_t* r, uint32_t addr) {
    asm volatile("ldmatrix.sync.aligned.m8n8.x4.trans.shared.b16 {%0,%1,%2,%3}, [%4];\n"
                 : "=r"(r[0]), "=r"(r[1]), "=r"(r[2]), "=r"(r[3]) : "r"(addr));
}
__device__ __forceinline__ void mma16816(float* c, const uint32_t* a, const uint32_t* b) {
    asm volatile(
        "mma.sync.aligned.m16n8k16.row.col.f32.f16.f16.f32 "
        "{%0,%1,%2,%3}, {%4,%5,%6,%7}, {%8,%9}, {%0,%1,%2,%3};\n"
        : "+f"(c[0]), "+f"(c[1]), "+f"(c[2]), "+f"(c[3])
        : "r"(a[0]), "r"(a[1]), "r"(a[2]), "r"(a[3]), "r"(b[0]), "r"(b[1]));
}

#define EPI_BIAS   1
#define EPI_RES    2
#define EPI_GELU   4
#define EPI_SPLITH 16

// ================= mm1: 512 thr, BM=128 x BN=256, 4-stage (feed-optimal) ===
#define MM_SMEM 196608

__device__ __forceinline__ void load_tile1(uint32_t stg,
    const fp16* __restrict__ A, const fp16* __restrict__ B,
    int bm, int bn, int M, int Brows, int lda, int ldb, int k0, int tid)
{
    constexpr uint32_t SB = 16384;
    #pragma unroll
    for (int it = 0; it < 2; it++) {
        int i = tid + it*512;
        int row = i >> 3, j = i & 7;
        int gm = bm + row;
        uint32_t sz = (gm < M) ? 16u : 0u;
        int gmc = (gm < M) ? gm : 0;
        const char* p = (const char*)(A + (LL)gmc*lda + k0) + j*16;
        cp16z(stg + swz((uint32_t)row*128u + (uint32_t)j*16u), p, sz);
    }
    #pragma unroll
    for (int it = 0; it < 4; it++) {
        int i = tid + it*512;
        int row = i >> 3, j = i & 7;
        int gn = bn + row;
        uint32_t sz = (gn < Brows) ? 16u : 0u;
        int gnc = (gn < Brows) ? gn : 0;
        const char* p = (const char*)(B + (LL)gnc*ldb + k0) + j*16;
        cp16z(stg + SB + swz((uint32_t)row*128u + (uint32_t)j*16u), p, sz);
    }
}

template<int EPI>
__global__ void __launch_bounds__(512, 1)
mm1(const fp16* __restrict__ A, const fp16* __restrict__ B,
    float* __restrict__ C, fp16* __restrict__ Ch,
    const float* __restrict__ bias, const float* __restrict__ res,
    int M, int N, int Brows, int K, int lda, int ldb, int ldc, float alpha)
{
    constexpr uint32_t SB = 16384;
    constexpr int STG = 49152, NSTG = 4;

    extern __shared__ char smem[];
    uint32_t sb = smem_u32(smem);
    const int tid  = threadIdx.x;
    const int wid  = tid >> 5;
    const int lane = tid & 31;
    const int bm = blockIdx.y * 128;
    const int bn = blockIdx.x * 256;

    const int m_warp = (wid & 3) * 32;
    const int n_warp = (wid >> 2) * 64;

    float acc[2][8][4];
    #pragma unroll
    for (int mt = 0; mt < 2; mt++)
        #pragma unroll
        for (int nt = 0; nt < 8; nt++)
            #pragma unroll
            for (int e = 0; e < 4; e++) acc[mt][nt][e] = 0.f;

    const int NCH = K >> 6;

    #pragma unroll
    for (int s = 0; s < NSTG-1; s++) {
        if (s < NCH)
            load_tile1(sb + s*STG, A, B, bm, bn, M, Brows, lda, ldb, s*64, tid);
        cp_commit();
    }

    const int lar = lane & 15;
    const int lac = (lane >> 4) * 16;
    const int lbr = ((lane & 16) >> 1) + (lane & 7);
    const int lbc = ((lane >> 3) & 1) * 16;

    for (int c = 0; c < NCH; c++) {
        if (c + NSTG-1 < NCH)
            load_tile1(sb + ((c + NSTG-1) % NSTG)*STG,
                       A, B, bm, bn, M, Brows, lda, ldb, (c + NSTG-1)*64, tid);
        cp_commit();
        asm volatile("cp.async.wait_group %0;\n" :: "n"(NSTG-1) : "memory");
        __syncthreads();

        uint32_t stg = sb + (c % NSTG)*STG;
        #pragma unroll
        for (int ks = 0; ks < 4; ks++) {
            uint32_t a[2][4];
            #pragma unroll
            for (int mt = 0; mt < 2; mt++) {
                uint32_t off = swz((uint32_t)(m_warp + mt*16 + lar)*128u + ks*32 + lac);
                ldsm4(a[mt], stg + off);
            }
            #pragma unroll
            for (int p = 0; p < 4; p++) {
                uint32_t rb[4];
                uint32_t off = swz((uint32_t)(n_warp + p*16 + lbr)*128u + ks*32 + lbc);
                ldsm4(rb, stg + SB + off);
                #pragma unroll
                for (int mt = 0; mt < 2; mt++) {
                    mma16816(acc[mt][2*p],   a[mt], rb);
                    mma16816(acc[mt][2*p+1], a[mt], rb+2);
                }
            }
        }
        __syncthreads();
    }

    #pragma unroll
    for (int mt = 0; mt < 2; mt++) {
        #pragma unroll
        for (int half = 0; half < 2; half++) {
            int m = bm + m_warp + mt*16 + (lane >> 2) + half*8;
            if (m >= M) continue;
            #pragma unroll
            for (int nt = 0; nt < 8; nt++) {
                int n = bn + n_warp + nt*8 + (lane & 3)*2;
                if (n >= N) continue;
                float v0 = acc[mt][nt][half*2 + 0] * alpha;
                float v1 = acc[mt][nt][half*2 + 1] * alpha;
                if (EPI & EPI_BIAS) { v0 += __ldg(&bias[n]); v1 += __ldg(&bias[n+1]); }
                if (EPI & EPI_RES) {
                    const float2 rv = *(const float2*)(res + (LL)m*ldc + n);
                    v0 += rv.x; v1 += rv.y;
                }
                if (EPI & EPI_GELU) {
                    v0 = 0.5f*v0*(1.f + erff(v0*0.70710678118654752440f));
                    v1 = 0.5f*v1*(1.f + erff(v1*0.70710678118654752440f));
                }
                if (EPI & EPI_SPLITH) {
                    __half2 ph; ph.x = __float2half_rn(v0); ph.y = __float2half_rn(v1);
                    *(__half2*)(Ch + (LL)m*ldc + n) = ph;
                } else {
                    *(float2*)(C + (LL)m*ldc + n) = make_float2(v0, v1);
                }
            }
        }
    }
}

// ================= mms: 256 thr, BM=64 x BN=128, 3-stage, 3 CTAs/SM ========
#define MS_SMEM 73728

template<bool BT>
__device__ __forceinline__ void load_tile_s(uint32_t stg,
    const fp16* __restrict__ A, const fp16* __restrict__ B,
    int bm, int bn, int M, int Brows, int lda, int ldb, int k0, int tid)
{
    constexpr uint32_t SB = 8192;
    #pragma unroll
    for (int it = 0; it < 2; it++) {
        int i = tid + it*256;
        int row = i >> 3, j = i & 7;
        int gm = bm + row;
        uint32_t sz = (gm < M) ? 16u : 0u;
        int gmc = (gm < M) ? gm : 0;
        const char* p = (const char*)(A + (LL)gmc*lda + k0) + j*16;
        cp16z(stg + swz((uint32_t)row*128u + (uint32_t)j*16u), p, sz);
    }
    if (!BT) {
        #pragma unroll
        for (int it = 0; it < 4; it++) {
            int i = tid + it*256;
            int row = i >> 3, j = i & 7;
            int gn = bn + row;
            uint32_t sz = (gn < Brows) ? 16u : 0u;
            int gnc = (gn < Brows) ? gn : 0;
            const char* p = (const char*)(B + (LL)gnc*ldb + k0) + j*16;
            cp16z(stg + SB + swz((uint32_t)row*128u + (uint32_t)j*16u), p, sz);
        }
    } else {
        #pragma unroll
        for (int it = 0; it < 4; it++) {
            int i = tid + it*256;
            int row = i >> 4, j = i & 15;
            int gk = k0 + row;
            uint32_t sz = (gk < Brows) ? 16u : 0u;
            int gkc = (gk < Brows) ? gk : 0;
            const char* p = (const char*)(B + (LL)gkc*ldb + bn) + j*16;
            uint32_t so = (uint32_t)row*256u + (((uint32_t)j*16u) ^ (((uint32_t)row & 7u) << 4));
            cp16z(stg + SB + so, p, sz);
        }
    }
}

template<int EPI, bool BT>
__global__ void __launch_bounds__(256, 3)
mms(const fp16* __restrict__ A, const fp16* __restrict__ B,
    float* __restrict__ C, fp16* __restrict__ Ch,
    const float* __restrict__ bias, const float* __restrict__ res,
    int M, int N, int Brows, int K, int lda, int ldb, int ldc,
    int zdiv, LL sA0, LL sA1, LL sB0, LL sB1, LL sC0, LL sC1,
    float alpha)
{
    constexpr uint32_t SB = 8192;
    constexpr int STG = 24576, NSTG = 3;

    extern __shared__ char smem[];
    uint32_t sb = smem_u32(smem);
    const int tid  = threadIdx.x;
    const int wid  = tid >> 5;
    const int lane = tid & 31;
    const int bm = blockIdx.y * 64;
    const int bn = blockIdx.x * 128;
    const int zo = blockIdx.z / zdiv, zi = blockIdx.z - zo*zdiv;
    A += zo*sA0 + zi*sA1;
    B += zo*sB0 + zi*sB1;
    const LL cbase = zo*sC0 + zi*sC1;

    const int m_warp = (wid & 1) * 32;
    const int n_warp = (wid >> 1) * 32;

    float acc[2][4][4];
    #pragma unroll
    for (int mt = 0; mt < 2; mt++)
        #pragma unroll
        for (int nt = 0; nt < 4; nt++)
            #pragma unroll
            for (int e = 0; e < 4; e++) acc[mt][nt][e] = 0.f;

    const int NCH = K >> 6;

    #pragma unroll
    for (int s = 0; s < NSTG-1; s++) {
        if (s < NCH)
            load_tile_s<BT>(sb + s*STG, A, B, bm, bn, M, Brows, lda, ldb, s*64, tid);
        cp_commit();
    }

    const int lar = lane & 15;
    const int lac = (lane >> 4) * 16;
    const int lbr = ((lane & 16) >> 1) + (lane & 7);
    const int lbc = ((lane >> 3) & 1) * 16;

    for (int c = 0; c < NCH; c++) {
        if (c + NSTG-1 < NCH)
            load_tile_s<BT>(sb + ((c + NSTG-1) % NSTG)*STG,
                            A, B, bm, bn, M, Brows, lda, ldb, (c + NSTG-1)*64, tid);
        cp_commit();
        asm volatile("cp.async.wait_group %0;\n" :: "n"(NSTG-1) : "memory");
        __syncthreads();

        uint32_t stg = sb + (c % NSTG)*STG;
        #pragma unroll
        for (int ks = 0; ks < 4; ks++) {
            uint32_t a[2][4];
            #pragma unroll
            for (int mt = 0; mt < 2; mt++) {
                uint32_t off = swz((uint32_t)(m_warp + mt*16 + lar)*128u + ks*32 + lac);
                ldsm4(a[mt], stg + off);
            }
            #pragma unroll
            for (int p = 0; p < 2; p++) {
                uint32_t rb[4];
                if (!BT) {
                    uint32_t off = swz((uint32_t)(n_warp + p*16 + lbr)*128u + ks*32 + lbc);
                    ldsm4(rb, stg + SB + off);
                } else {
                    uint32_t row = (uint32_t)(ks*16 + (lane & 15));
                    uint32_t nb  = (uint32_t)((n_warp + p*16)*2) + (((uint32_t)lane >> 4) << 4);
                    uint32_t off = row*256u + (nb ^ ((row & 7u) << 4));
                    ldsm4t(rb, stg + SB + off);
                }
                #pragma unroll
                for (int mt = 0; mt < 2; mt++) {
                    mma16816(acc[mt][2*p],   a[mt], rb);
                    mma16816(acc[mt][2*p+1], a[mt], rb+2);
                }
            }
        }
        __syncthreads();
    }

    #pragma unroll
    for (int mt = 0; mt < 2; mt++) {
        #pragma unroll
        for (int half = 0; half < 2; half++) {
            int m = bm + m_warp + mt*16 + (lane >> 2) + half*8;
            if (m >= M) continue;
            #pragma unroll
            for (int nt = 0; nt < 4; nt++) {
                int n = bn + n_warp + nt*8 + (lane & 3)*2;
                if (n >= N) continue;
                float v0 = acc[mt][nt][half*2 + 0] * alpha;
                float v1 = acc[mt][nt][half*2 + 1] * alpha;
                if (EPI & EPI_BIAS) { v0 += __ldg(&bias[n]); v1 += __ldg(&bias[n+1]); }
                if (EPI & EPI_RES) {
                    const float2 rv = *(const float2*)(res + (LL)m*ldc + n);
                    v0 += rv.x; v1 += rv.y;
                }
                if (EPI & EPI_GELU) {
                    v0 = 0.5f*v0*(1.f + erff(v0*0.70710678118654752440f));
                    v1 = 0.5f*v1*(1.f + erff(v1*0.70710678118654752440f));
                }
                if (EPI & EPI_SPLITH) {
                    __half2 ph; ph.x = __float2half_rn(v0); ph.y = __float2half_rn(v1);
                    *(__half2*)(Ch + cbase + (LL)m*ldc + n) = ph;
                } else {
                    *(float2*)(C + cbase + (LL)m*ldc + n) = make_float2(v0, v1);
                }
            }
        }
    }
}

// ---------------- conversion / small kernels ----------------
__global__ void conv_k(const float4* __restrict__ in, fp16* __restrict__ out, int n4) {
    int i = blockIdx.x*blockDim.x + threadIdx.x;
    if (i >= n4) return;
    float4 v = in[i];
    __half2 a, b;
    a.x = __float2half_rn(v.x); a.y = __float2half_rn(v.y);
    b.x = __float2half_rn(v.z); b.y = __float2half_rn(v.w);
    *(__half2*)(out + i*4)     = a;
    *(__half2*)(out + i*4 + 2) = b;
}

// fused QKV fold+transpose+convert + bias-fold partials (deterministic)
__global__ void fold_qkv_w(const float* __restrict__ Wq, const float* __restrict__ Wk,
                           const float* __restrict__ Wv, const float* __restrict__ g,
                           const float* __restrict__ b1,
                           fp16* __restrict__ out, float* __restrict__ part) {
    __shared__ float t[32][33];
    __shared__ float red[8][32];
    int z = blockIdx.z;
    int m = z / NH, h = z % NH;
    const float* W = ((m == 0) ? Wq : (m == 1) ? Wk : Wv) + (LL)h*DIM*DIM;
    int d0 = blockIdx.y*32, k0 = blockIdx.x*32;
    const float* b1h = b1 + (LL)h*DIM;
    float pb = 0.f;
    for (int i = threadIdx.y; i < 32; i += 8) {
        float w = W[(LL)(d0+i)*DIM + k0 + threadIdx.x];
        t[i][threadIdx.x] = w * g[h*DIM + d0 + i];
        pb = fmaf(b1h[d0 + i], w, pb);
    }
    red[threadIdx.y][threadIdx.x] = pb;
    __syncthreads();
    for (int i = threadIdx.y; i < 32; i += 8)
        out[(LL)(m*HDK + h*DIM + k0 + i)*DIM + d0 + threadIdx.x] = __float2half_rn(t[threadIdx.x][i]);
    if (threadIdx.y == 0) {
        float s = red[0][threadIdx.x];
        #pragma unroll
        for (int j = 1; j < 8; j++) s += red[j][threadIdx.x];
        part[(LL)blockIdx.y*HDK3 + m*HDK + h*DIM + k0 + threadIdx.x] = s;
    }
}

__global__ void reduce_bf(const float* __restrict__ part,
                          const float* __restrict__ bq, const float* __restrict__ bk,
                          const float* __restrict__ bv, float* __restrict__ Bf) {
    int n = blockIdx.x*256 + threadIdx.x;
    if (n >= HDK3) return;
    int m = n / HDK, r = n - m*HDK;
    float s = ((m == 0) ? bq : (m == 1) ? bk : bv)[r];
    #pragma unroll 8
    for (int j = 0; j < 24; j++) s += part[(LL)j*HDK3 + n];
    Bf[n] = s;
}

__global__ void tconv_k(const float* __restrict__ W, fp16* __restrict__ out, int K, int N) {
    __shared__ float t[32][33];
    int k0 = blockIdx.x*32, n0 = blockIdx.y*32;
    for (int i = threadIdx.y; i < 32; i += 8)
        t[i][threadIdx.x] = W[(LL)(k0+i)*N + n0 + threadIdx.x];
    __syncthreads();
    for (int i = threadIdx.y; i < 32; i += 8)
        out[(LL)(n0+i)*K + k0 + threadIdx.x] = __float2half_rn(t[threadIdx.x][i]);
}

__global__ void im2col_half(const float* __restrict__ x, fp16* __restrict__ oh) {
    int idx = blockIdx.x*blockDim.x + threadIdx.x;
    if (idx >= PROWS*DIM) return;
    int f   = idx % DIM;
    int row = idx / DIM;
    int b = row / NPATCH, n = row % NPATCH;
    int ph = n / 14, pw = n % 14;
    int c = f / 256, r = f % 256;
    int p = r / 16,  q = r % 16;
    oh[idx] = __float2half_rn(x[(((LL)b*3 + c)*224 + ph*16 + p)*224 + pw*16 + q]);
}

__global__ void assemble_k(const float* __restrict__ patch, const float* __restrict__ cls,
                           const float* __restrict__ pos, float* __restrict__ h) {
    int idx = blockIdx.x*blockDim.x + threadIdx.x;
    if (idx >= ROWS*DIM) return;
    int d = idx % DIM;
    int row = idx / DIM;
    int b = row / SEQ, s = row % SEQ;
    float v = (s == 0) ? cls[d] : patch[((LL)b*NPATCH + (s-1))*DIM + d];
    h[idx] = v + pos[s*DIM + d];
}

template<bool AFF>
__global__ void ln_half_k(const float* __restrict__ in, const float* __restrict__ g,
                          const float* __restrict__ b, fp16* __restrict__ oh) {
    int row = blockIdx.x;
    const float* xr = in + (LL)row*DIM;
    int t = threadIdx.x;
    float v0 = xr[t], v1 = xr[t+256], v2 = xr[t+512];
    __shared__ float rs[256], rss[256];
    rs[t]  = v0 + v1 + v2;
    rss[t] = v0*v0 + v1*v1 + v2*v2;
    __syncthreads();
    for (int off = 128; off > 0; off >>= 1) {
        if (t < off) { rs[t] += rs[t+off]; rss[t] += rss[t+off]; }
        __syncthreads();
    }
    float mu   = rs[0]  * (1.f/768.f);
    float rstd = rsqrtf(rss[0]*(1.f/768.f) - mu*mu + 1e-5f);
    float y[3] = { (v0-mu)*rstd, (v1-mu)*rstd, (v2-mu)*rstd };
    #pragma unroll
    for (int i = 0; i < 3; i++) {
        int d = t + i*256;
        float yy = y[i];
        if (AFF) yy = yy*g[d] + b[d];
        oh[(LL)row*DIM + d] = __float2half_rn(yy);
    }
}

__global__ void softmax_half_k(const float* __restrict__ S, fp16* __restrict__ Ph) {
    LL base = (LL)blockIdx.x * (SEQ*SEQP);
    int k = blockIdx.y*128 + threadIdx.x;
    if (k >= SEQ) {
        for (int q = 0; q < SEQ; q++) Ph[base + (LL)q*SEQP + k] = __float2half_rn(0.f);
        return;
    }
    float mx = -1e30f;
    for (int q = 0; q < SEQ; q++) mx = fmaxf(mx, S[base + (LL)q*SEQP + k]);
    float sum = 0.f;
    for (int q = 0; q < SEQ; q++) sum += expf(S[base + (LL)q*SEQP + k] - mx);
    float inv = 1.f / sum;
    for (int q = 0; q < SEQ; q++) {
        float p = expf(S[base + (LL)q*SEQP + k] - mx) * inv;
        Ph[base + (LL)q*SEQP + k] = __float2half_rn(p);
    }
}

__global__ void final_head_k(const float* __restrict__ h, const float* __restrict__ g,
                             const float* __restrict__ b, const float* __restrict__ Wc,
                             const float* __restrict__ bc, float* __restrict__ out) {
    int bi = blockIdx.x;
    const float* xr = h + (LL)bi*SEQ*DIM;
    int t = threadIdx.x;
    float v0 = xr[t], v1 = xr[t+256], v2 = xr[t+512];
    __shared__ float rs[256], rss[256];
    rs[t]  = v0 + v1 + v2;
    rss[t] = v0*v0 + v1*v1 + v2*v2;
    __syncthreads();
    for (int off = 128; off > 0; off >>= 1) {
        if (t < off) { rs[t] += rs[t+off]; rss[t] += rss[t+off]; }
        __syncthreads();
    }
    float mu   = rs[0]  * (1.f/768.f);
    float rstd = rsqrtf(rss[0]*(1.f/768.f) - mu*mu + 1e-5f);
    __shared__ float pa[NC][256];
    float a[NC] = {0.f, 0.f, 0.f, 0.f};
    float vv[3] = {v0, v1, v2};
    #pragma unroll
    for (int i = 0; i < 3; i++) {
        int d = t + i*256;
        float y = (vv[i]-mu)*rstd*g[d] + b[d];
        #pragma unroll
        for (int c = 0; c < NC; c++) a[c] = fmaf(y, Wc[d*NC + c], a[c]);
    }
    #pragma unroll
    for (int c = 0; c < NC; c++) pa[c][t] = a[c];
    __syncthreads();
    for (int off = 128; off > 0; off >>= 1) {
        if (t < off) {
            #pragma unroll
            for (int c = 0; c < NC; c++) pa[c][t] += pa[c][t+off];
        }
        __syncthreads();
    }
    if (t < NC) out[bi*NC + t] = pa[t][0] + bc[t];
}

// ---------------- orchestration ----------------
extern "C" void kernel_launch(void* const* d_in, const int* in_sizes, int n_in,
                              void* d_out, int out_size)
{
    const float* x      = (const float*)d_in[0];
    const float* Wpatch = (const float*)d_in[1];
    const float* bpatch = (const float*)d_in[2];
    const float* cls    = (const float*)d_in[3];
    const float* pos    = (const float*)d_in[4];
    const float* ln1g   = (const float*)d_in[5];
    const float* ln1b   = (const float*)d_in[6];
    const float* Wq     = (const float*)d_in[7];
    const float* bq     = (const float*)d_in[8];
    const float* Wk     = (const float*)d_in[9];
    const float* bk     = (const float*)d_in[10];
    const float* Wv     = (const float*)d_in[11];
    const float* bv     = (const float*)d_in[12];
    const float* Wo     = (const float*)d_in[13];
    const float* bo     = (const float*)d_in[14];
    const float* ln2g   = (const float*)d_in[15];
    const float* ln2b   = (const float*)d_in[16];
    const float* W1     = (const float*)d_in[17];
    const float* b1m    = (const float*)d_in[18];
    const float* W2     = (const float*)d_in[19];
    const float* b2m    = (const float*)d_in[20];
    const float* lnfg   = (const float*)d_in[21];
    const float* lnfb   = (const float*)d_in[22];
    const float* Wc     = (const float*)d_in[23];
    const float* bc     = (const float*)d_in[24];
    float* out = (float*)d_out;

    float *PO, *H, *Bf, *Part, *S;
    fp16 *Xn, *Xp, *QKV, *Cat, *Hid, *Ph, *Wqkv16, *Wt;
    { void* p;
      cudaGetSymbolAddress(&p, g_PO);   PO     = (float*)p;
      cudaGetSymbolAddress(&p, g_H);    H      = (float*)p;
      cudaGetSymbolAddress(&p, g_Bf);   Bf     = (float*)p;
      cudaGetSymbolAddress(&p, g_Part); Part   = (float*)p;
      cudaGetSymbolAddress(&p, g_S);    S      = (float*)p;
      cudaGetSymbolAddress(&p, g_Xn);   Xn     = (fp16*)p;
      cudaGetSymbolAddress(&p, g_Xp);   Xp     = (fp16*)p;
      cudaGetSymbolAddress(&p, g_QKV);  QKV    = (fp16*)p;
      cudaGetSymbolAddress(&p, g_Cat);  Cat    = (fp16*)p;
      cudaGetSymbolAddress(&p, g_Hid);  Hid    = (fp16*)p;
      cudaGetSymbolAddress(&p, g_Ph);   Ph     = (fp16*)p;
      cudaGetSymbolAddress(&p, g_Wqkv); Wqkv16 = (fp16*)p;
      cudaGetSymbolAddress(&p, g_Wt);   Wt     = (fp16*)p;
    }

    static int attr_done = 0;
    if (!attr_done) {
        cudaFuncSetAttribute(mm1<EPI_BIAS|EPI_SPLITH>,          cudaFuncAttributeMaxDynamicSharedMemorySize, MM_SMEM);
        cudaFuncSetAttribute(mm1<EPI_BIAS|EPI_GELU|EPI_SPLITH>, cudaFuncAttributeMaxDynamicSharedMemorySize, MM_SMEM);
        cudaFuncSetAttribute(mms<EPI_BIAS, false>,              cudaFuncAttributeMaxDynamicSharedMemorySize, MS_SMEM);
        cudaFuncSetAttribute(mms<0, false>,                     cudaFuncAttributeMaxDynamicSharedMemorySize, MS_SMEM);
        cudaFuncSetAttribute(mms<EPI_SPLITH, true>,             cudaFuncAttributeMaxDynamicSharedMemorySize, MS_SMEM);
        cudaFuncSetAttribute(mms<EPI_BIAS|EPI_RES, false>,      cudaFuncAttributeMaxDynamicSharedMemorySize, MS_SMEM);
        attr_done = 1;
    }

    const float inv_scale = 1.0f / sqrtf(768.0f);

    // ---- patch embed ----
    im2col_half<<<(PROWS*DIM + 255)/256, 256>>>(x, Xp);
    conv_k<<<((DIM*DIM/4) + 255)/256, 256>>>((const float4*)Wpatch, Wt, DIM*DIM/4);
    mms<EPI_BIAS, false><<<dim3(6, 49, 1), 256, MS_SMEM>>>(
        Xp, Wt, PO, nullptr, bpatch, nullptr,
        PROWS, DIM, DIM, DIM, DIM, DIM, DIM,
        1, 0, 0, 0, 0, 0, 0, 1.f);
    assemble_k<<<(ROWS*DIM + 255)/256, 256>>>(PO, cls, pos, H);

    // ---- transformer layers ----
    for (int l = 0; l < NLAYER; l++) {
        const float* ln1g_l = ln1g + (LL)l*NH*DIM;
        const float* ln1b_l = ln1b + (LL)l*NH*DIM;
        const float* Wq_l = Wq + (LL)l*NH*DIM*DIM;
        const float* Wk_l = Wk + (LL)l*NH*DIM*DIM;
        const float* Wv_l = Wv + (LL)l*NH*DIM*DIM;
        const float* bq_l = bq + (LL)l*NH*DIM;
        const float* bk_l = bk + (LL)l*NH*DIM;
        const float* bv_l = bv + (LL)l*NH*DIM;
        const float* Wo_l = Wo  + (LL)l*HDK*DIM;
        const float* bo_l = bo  + (LL)l*DIM;
        const float* g2_l = ln2g + (LL)l*DIM;
        const float* b2_l = ln2b + (LL)l*DIM;
        const float* W1_l = W1  + (LL)l*DIM*MLP;
        const float* b1_l = b1m + (LL)l*MLP;
        const float* W2_l = W2  + (LL)l*MLP*DIM;
        const float* bb2_l= b2m + (LL)l*DIM;

        ln_half_k<false><<<ROWS, 256>>>(H, nullptr, nullptr, Xn);

        fold_qkv_w<<<dim3(DIM/32, DIM/32, 3*NH), dim3(32,8)>>>(Wq_l, Wk_l, Wv_l, ln1g_l, ln1b_l, Wqkv16, Part);
        reduce_bf<<<HDK3/256, 256>>>(Part, bq_l, bk_l, bv_l, Bf);

        mm1<EPI_BIAS|EPI_SPLITH><<<dim3(HDK3/256, 25, 1), 512, MM_SMEM>>>(
            Xn, Wqkv16, nullptr, QKV, Bf, nullptr,
            ROWS, HDK3, HDK3, DIM, DIM, DIM, HDK3, 1.f);

        // scores = Q·K^T / sqrt(768)
        mms<0, false><<<dim3(2, 4, NBH), 256, MS_SMEM>>>(
            QKV, QKV + HDK, S, nullptr, nullptr, nullptr,
            SEQ, SEQ, SEQ, DIM,
            HDK3, HDK3, SEQP,
            NH, (LL)SEQ*HDK3, (LL)DIM, (LL)SEQ*HDK3, (LL)DIM,
            (LL)NH*SEQ*SEQP, (LL)SEQ*SEQP, inv_scale);

        softmax_half_k<<<dim3(NBH, 2), 128>>>(S, Ph);

        // av = P·V (trans-B) -> cat layout
        mms<EPI_SPLITH, true><<<dim3(6, 4, NBH), 256, MS_SMEM>>>(
            Ph, QKV + 2*HDK, nullptr, Cat, nullptr, nullptr,
            SEQ, DIM, SEQ, SEQP,
            SEQP, HDK3, HDK,
            NH, (LL)NH*SEQ*SEQP, (LL)SEQ*SEQP, (LL)SEQ*HDK3, (LL)DIM,
            (LL)SEQ*HDK, (LL)DIM, 1.f);

        // out proj + bias + residual -> H
        tconv_k<<<dim3(HDK/32, DIM/32), dim3(32,8)>>>(Wo_l, Wt, HDK, DIM);
        mms<EPI_BIAS|EPI_RES, false><<<dim3(6, 50, 1), 256, MS_SMEM>>>(
            Cat, Wt, H, nullptr, bo_l, H,
            ROWS, DIM, DIM, HDK, HDK, HDK, DIM,
            1, 0, 0, 0, 0, 0, 0, 1.f);

        // MLP
        ln_half_k<true><<<ROWS, 256>>>(H, g2_l, b2_l, Xn);
        tconv_k<<<dim3(DIM/32, MLP/32), dim3(32,8)>>>(W1_l, Wt, DIM, MLP);
        mm1<EPI_BIAS|EPI_GELU|EPI_SPLITH><<<dim3(MLP/256, 25, 1), 512, MM_SMEM>>>(
            Xn, Wt, nullptr, Hid, b1_l, nullptr,
            ROWS, MLP, MLP, DIM, DIM, DIM, MLP, 1.f);

        tconv_k<<<dim3(MLP/32, DIM/32), dim3(32,8)>>>(W2_l, Wt, MLP, DIM);
        mms<EPI_BIAS|EPI_RES, false><<<dim3(6, 50, 1), 256, MS_SMEM>>>(
            Hid, Wt, H, nullptr, bb2_l, H,
            ROWS, DIM, DIM, MLP, MLP, MLP, DIM,
            1, 0, 0, 0, 0, 0, 0, 1.f);
    }

    // ---- final LN on CLS + classifier ----
    final_head_k<<<BATCH, 256>>>(H, lnfg, lnfb, Wc, bc, out);
}

// round 9
// speedup vs baseline: 8.6859x; 1.0247x over previous
#include <cuda_runtime.h>
#include <cuda_fp16.h>
#include <math.h>
#include <stdint.h>

typedef long long LL;
typedef __half fp16;

#define BATCH   16
#define SEQ     197
#define SEQP    256
#define NPATCH  196
#define DIM     768
#define NH      12
#define HDK     9216
#define HDK3    27648
#define MLP     3072
#define ROWS    (BATCH*SEQ)     /* 3152 */
#define PROWS   (BATCH*NPATCH)  /* 3136 */
#define NLAYER  4
#define NC      4
#define NBH     (BATCH*NH)      /* 192 */

// ---------------- scratch (device globals) ----------------
__device__ float g_PO [PROWS*DIM];
__device__ float g_H  [ROWS*DIM];
__device__ float g_BfL[(LL)NLAYER*HDK3];
__device__ float g_Part[(LL)24*HDK3];
__device__ float g_S  [(LL)NBH*SEQ*SEQP];

__device__ fp16 g_Xn  [ROWS*DIM];
__device__ fp16 g_Xp  [PROWS*DIM];
__device__ fp16 g_QKV [(LL)ROWS*HDK3];
__device__ fp16 g_Cat [(LL)ROWS*HDK];
__device__ fp16 g_Hid [(LL)ROWS*MLP];
__device__ fp16 g_Ph  [(LL)NBH*SEQ*SEQP];
__device__ fp16 g_WqkvL[(LL)NLAYER*3*HDK*DIM];   // folded QKV per layer
__device__ fp16 g_WoL [(LL)NLAYER*HDK*DIM];
__device__ fp16 g_W1L [(LL)NLAYER*DIM*MLP];
__device__ fp16 g_W2L [(LL)NLAYER*MLP*DIM];
__device__ fp16 g_Wp  [DIM*DIM];

// ---------------- helpers ----------------
__device__ __forceinline__ uint32_t smem_u32(const void* p) {
    uint32_t a;
    asm("{ .reg .u64 t; cvta.to.shared.u64 t, %1; cvt.u32.u64 %0, t; }" : "=r"(a) : "l"(p));
    return a;
}
__device__ __forceinline__ uint32_t swz(uint32_t off) { return off ^ ((off >> 3) & 0x70); }

__device__ __forceinline__ void cp16z(uint32_t dst, const void* src, uint32_t sz) {
    asm volatile("cp.async.cg.shared.global [%0], [%1], 16, %2;\n"
                 :: "r"(dst), "l"(src), "r"(sz) : "memory");
}
__device__ __forceinline__ void cp_commit() {
    asm volatile("cp.async.commit_group;\n" ::: "memory");
}
__device__ __forceinline__ void ldsm4(uint32_t* r, uint32_t addr) {
    asm volatile("ldmatrix.sync.aligned.m8n8.x4.shared.b16 {%0,%1,%2,%3}, [%4];\n"
                 : "=r"(r[0]), "=r"(r[1]), "=r"(r[2]), "=r"(r[3]) : "r"(addr));
}
__device__ __forceinline__ void ldsm4t(uint32_t* r, uint32_t addr) {
    asm volatile("ldmatrix.sync.aligned.m8n8.x4.trans.shared.b16 {%0,%1,%2,%3}, [%4];\n"
                 : "=r"(r[0]), "=r"(r[1]), "=r"(r[2]), "=r"(r[3]) : "r"(addr));
}
__device__ __forceinline__ void mma16816(float* c, const uint32_t* a, const uint32_t* b) {
    asm volatile(
        "mma.sync.aligned.m16n8k16.row.col.f32.f16.f16.f32 "
        "{%0,%1,%2,%3}, {%4,%5,%6,%7}, {%8,%9}, {%0,%1,%2,%3};\n"
        : "+f"(c[0]), "+f"(c[1]), "+f"(c[2]), "+f"(c[3])
        : "r"(a[0]), "r"(a[1]), "r"(a[2]), "r"(a[3]), "r"(b[0]), "r"(b[1]));
}

#define EPI_BIAS   1
#define EPI_RES    2
#define EPI_GELU   4
#define EPI_SPLITH 16

// ================= mm1: 512 thr, BM=128 x BN=256, 4-stage ===================
#define MM_SMEM 196608

__device__ __forceinline__ void load_tile1(uint32_t stg,
    const fp16* __restrict__ A, const fp16* __restrict__ B,
    int bm, int bn, int M, int Brows, int lda, int ldb, int k0, int tid)
{
    constexpr uint32_t SB = 16384;
    #pragma unroll
    for (int it = 0; it < 2; it++) {
        int i = tid + it*512;
        int row = i >> 3, j = i & 7;
        int gm = bm + row;
        uint32_t sz = (gm < M) ? 16u : 0u;
        int gmc = (gm < M) ? gm : 0;
        const char* p = (const char*)(A + (LL)gmc*lda + k0) + j*16;
        cp16z(stg + swz((uint32_t)row*128u + (uint32_t)j*16u), p, sz);
    }
    #pragma unroll
    for (int it = 0; it < 4; it++) {
        int i = tid + it*512;
        int row = i >> 3, j = i & 7;
        int gn = bn + row;
        uint32_t sz = (gn < Brows) ? 16u : 0u;
        int gnc = (gn < Brows) ? gn : 0;
        const char* p = (const char*)(B + (LL)gnc*ldb + k0) + j*16;
        cp16z(stg + SB + swz((uint32_t)row*128u + (uint32_t)j*16u), p, sz);
    }
}

template<int EPI>
__global__ void __launch_bounds__(512, 1)
mm1(const fp16* __restrict__ A, const fp16* __restrict__ B,
    float* __restrict__ C, fp16* __restrict__ Ch,
    const float* __restrict__ bias, const float* __restrict__ res,
    int M, int N, int Brows, int K, int lda, int ldb, int ldc, float alpha)
{
    constexpr uint32_t SB = 16384;
    constexpr int STG = 49152, NSTG = 4;

    extern __shared__ char smem[];
    uint32_t sb = smem_u32(smem);
    const int tid  = threadIdx.x;
    const int wid  = tid >> 5;
    const int lane = tid & 31;
    const int bm = blockIdx.y * 128;
    const int bn = blockIdx.x * 256;

    const int m_warp = (wid & 3) * 32;
    const int n_warp = (wid >> 2) * 64;

    float acc[2][8][4];
    #pragma unroll
    for (int mt = 0; mt < 2; mt++)
        #pragma unroll
        for (int nt = 0; nt < 8; nt++)
            #pragma unroll
            for (int e = 0; e < 4; e++) acc[mt][nt][e] = 0.f;

    const int NCH = K >> 6;

    #pragma unroll
    for (int s = 0; s < NSTG-1; s++) {
        if (s < NCH)
            load_tile1(sb + s*STG, A, B, bm, bn, M, Brows, lda, ldb, s*64, tid);
        cp_commit();
    }

    const int lar = lane & 15;
    const int lac = (lane >> 4) * 16;
    const int lbr = ((lane & 16) >> 1) + (lane & 7);
    const int lbc = ((lane >> 3) & 1) * 16;

    for (int c = 0; c < NCH; c++) {
        if (c + NSTG-1 < NCH)
            load_tile1(sb + ((c + NSTG-1) % NSTG)*STG,
                       A, B, bm, bn, M, Brows, lda, ldb, (c + NSTG-1)*64, tid);
        cp_commit();
        asm volatile("cp.async.wait_group %0;\n" :: "n"(NSTG-1) : "memory");
        __syncthreads();

        uint32_t stg = sb + (c % NSTG)*STG;
        #pragma unroll
        for (int ks = 0; ks < 4; ks++) {
            uint32_t a[2][4];
            #pragma unroll
            for (int mt = 0; mt < 2; mt++) {
                uint32_t off = swz((uint32_t)(m_warp + mt*16 + lar)*128u + ks*32 + lac);
                ldsm4(a[mt], stg + off);
            }
            #pragma unroll
            for (int p = 0; p < 4; p++) {
                uint32_t rb[4];
                uint32_t off = swz((uint32_t)(n_warp + p*16 + lbr)*128u + ks*32 + lbc);
                ldsm4(rb, stg + SB + off);
                #pragma unroll
                for (int mt = 0; mt < 2; mt++) {
                    mma16816(acc[mt][2*p],   a[mt], rb);
                    mma16816(acc[mt][2*p+1], a[mt], rb+2);
                }
            }
        }
        __syncthreads();
    }

    #pragma unroll
    for (int mt = 0; mt < 2; mt++) {
        #pragma unroll
        for (int half = 0; half < 2; half++) {
            int m = bm + m_warp + mt*16 + (lane >> 2) + half*8;
            if (m >= M) continue;
            #pragma unroll
            for (int nt = 0; nt < 8; nt++) {
                int n = bn + n_warp + nt*8 + (lane & 3)*2;
                if (n >= N) continue;
                float v0 = acc[mt][nt][half*2 + 0] * alpha;
                float v1 = acc[mt][nt][half*2 + 1] * alpha;
                if (EPI & EPI_BIAS) { v0 += __ldg(&bias[n]); v1 += __ldg(&bias[n+1]); }
                if (EPI & EPI_RES) {
                    const float2 rv = *(const float2*)(res + (LL)m*ldc + n);
                    v0 += rv.x; v1 += rv.y;
                }
                if (EPI & EPI_GELU) {
                    v0 = 0.5f*v0*(1.f + erff(v0*0.70710678118654752440f));
                    v1 = 0.5f*v1*(1.f + erff(v1*0.70710678118654752440f));
                }
                if (EPI & EPI_SPLITH) {
                    __half2 ph; ph.x = __float2half_rn(v0); ph.y = __float2half_rn(v1);
                    *(__half2*)(Ch + (LL)m*ldc + n) = ph;
                } else {
                    *(float2*)(C + (LL)m*ldc + n) = make_float2(v0, v1);
                }
            }
        }
    }
}

// ================= mms: 256 thr, BM=64 x BN=128, 3-stage ====================
#define MS_SMEM 73728

template<bool BT>
__device__ __forceinline__ void load_tile_s(uint32_t stg,
    const fp16* __restrict__ A, const fp16* __restrict__ B,
    int bm, int bn, int M, int Brows, int lda, int ldb, int k0, int tid)
{
    constexpr uint32_t SB = 8192;
    #pragma unroll
    for (int it = 0; it < 2; it++) {
        int i = tid + it*256;
        int row = i >> 3, j = i & 7;
        int gm = bm + row;
        uint32_t sz = (gm < M) ? 16u : 0u;
        int gmc = (gm < M) ? gm : 0;
        const char* p = (const char*)(A + (LL)gmc*lda + k0) + j*16;
        cp16z(stg + swz((uint32_t)row*128u + (uint32_t)j*16u), p, sz);
    }
    if (!BT) {
        #pragma unroll
        for (int it = 0; it < 4; it++) {
            int i = tid + it*256;
            int row = i >> 3, j = i & 7;
            int gn = bn + row;
            uint32_t sz = (gn < Brows) ? 16u : 0u;
            int gnc = (gn < Brows) ? gn : 0;
            const char* p = (const char*)(B + (LL)gnc*ldb + k0) + j*16;
            cp16z(stg + SB + swz((uint32_t)row*128u + (uint32_t)j*16u), p, sz);
        }
    } else {
        #pragma unroll
        for (int it = 0; it < 4; it++) {
            int i = tid + it*256;
            int row = i >> 4, j = i & 15;
            int gk = k0 + row;
            uint32_t sz = (gk < Brows) ? 16u : 0u;
            int gkc = (gk < Brows) ? gk : 0;
            const char* p = (const char*)(B + (LL)gkc*ldb + bn) + j*16;
            uint32_t so = (uint32_t)row*256u + (((uint32_t)j*16u) ^ (((uint32_t)row & 7u) << 4));
            cp16z(stg + SB + so, p, sz);
        }
    }
}

template<int EPI, bool BT>
__global__ void __launch_bounds__(256, 3)
mms(const fp16* __restrict__ A, const fp16* __restrict__ B,
    float* __restrict__ C, fp16* __restrict__ Ch,
    const float* __restrict__ bias, const float* __restrict__ res,
    int M, int N, int Brows, int K, int lda, int ldb, int ldc,
    int zdiv, LL sA0, LL sA1, LL sB0, LL sB1, LL sC0, LL sC1,
    float alpha)
{
    constexpr uint32_t SB = 8192;
    constexpr int STG = 24576, NSTG = 3;

    extern __shared__ char smem[];
    uint32_t sb = smem_u32(smem);
    const int tid  = threadIdx.x;
    const int wid  = tid >> 5;
    const int lane = tid & 31;
    const int bm = blockIdx.y * 64;
    const int bn = blockIdx.x * 128;
    const int zo = blockIdx.z / zdiv, zi = blockIdx.z - zo*zdiv;
    A += zo*sA0 + zi*sA1;
    B += zo*sB0 + zi*sB1;
    const LL cbase = zo*sC0 + zi*sC1;

    const int m_warp = (wid & 1) * 32;
    const int n_warp = (wid >> 1) * 32;

    float acc[2][4][4];
    #pragma unroll
    for (int mt = 0; mt < 2; mt++)
        #pragma unroll
        for (int nt = 0; nt < 4; nt++)
            #pragma unroll
            for (int e = 0; e < 4; e++) acc[mt][nt][e] = 0.f;

    const int NCH = K >> 6;

    #pragma unroll
    for (int s = 0; s < NSTG-1; s++) {
        if (s < NCH)
            load_tile_s<BT>(sb + s*STG, A, B, bm, bn, M, Brows, lda, ldb, s*64, tid);
        cp_commit();
    }

    const int lar = lane & 15;
    const int lac = (lane >> 4) * 16;
    const int lbr = ((lane & 16) >> 1) + (lane & 7);
    const int lbc = ((lane >> 3) & 1) * 16;

    for (int c = 0; c < NCH; c++) {
        if (c + NSTG-1 < NCH)
            load_tile_s<BT>(sb + ((c + NSTG-1) % NSTG)*STG,
                            A, B, bm, bn, M, Brows, lda, ldb, (c + NSTG-1)*64, tid);
        cp_commit();
        asm volatile("cp.async.wait_group %0;\n" :: "n"(NSTG-1) : "memory");
        __syncthreads();

        uint32_t stg = sb + (c % NSTG)*STG;
        #pragma unroll
        for (int ks = 0; ks < 4; ks++) {
            uint32_t a[2][4];
            #pragma unroll
            for (int mt = 0; mt < 2; mt++) {
                uint32_t off = swz((uint32_t)(m_warp + mt*16 + lar)*128u + ks*32 + lac);
                ldsm4(a[mt], stg + off);
            }
            #pragma unroll
            for (int p = 0; p < 2; p++) {
                uint32_t rb[4];
                if (!BT) {
                    uint32_t off = swz((uint32_t)(n_warp + p*16 + lbr)*128u + ks*32 + lbc);
                    ldsm4(rb, stg + SB + off);
                } else {
                    uint32_t row = (uint32_t)(ks*16 + (lane & 15));
                    uint32_t nb  = (uint32_t)((n_warp + p*16)*2) + (((uint32_t)lane >> 4) << 4);
                    uint32_t off = row*256u + (nb ^ ((row & 7u) << 4));
                    ldsm4t(rb, stg + SB + off);
                }
                #pragma unroll
                for (int mt = 0; mt < 2; mt++) {
                    mma16816(acc[mt][2*p],   a[mt], rb);
                    mma16816(acc[mt][2*p+1], a[mt], rb+2);
                }
            }
        }
        __syncthreads();
    }

    #pragma unroll
    for (int mt = 0; mt < 2; mt++) {
        #pragma unroll
        for (int half = 0; half < 2; half++) {
            int m = bm + m_warp + mt*16 + (lane >> 2) + half*8;
            if (m >= M) continue;
            #pragma unroll
            for (int nt = 0; nt < 4; nt++) {
                int n = bn + n_warp + nt*8 + (lane & 3)*2;
                if (n >= N) continue;
                float v0 = acc[mt][nt][half*2 + 0] * alpha;
                float v1 = acc[mt][nt][half*2 + 1] * alpha;
                if (EPI & EPI_BIAS) { v0 += __ldg(&bias[n]); v1 += __ldg(&bias[n+1]); }
                if (EPI & EPI_RES) {
                    const float2 rv = *(const float2*)(res + (LL)m*ldc + n);
                    v0 += rv.x; v1 += rv.y;
                }
                if (EPI & EPI_GELU) {
                    v0 = 0.5f*v0*(1.f + erff(v0*0.70710678118654752440f));
                    v1 = 0.5f*v1*(1.f + erff(v1*0.70710678118654752440f));
                }
                if (EPI & EPI_SPLITH) {
                    __half2 ph; ph.x = __float2half_rn(v0); ph.y = __float2half_rn(v1);
                    *(__half2*)(Ch + cbase + (LL)m*ldc + n) = ph;
                } else {
                    *(float2*)(C + cbase + (LL)m*ldc + n) = make_float2(v0, v1);
                }
            }
        }
    }
}

// ---------------- conversion / small kernels ----------------
__global__ void conv_k(const float4* __restrict__ in, fp16* __restrict__ out, int n4) {
    int i = blockIdx.x*blockDim.x + threadIdx.x;
    if (i >= n4) return;
    float4 v = in[i];
    __half2 a, b;
    a.x = __float2half_rn(v.x); a.y = __float2half_rn(v.y);
    b.x = __float2half_rn(v.z); b.y = __float2half_rn(v.w);
    *(__half2*)(out + i*4)     = a;
    *(__half2*)(out + i*4 + 2) = b;
}

__global__ void fold_qkv_w(const float* __restrict__ Wq, const float* __restrict__ Wk,
                           const float* __restrict__ Wv, const float* __restrict__ g,
                           const float* __restrict__ b1,
                           fp16* __restrict__ out, float* __restrict__ part) {
    __shared__ float t[32][33];
    __shared__ float red[8][32];
    int z = blockIdx.z;
    int m = z / NH, h = z % NH;
    const float* W = ((m == 0) ? Wq : (m == 1) ? Wk : Wv) + (LL)h*DIM*DIM;
    int d0 = blockIdx.y*32, k0 = blockIdx.x*32;
    const float* b1h = b1 + (LL)h*DIM;
    float pb = 0.f;
    for (int i = threadIdx.y; i < 32; i += 8) {
        float w = W[(LL)(d0+i)*DIM + k0 + threadIdx.x];
        t[i][threadIdx.x] = w * g[h*DIM + d0 + i];
        pb = fmaf(b1h[d0 + i], w, pb);
    }
    red[threadIdx.y][threadIdx.x] = pb;
    __syncthreads();
    for (int i = threadIdx.y; i < 32; i += 8)
        out[(LL)(m*HDK + h*DIM + k0 + i)*DIM + d0 + threadIdx.x] = __float2half_rn(t[threadIdx.x][i]);
    if (threadIdx.y == 0) {
        float s = red[0][threadIdx.x];
        #pragma unroll
        for (int j = 1; j < 8; j++) s += red[j][threadIdx.x];
        part[(LL)blockIdx.y*HDK3 + m*HDK + h*DIM + k0 + threadIdx.x] = s;
    }
}

__global__ void reduce_bf(const float* __restrict__ part,
                          const float* __restrict__ bq, const float* __restrict__ bk,
                          const float* __restrict__ bv, float* __restrict__ Bf) {
    int n = blockIdx.x*256 + threadIdx.x;
    if (n >= HDK3) return;
    int m = n / HDK, r = n - m*HDK;
    float s = ((m == 0) ? bq : (m == 1) ? bk : bv)[r];
    #pragma unroll 8
    for (int j = 0; j < 24; j++) s += part[(LL)j*HDK3 + n];
    Bf[n] = s;
}

__global__ void tconv_k(const float* __restrict__ W, fp16* __restrict__ out, int K, int N) {
    __shared__ float t[32][33];
    int k0 = blockIdx.x*32, n0 = blockIdx.y*32;
    for (int i = threadIdx.y; i < 32; i += 8)
        t[i][threadIdx.x] = W[(LL)(k0+i)*N + n0 + threadIdx.x];
    __syncthreads();
    for (int i = threadIdx.y; i < 32; i += 8)
        out[(LL)(n0+i)*K + k0 + threadIdx.x] = __float2half_rn(t[threadIdx.x][i]);
}

__global__ void im2col_half(const float* __restrict__ x, fp16* __restrict__ oh) {
    int idx = blockIdx.x*blockDim.x + threadIdx.x;
    if (idx >= PROWS*DIM) return;
    int f   = idx % DIM;
    int row = idx / DIM;
    int b = row / NPATCH, n = row % NPATCH;
    int ph = n / 14, pw = n % 14;
    int c = f / 256, r = f % 256;
    int p = r / 16,  q = r % 16;
    oh[idx] = __float2half_rn(x[(((LL)b*3 + c)*224 + ph*16 + p)*224 + pw*16 + q]);
}

__global__ void assemble_k(const float* __restrict__ patch, const float* __restrict__ cls,
                           const float* __restrict__ pos, float* __restrict__ h) {
    int idx = blockIdx.x*blockDim.x + threadIdx.x;
    if (idx >= ROWS*DIM) return;
    int d = idx % DIM;
    int row = idx / DIM;
    int b = row / SEQ, s = row % SEQ;
    float v = (s == 0) ? cls[d] : patch[((LL)b*NPATCH + (s-1))*DIM + d];
    h[idx] = v + pos[s*DIM + d];
}

template<bool AFF>
__global__ void ln_half_k(const float* __restrict__ in, const float* __restrict__ g,
                          const float* __restrict__ b, fp16* __restrict__ oh) {
    int row = blockIdx.x;
    const float* xr = in + (LL)row*DIM;
    int t = threadIdx.x;
    float v0 = xr[t], v1 = xr[t+256], v2 = xr[t+512];
    __shared__ float rs[256], rss[256];
    rs[t]  = v0 + v1 + v2;
    rss[t] = v0*v0 + v1*v1 + v2*v2;
    __syncthreads();
    for (int off = 128; off > 0; off >>= 1) {
        if (t < off) { rs[t] += rs[t+off]; rss[t] += rss[t+off]; }
        __syncthreads();
    }
    float mu   = rs[0]  * (1.f/768.f);
    float rstd = rsqrtf(rss[0]*(1.f/768.f) - mu*mu + 1e-5f);
    float y[3] = { (v0-mu)*rstd, (v1-mu)*rstd, (v2-mu)*rstd };
    #pragma unroll
    for (int i = 0; i < 3; i++) {
        int d = t + i*256;
        float yy = y[i];
        if (AFF) yy = yy*g[d] + b[d];
        oh[(LL)row*DIM + d] = __float2half_rn(yy);
    }
}

__global__ void softmax_half_k(const float* __restrict__ S, fp16* __restrict__ Ph) {
    LL base = (LL)blockIdx.x * (SEQ*SEQP);
    int k = blockIdx.y*128 + threadIdx.x;
    if (k >= SEQ) {
        for (int q = 0; q < SEQ; q++) Ph[base + (LL)q*SEQP + k] = __float2half_rn(0.f);
        return;
    }
    float mx = -1e30f;
    for (int q = 0; q < SEQ; q++) mx = fmaxf(mx, S[base + (LL)q*SEQP + k]);
    float sum = 0.f;
    for (int q = 0; q < SEQ; q++) sum += expf(S[base + (LL)q*SEQP + k] - mx);
    float inv = 1.f / sum;
    for (int q = 0; q < SEQ; q++) {
        float p = expf(S[base + (LL)q*SEQP + k] - mx) * inv;
        Ph[base + (LL)q*SEQP + k] = __float2half_rn(p);
    }
}

__global__ void final_head_k(const float* __restrict__ h, const float* __restrict__ g,
                             const float* __restrict__ b, const float* __restrict__ Wc,
                             const float* __restrict__ bc, float* __restrict__ out) {
    int bi = blockIdx.x;
    const float* xr = h + (LL)bi*SEQ*DIM;
    int t = threadIdx.x;
    float v0 = xr[t], v1 = xr[t+256], v2 = xr[t+512];
    __shared__ float rs[256], rss[256];
    rs[t]  = v0 + v1 + v2;
    rss[t] = v0*v0 + v1*v1 + v2*v2;
    __syncthreads();
    for (int off = 128; off > 0; off >>= 1) {
        if (t < off) { rs[t] += rs[t+off]; rss[t] += rss[t+off]; }
        __syncthreads();
    }
    float mu   = rs[0]  * (1.f/768.f);
    float rstd = rsqrtf(rss[0]*(1.f/768.f) - mu*mu + 1e-5f);
    __shared__ float pa[NC][256];
    float a[NC] = {0.f, 0.f, 0.f, 0.f};
    float vv[3] = {v0, v1, v2};
    #pragma unroll
    for (int i = 0; i < 3; i++) {
        int d = t + i*256;
        float y = (vv[i]-mu)*rstd*g[d] + b[d];
        #pragma unroll
        for (int c = 0; c < NC; c++) a[c] = fmaf(y, Wc[d*NC + c], a[c]);
    }
    #pragma unroll
    for (int c = 0; c < NC; c++) pa[c][t] = a[c];
    __syncthreads();
    for (int off = 128; off > 0; off >>= 1) {
        if (t < off) {
            #pragma unroll
            for (int c = 0; c < NC; c++) pa[c][t] += pa[c][t+off];
        }
        __syncthreads();
    }
    if (t < NC) out[bi*NC + t] = pa[t][0] + bc[t];
}

// ---------------- orchestration ----------------
extern "C" void kernel_launch(void* const* d_in, const int* in_sizes, int n_in,
                              void* d_out, int out_size)
{
    const float* x      = (const float*)d_in[0];
    const float* Wpatch = (const float*)d_in[1];
    const float* bpatch = (const float*)d_in[2];
    const float* cls    = (const float*)d_in[3];
    const float* pos    = (const float*)d_in[4];
    const float* ln1g   = (const float*)d_in[5];
    const float* ln1b   = (const float*)d_in[6];
    const float* Wq     = (const float*)d_in[7];
    const float* bq     = (const float*)d_in[8];
    const float* Wk     = (const float*)d_in[9];
    const float* bk     = (const float*)d_in[10];
    const float* Wv     = (const float*)d_in[11];
    const float* bv     = (const float*)d_in[12];
    const float* Wo     = (const float*)d_in[13];
    const float* bo     = (const float*)d_in[14];
    const float* ln2g   = (const float*)d_in[15];
    const float* ln2b   = (const float*)d_in[16];
    const float* W1     = (const float*)d_in[17];
    const float* b1m    = (const float*)d_in[18];
    const float* W2     = (const float*)d_in[19];
    const float* b2m    = (const float*)d_in[20];
    const float* lnfg   = (const float*)d_in[21];
    const float* lnfb   = (const float*)d_in[22];
    const float* Wc     = (const float*)d_in[23];
    const float* bc     = (const float*)d_in[24];
    float* out = (float*)d_out;

    float *PO, *H, *BfL, *Part, *S;
    fp16 *Xn, *Xp, *QKV, *Cat, *Hid, *Ph, *WqkvL, *WoL, *W1L, *W2L, *Wp;
    { void* p;
      cudaGetSymbolAddress(&p, g_PO);    PO    = (float*)p;
      cudaGetSymbolAddress(&p, g_H);     H     = (float*)p;
      cudaGetSymbolAddress(&p, g_BfL);   BfL   = (float*)p;
      cudaGetSymbolAddress(&p, g_Part);  Part  = (float*)p;
      cudaGetSymbolAddress(&p, g_S);     S     = (float*)p;
      cudaGetSymbolAddress(&p, g_Xn);    Xn    = (fp16*)p;
      cudaGetSymbolAddress(&p, g_Xp);    Xp    = (fp16*)p;
      cudaGetSymbolAddress(&p, g_QKV);   QKV   = (fp16*)p;
      cudaGetSymbolAddress(&p, g_Cat);   Cat   = (fp16*)p;
      cudaGetSymbolAddress(&p, g_Hid);   Hid   = (fp16*)p;
      cudaGetSymbolAddress(&p, g_Ph);    Ph    = (fp16*)p;
      cudaGetSymbolAddress(&p, g_WqkvL); WqkvL = (fp16*)p;
      cudaGetSymbolAddress(&p, g_WoL);   WoL   = (fp16*)p;
      cudaGetSymbolAddress(&p, g_W1L);   W1L   = (fp16*)p;
      cudaGetSymbolAddress(&p, g_W2L);   W2L   = (fp16*)p;
      cudaGetSymbolAddress(&p, g_Wp);    Wp    = (fp16*)p;
    }

    static cudaStream_t sW = nullptr;
    static cudaEvent_t evFork, evPatch, evL[NLAYER];
    static int init_done = 0;
    if (!init_done) {
        cudaStreamCreateWithFlags(&sW, cudaStreamNonBlocking);
        cudaEventCreateWithFlags(&evFork,  cudaEventDisableTiming);
        cudaEventCreateWithFlags(&evPatch, cudaEventDisableTiming);
        for (int l = 0; l < NLAYER; l++)
            cudaEventCreateWithFlags(&evL[l], cudaEventDisableTiming);
        cudaFuncSetAttribute(mm1<EPI_BIAS|EPI_SPLITH>,          cudaFuncAttributeMaxDynamicSharedMemorySize, MM_SMEM);
        cudaFuncSetAttribute(mm1<EPI_BIAS|EPI_GELU|EPI_SPLITH>, cudaFuncAttributeMaxDynamicSharedMemorySize, MM_SMEM);
        cudaFuncSetAttribute(mms<EPI_BIAS, false>,              cudaFuncAttributeMaxDynamicSharedMemorySize, MS_SMEM);
        cudaFuncSetAttribute(mms<0, false>,                     cudaFuncAttributeMaxDynamicSharedMemorySize, MS_SMEM);
        cudaFuncSetAttribute(mms<EPI_SPLITH, true>,             cudaFuncAttributeMaxDynamicSharedMemorySize, MS_SMEM);
        cudaFuncSetAttribute(mms<EPI_BIAS|EPI_RES, false>,      cudaFuncAttributeMaxDynamicSharedMemorySize, MS_SMEM);
        init_done = 1;
    }

    const float inv_scale = 1.0f / sqrtf(768.0f);

    // ================= fork weight-prep stream =================
    cudaEventRecord(evFork, 0);
    cudaStreamWaitEvent(sW, evFork, 0);

    // patch weight convert on sW
    conv_k<<<((DIM*DIM/4) + 255)/256, 256, 0, sW>>>((const float4*)Wpatch, Wp, DIM*DIM/4);
    cudaEventRecord(evPatch, sW);

    // per-layer weight prep on sW
    for (int l = 0; l < NLAYER; l++) {
        const float* Wq_l = Wq + (LL)l*NH*DIM*DIM;
        const float* Wk_l = Wk + (LL)l*NH*DIM*DIM;
        const float* Wv_l = Wv + (LL)l*NH*DIM*DIM;
        fold_qkv_w<<<dim3(DIM/32, DIM/32, 3*NH), dim3(32,8), 0, sW>>>(
            Wq_l, Wk_l, Wv_l, ln1g + (LL)l*NH*DIM, ln1b + (LL)l*NH*DIM,
            WqkvL + (LL)l*3*HDK*DIM, Part);
        reduce_bf<<<HDK3/256, 256, 0, sW>>>(
            Part, bq + (LL)l*NH*DIM, bk + (LL)l*NH*DIM, bv + (LL)l*NH*DIM,
            BfL + (LL)l*HDK3);
        tconv_k<<<dim3(HDK/32, DIM/32), dim3(32,8), 0, sW>>>(
            Wo + (LL)l*HDK*DIM, WoL + (LL)l*HDK*DIM, HDK, DIM);
        tconv_k<<<dim3(DIM/32, MLP/32), dim3(32,8), 0, sW>>>(
            W1 + (LL)l*DIM*MLP, W1L + (LL)l*DIM*MLP, DIM, MLP);
        tconv_k<<<dim3(MLP/32, DIM/32), dim3(32,8), 0, sW>>>(
            W2 + (LL)l*MLP*DIM, W2L + (LL)l*MLP*DIM, MLP, DIM);
        cudaEventRecord(evL[l], sW);
    }

    // ================= main stream =================
    im2col_half<<<(PROWS*DIM + 255)/256, 256>>>(x, Xp);
    cudaStreamWaitEvent(0, evPatch, 0);
    mms<EPI_BIAS, false><<<dim3(6, 49, 1), 256, MS_SMEM>>>(
        Xp, Wp, PO, nullptr, bpatch, nullptr,
        PROWS, DIM, DIM, DIM, DIM, DIM, DIM,
        1, 0, 0, 0, 0, 0, 0, 1.f);
    assemble_k<<<(ROWS*DIM + 255)/256, 256>>>(PO, cls, pos, H);

    for (int l = 0; l < NLAYER; l++) {
        const fp16* Wqkv_l = WqkvL + (LL)l*3*HDK*DIM;
        const float* Bf_l  = BfL + (LL)l*HDK3;
        const fp16* Wo_l   = WoL + (LL)l*HDK*DIM;
        const fp16* W1_l   = W1L + (LL)l*DIM*MLP;
        const fp16* W2_l   = W2L + (LL)l*MLP*DIM;
        const float* bo_l  = bo  + (LL)l*DIM;
        const float* g2_l  = ln2g + (LL)l*DIM;
        const float* b2_l  = ln2b + (LL)l*DIM;
        const float* b1_l  = b1m + (LL)l*MLP;
        const float* bb2_l = b2m + (LL)l*DIM;

        ln_half_k<false><<<ROWS, 256>>>(H, nullptr, nullptr, Xn);

        cudaStreamWaitEvent(0, evL[l], 0);   // layer's weights ready

        mm1<EPI_BIAS|EPI_SPLITH><<<dim3(HDK3/256, 25, 1), 512, MM_SMEM>>>(
            Xn, Wqkv_l, nullptr, QKV, Bf_l, nullptr,
            ROWS, HDK3, HDK3, DIM, DIM, DIM, HDK3, 1.f);

        // scores = Q·K^T / sqrt(768)
        mms<0, false><<<dim3(2, 4, NBH), 256, MS_SMEM>>>(
            QKV, QKV + HDK, S, nullptr, nullptr, nullptr,
            SEQ, SEQ, SEQ, DIM,
            HDK3, HDK3, SEQP,
            NH, (LL)SEQ*HDK3, (LL)DIM, (LL)SEQ*HDK3, (LL)DIM,
            (LL)NH*SEQ*SEQP, (LL)SEQ*SEQP, inv_scale);

        softmax_half_k<<<dim3(NBH, 2), 128>>>(S, Ph);

        // av = P·V (trans-B) -> cat layout
        mms<EPI_SPLITH, true><<<dim3(6, 4, NBH), 256, MS_SMEM>>>(
            Ph, QKV + 2*HDK, nullptr, Cat, nullptr, nullptr,
            SEQ, DIM, SEQ, SEQP,
            SEQP, HDK3, HDK,
            NH, (LL)NH*SEQ*SEQP, (LL)SEQ*SEQP, (LL)SEQ*HDK3, (LL)DIM,
            (LL)SEQ*HDK, (LL)DIM, 1.f);

        // out proj + bias + residual -> H
        mms<EPI_BIAS|EPI_RES, false><<<dim3(6, 50, 1), 256, MS_SMEM>>>(
            Cat, Wo_l, H, nullptr, bo_l, H,
            ROWS, DIM, DIM, HDK, HDK, HDK, DIM,
            1, 0, 0, 0, 0, 0, 0, 1.f);

        // MLP
        ln_half_k<true><<<ROWS, 256>>>(H, g2_l, b2_l, Xn);
        mm1<EPI_BIAS|EPI_GELU|EPI_SPLITH><<<dim3(MLP/256, 25, 1), 512, MM_SMEM>>>(
            Xn, W1_l, nullptr, Hid, b1_l, nullptr,
            ROWS, MLP, MLP, DIM, DIM, DIM, MLP, 1.f);

        mms<EPI_BIAS|EPI_RES, false><<<dim3(6, 50, 1), 256, MS_SMEM>>>(
            Hid, W2_l, H, nullptr, bb2_l, H,
            ROWS, DIM, DIM, MLP, MLP, MLP, DIM,
            1, 0, 0, 0, 0, 0, 0, 1.f);
    }

    // ---- final LN on CLS + classifier ----
    final_head_k<<<BATCH, 256>>>(H, lnfg, lnfb, Wc, bc, out);
}